// round 2
// baseline (speedup 1.0000x reference)
#include <cuda_runtime.h>
#include <math.h>

#define BDIM 16
#define CDIM 256
#define NDIM 2048
#define OTOT 320
#define EPSV 1e-5f

typedef unsigned long long u64;

__device__ __align__(16) float g_proj[(size_t)BDIM * OTOT * NDIM];
__device__ float g_scale[OTOT];
__device__ float g_shift[OTOT];

__device__ __forceinline__ u64 dup2(float v) {
    u64 r; asm("mov.b64 %0, {%1, %1};" : "=l"(r) : "f"(v)); return r;
}
__device__ __forceinline__ void up2(u64 a, float& lo, float& hi) {
    asm("mov.b64 {%0, %1}, %2;" : "=f"(lo), "=f"(hi) : "l"(a));
}
__device__ __forceinline__ void fma2(u64& d, u64 a, u64 b) {
    asm("fma.rn.f32x2 %0, %1, %2, %3;" : "=l"(d) : "l"(a), "l"(b), "l"(d));
}
__device__ __forceinline__ u64 mul2(u64 a, u64 b) {
    u64 r; asm("mul.rn.f32x2 %0, %1, %2;" : "=l"(r) : "l"(a), "l"(b)); return r;
}

// ================= Kernel 1: fused QKV projection (no bias) =================
__global__ void __launch_bounds__(256) proj_kernel(
    const float* __restrict__ x, const float* __restrict__ qw,
    const float* __restrict__ kw, const float* __restrict__ vw)
{
    __shared__ float w_s[64 * 17];
    __shared__ __align__(16) float x_s[16 * 64];
    const int tid = threadIdx.x;
    const int o0 = blockIdx.x * 64, n0 = blockIdx.y * 64, b = blockIdx.z;
    const int to = tid >> 4, tn = tid & 15;

    u64 acc[4][2];
#pragma unroll
    for (int i = 0; i < 4; i++) { acc[i][0] = 0ULL; acc[i][1] = 0ULL; }

    for (int c0 = 0; c0 < CDIM; c0 += 16) {
        __syncthreads();
#pragma unroll
        for (int p = 0; p < 4; p++) {
            int o = (tid >> 4) + p * 16, cc = tid & 15, og = o0 + o;
            const float* wr;
            if (og < 32)      wr = qw + (size_t)og * CDIM;
            else if (og < 64) wr = kw + (size_t)(og - 32) * CDIM;
            else              wr = vw + (size_t)(og - 64) * CDIM;
            w_s[o * 17 + cc] = wr[c0 + cc];
        }
#pragma unroll
        for (int p = 0; p < 4; p++) {
            int cc = (tid >> 6) + p * 4, nn = tid & 63;
            x_s[cc * 64 + nn] = x[((size_t)b * CDIM + c0 + cc) * NDIM + n0 + nn];
        }
        __syncthreads();
#pragma unroll
        for (int cc = 0; cc < 16; cc++) {
            const u64* xp = reinterpret_cast<const u64*>(&x_s[cc * 64 + tn * 4]);
            u64 x01 = xp[0], x23 = xp[1];
#pragma unroll
            for (int i = 0; i < 4; i++) {
                u64 ad = dup2(w_s[(to * 4 + i) * 17 + cc]);
                fma2(acc[i][0], ad, x01);
                fma2(acc[i][1], ad, x23);
            }
        }
    }
#pragma unroll
    for (int i = 0; i < 4; i++) {
        float r0, r1, r2, r3;
        up2(acc[i][0], r0, r1); up2(acc[i][1], r2, r3);
        *reinterpret_cast<float4*>(
            &g_proj[((size_t)b * OTOT + o0 + to * 4 + i) * NDIM + n0 + tn * 4]) =
            make_float4(r0, r1, r2, r3);
    }
}

// ================= Kernel 2: BN stats -> scale/shift =================
__global__ void __launch_bounds__(256) stats_kernel(
    const float* __restrict__ qg, const float* __restrict__ qbe,
    const float* __restrict__ kg, const float* __restrict__ kbe,
    const float* __restrict__ vg, const float* __restrict__ vbe)
{
    const int ch = blockIdx.x, tid = threadIdx.x;
    __shared__ float red[256];
    const float* base = g_proj + (size_t)ch * NDIM;
    const float invM = 1.0f / (float)(BDIM * NDIM);

    float s = 0.0f;
    for (int b = 0; b < BDIM; b++) {
        const float* p = base + (size_t)b * OTOT * NDIM;
        for (int n = tid; n < NDIM; n += 256) s += p[n];
    }
    red[tid] = s; __syncthreads();
    for (int off = 128; off; off >>= 1) { if (tid < off) red[tid] += red[tid + off]; __syncthreads(); }
    float mean = red[0] * invM;
    __syncthreads();

    float v = 0.0f;
    for (int b = 0; b < BDIM; b++) {
        const float* p = base + (size_t)b * OTOT * NDIM;
        for (int n = tid; n < NDIM; n += 256) { float d = p[n] - mean; v += d * d; }
    }
    red[tid] = v; __syncthreads();
    for (int off = 128; off; off >>= 1) { if (tid < off) red[tid] += red[tid + off]; __syncthreads(); }
    if (tid == 0) {
        float var = red[0] * invM, gamma, beta;
        if (ch < 32)      { gamma = qg[ch];      beta = qbe[ch]; }
        else if (ch < 64) { gamma = kg[ch - 32]; beta = kbe[ch - 32]; }
        else              { gamma = vg[ch - 64]; beta = vbe[ch - 64]; }
        float sc = gamma * rsqrtf(var + EPSV);
        g_scale[ch] = sc;
        g_shift[ch] = beta - mean * sc;
    }
}

// ================= Kernel 3: in-place normalize (+LeakyReLU on V) =================
__global__ void __launch_bounds__(256) norm_kernel()
{
    const size_t total4 = (size_t)BDIM * OTOT * NDIM / 4;
    float4* p4 = reinterpret_cast<float4*>(g_proj);
    for (size_t i = (size_t)blockIdx.x * blockDim.x + threadIdx.x; i < total4;
         i += (size_t)gridDim.x * blockDim.x) {
        int ch = (int)((i >> 9) % OTOT);
        float sc = g_scale[ch], sh = g_shift[ch];
        float4 v = p4[i];
        v.x = v.x * sc + sh; v.y = v.y * sc + sh;
        v.z = v.z * sc + sh; v.w = v.w * sc + sh;
        if (ch >= 64) {
            v.x = v.x > 0.f ? v.x : 0.2f * v.x;
            v.y = v.y > 0.f ? v.y : 0.2f * v.y;
            v.z = v.z > 0.f ? v.z : 0.2f * v.z;
            v.w = v.w > 0.f ? v.w : 0.2f * v.w;
        }
        p4[i] = v;
    }
}

// ================= Kernel 4: fused flash attention + residual =================
// dyn smem: q[32*64] k[32*64] p[64*65] v[64*258] M[64] L[64] A[64]
#define PSTR 65
#define VSTR 258
#define SMEM_FLOATS (2048 + 2048 + 64*PSTR + 64*VSTR + 192)

__global__ void __launch_bounds__(256, 2) attn_kernel(
    const float* __restrict__ x, float* __restrict__ out)
{
    extern __shared__ __align__(16) float sm[];
    float* q_s = sm;
    float* k_s = q_s + 2048;
    float* p_s = k_s + 2048;
    float* v_s = p_s + 64 * PSTR;
    float* M_s = v_s + 64 * VSTR;
    float* L_s = M_s + 64;
    float* A_s = L_s + 64;

    const int tid = threadIdx.x;
    const int n0 = blockIdx.x * 64, b = blockIdx.y;
    const int tm = tid & 15, tn = tid >> 4;   // S-phase mapping
    const int to = tid >> 4, tp = tid & 15;   // PV mapping: c-group, n-group
    const float* qn = g_proj + (size_t)b * OTOT * NDIM;

    // load Q tile [32 d][64 n]
    for (int idx = tid; idx < 2048; idx += 256) {
        int d = idx >> 6, n = idx & 63;
        q_s[idx] = qn[(size_t)d * NDIM + n0 + n];
    }
    if (tid < 64) { M_s[tid] = -INFINITY; L_s[tid] = 0.0f; }

    u64 acc2[8][4];
#pragma unroll
    for (int cp = 0; cp < 8; cp++)
#pragma unroll
        for (int j = 0; j < 4; j++) acc2[cp][j] = 0ULL;
    __syncthreads();

    for (int mt = 0; mt < 32; mt++) {
        const int m0 = mt * 64;
        // load K tile [32 d][64 m] and V tile transposed [64 m][256 c]
        for (int idx = tid; idx < 2048; idx += 256) {
            int d = idx >> 6, m = idx & 63;
            k_s[idx] = qn[(size_t)(32 + d) * NDIM + m0 + m];
        }
        for (int idx = tid; idx < 16384; idx += 256) {
            int cc = idx >> 6, mm = idx & 63;
            v_s[mm * VSTR + cc] = qn[(size_t)(64 + cc) * NDIM + m0 + mm];
        }
        __syncthreads();

        // ---- S = Q^T K (4n x 4m per thread, m-paired f32x2) ----
        u64 s2[4][2];
#pragma unroll
        for (int i = 0; i < 4; i++) { s2[i][0] = 0ULL; s2[i][1] = 0ULL; }
#pragma unroll 4
        for (int d = 0; d < 32; d++) {
            const u64* kp = reinterpret_cast<const u64*>(&k_s[d * 64 + tm * 4]);
            u64 k01 = kp[0], k23 = kp[1];
            float4 qv = *reinterpret_cast<const float4*>(&q_s[d * 64 + tn * 4]);
            u64 qd;
            qd = dup2(qv.x); fma2(s2[0][0], qd, k01); fma2(s2[0][1], qd, k23);
            qd = dup2(qv.y); fma2(s2[1][0], qd, k01); fma2(s2[1][1], qd, k23);
            qd = dup2(qv.z); fma2(s2[2][0], qd, k01); fma2(s2[2][1], qd, k23);
            qd = dup2(qv.w); fma2(s2[3][0], qd, k01); fma2(s2[3][1], qd, k23);
        }

        // ---- online softmax; rows owned per 16-lane group ----
#pragma unroll
        for (int i = 0; i < 4; i++) {
            float s0, s1, s2v, s3;
            up2(s2[i][0], s0, s1); up2(s2[i][1], s2v, s3);
            const int nrow = tn * 4 + i;
            float mx = fmaxf(fmaxf(s0, s1), fmaxf(s2v, s3));
#pragma unroll
            for (int off = 1; off < 16; off <<= 1)
                mx = fmaxf(mx, __shfl_xor_sync(0xffffffffu, mx, off));
            float oldM = M_s[nrow];
            float newM = fmaxf(oldM, mx);
            float p0 = __expf(s0 - newM), p1 = __expf(s1 - newM);
            float p2 = __expf(s2v - newM), p3 = __expf(s3 - newM);
            float* pr = &p_s[nrow * PSTR + tm * 4];
            pr[0] = p0; pr[1] = p1; pr[2] = p2; pr[3] = p3;
            float rs = (p0 + p1) + (p2 + p3);
#pragma unroll
            for (int off = 1; off < 16; off <<= 1)
                rs += __shfl_xor_sync(0xffffffffu, rs, off);
            if (tm == 0) {
                float alpha = __expf(oldM - newM);
                L_s[nrow] = L_s[nrow] * alpha + rs;
                M_s[nrow] = newM;
                A_s[nrow] = alpha;
            }
        }
        __syncthreads();

        // ---- PV: rescale then accumulate ----
        u64 a2[4];
#pragma unroll
        for (int j = 0; j < 4; j++) a2[j] = dup2(A_s[tp * 4 + j]);
#pragma unroll
        for (int cp = 0; cp < 8; cp++)
#pragma unroll
            for (int j = 0; j < 4; j++) acc2[cp][j] = mul2(acc2[cp][j], a2[j]);

        const int vbase = to * 16;
#pragma unroll 2
        for (int m = 0; m < 64; m++) {
            const u64* vp = reinterpret_cast<const u64*>(&v_s[m * VSTR + vbase]);
            u64 v2[8];
#pragma unroll
            for (int k = 0; k < 8; k++) v2[k] = vp[k];
            u64 p2[4];
#pragma unroll
            for (int j = 0; j < 4; j++) p2[j] = dup2(p_s[(tp * 4 + j) * PSTR + m]);
#pragma unroll
            for (int cp = 0; cp < 8; cp++)
#pragma unroll
                for (int j = 0; j < 4; j++) fma2(acc2[cp][j], v2[cp], p2[j]);
        }
        __syncthreads();
    }

    // ---- epilogue: /L + residual ----
    float inv[4];
#pragma unroll
    for (int j = 0; j < 4; j++) inv[j] = 1.0f / L_s[tp * 4 + j];
#pragma unroll
    for (int cp = 0; cp < 8; cp++) {
        float lo[4], hi[4];
#pragma unroll
        for (int j = 0; j < 4; j++) up2(acc2[cp][j], lo[j], hi[j]);
        int c0 = to * 16 + cp * 2;
        size_t base0 = ((size_t)b * CDIM + c0) * NDIM + n0 + tp * 4;
        size_t base1 = base0 + NDIM;
        float4 x0 = *reinterpret_cast<const float4*>(&x[base0]);
        float4 x1 = *reinterpret_cast<const float4*>(&x[base1]);
        float4 o0 = make_float4(lo[0]*inv[0]+x0.x, lo[1]*inv[1]+x0.y,
                                lo[2]*inv[2]+x0.z, lo[3]*inv[3]+x0.w);
        float4 o1 = make_float4(hi[0]*inv[0]+x1.x, hi[1]*inv[1]+x1.y,
                                hi[2]*inv[2]+x1.z, hi[3]*inv[3]+x1.w);
        *reinterpret_cast<float4*>(&out[base0]) = o0;
        *reinterpret_cast<float4*>(&out[base1]) = o1;
    }
}

extern "C" void kernel_launch(void* const* d_in, const int* in_sizes, int n_in,
                              void* d_out, int out_size) {
    const float* x   = (const float*)d_in[0];
    const float* q_w = (const float*)d_in[1];
    const float* q_g = (const float*)d_in[3];
    const float* q_be= (const float*)d_in[4];
    const float* k_w = (const float*)d_in[5];
    const float* k_g = (const float*)d_in[7];
    const float* k_be= (const float*)d_in[8];
    const float* v_w = (const float*)d_in[9];
    const float* v_g = (const float*)d_in[11];
    const float* v_be= (const float*)d_in[12];
    float* out = (float*)d_out;

    proj_kernel<<<dim3(5, 32, 16), 256>>>(x, q_w, k_w, v_w);
    stats_kernel<<<320, 256>>>(q_g, q_be, k_g, k_be, v_g, v_be);
    norm_kernel<<<2048, 256>>>();

    static int smem_set = 0;
    if (!smem_set) {
        cudaFuncSetAttribute(attn_kernel, cudaFuncAttributeMaxDynamicSharedMemorySize,
                             SMEM_FLOATS * (int)sizeof(float));
        smem_set = 1;
    }
    attn_kernel<<<dim3(32, 16), 256, SMEM_FLOATS * sizeof(float)>>>(x, out);
}

// round 4
// speedup vs baseline: 2.4498x; 2.4498x over previous
#include <cuda_runtime.h>
#include <math.h>
#include <stdint.h>

typedef unsigned int u32;
typedef unsigned long long u64;

#define BDIM 16
#define CDIM 256
#define NDIM 2048
#define OTOT 320
#define EPSV 1e-5f

__device__ __align__(16) float g_proj[(size_t)BDIM * OTOT * NDIM];
__device__ __align__(16) float g_klo[(size_t)BDIM * 32 * NDIM];
__device__ float g_mhat[BDIM * NDIM];
__device__ float g_scale[OTOT];
__device__ float g_shift[OTOT];

// ---------------- helpers ----------------
__device__ __forceinline__ u64 dup2(float v) {
    u64 r; asm("mov.b64 %0, {%1, %1};" : "=l"(r) : "f"(v)); return r;
}
__device__ __forceinline__ void up2(u64 a, float& lo, float& hi) {
    asm("mov.b64 {%0, %1}, %2;" : "=f"(lo), "=f"(hi) : "l"(a));
}
__device__ __forceinline__ void fma2(u64& d, u64 a, u64 b) {
    asm("fma.rn.f32x2 %0, %1, %2, %3;" : "=l"(d) : "l"(a), "l"(b), "l"(d));
}
__device__ __forceinline__ u32 f2tf(float f) {
    u32 r; asm("cvt.rna.tf32.f32 %0, %1;" : "=r"(r) : "f"(f)); return r;
}
__device__ __forceinline__ u32 smem_u32(const void* p) {
    u32 a; asm("{ .reg .u64 t; cvta.to.shared.u64 t, %1; cvt.u32.u64 %0, t; }" : "=r"(a) : "l"(p));
    return a;
}
__device__ __forceinline__ void mma8(float d[4], const u32 a[4], u32 b0, u32 b1) {
    asm volatile("mma.sync.aligned.m16n8k8.row.col.f32.tf32.tf32.f32 "
                 "{%0,%1,%2,%3}, {%4,%5,%6,%7}, {%8,%9}, {%0,%1,%2,%3};"
                 : "+f"(d[0]), "+f"(d[1]), "+f"(d[2]), "+f"(d[3])
                 : "r"(a[0]), "r"(a[1]), "r"(a[2]), "r"(a[3]), "r"(b0), "r"(b1));
}
#define CP16(dst, src) asm volatile("cp.async.cg.shared.global [%0], [%1], 16;" :: "r"(dst), "l"(src))
#define CP_COMMIT()    asm volatile("cp.async.commit_group;" ::: "memory")
#define CP_WAIT1()     asm volatile("cp.async.wait_group 1;" ::: "memory")
#define CP_WAIT0()     asm volatile("cp.async.wait_group 0;" ::: "memory")

// ================= Kernel 1: fused QKV projection (f32x2) =================
__global__ void __launch_bounds__(256) proj_kernel(
    const float* __restrict__ x, const float* __restrict__ qw,
    const float* __restrict__ kw, const float* __restrict__ vw)
{
    __shared__ float w_s[64 * 17];
    __shared__ __align__(16) float x_s[16 * 64];
    const int tid = threadIdx.x;
    const int o0 = blockIdx.x * 64, n0 = blockIdx.y * 64, b = blockIdx.z;
    const int to = tid >> 4, tn = tid & 15;

    u64 acc[4][2];
#pragma unroll
    for (int i = 0; i < 4; i++) { acc[i][0] = 0ULL; acc[i][1] = 0ULL; }

    for (int c0 = 0; c0 < CDIM; c0 += 16) {
        __syncthreads();
#pragma unroll
        for (int p = 0; p < 4; p++) {
            int o = (tid >> 4) + p * 16, cc = tid & 15, og = o0 + o;
            const float* wr;
            if (og < 32)      wr = qw + (size_t)og * CDIM;
            else if (og < 64) wr = kw + (size_t)(og - 32) * CDIM;
            else              wr = vw + (size_t)(og - 64) * CDIM;
            w_s[o * 17 + cc] = wr[c0 + cc];
        }
#pragma unroll
        for (int p = 0; p < 4; p++) {
            int cc = (tid >> 6) + p * 4, nn = tid & 63;
            x_s[cc * 64 + nn] = x[((size_t)b * CDIM + c0 + cc) * NDIM + n0 + nn];
        }
        __syncthreads();
#pragma unroll
        for (int cc = 0; cc < 16; cc++) {
            const u64* xp = reinterpret_cast<const u64*>(&x_s[cc * 64 + tn * 4]);
            u64 x01 = xp[0], x23 = xp[1];
#pragma unroll
            for (int i = 0; i < 4; i++) {
                u64 ad = dup2(w_s[(to * 4 + i) * 17 + cc]);
                fma2(acc[i][0], ad, x01);
                fma2(acc[i][1], ad, x23);
            }
        }
    }
#pragma unroll
    for (int i = 0; i < 4; i++) {
        float r0, r1, r2, r3;
        up2(acc[i][0], r0, r1); up2(acc[i][1], r2, r3);
        *reinterpret_cast<float4*>(
            &g_proj[((size_t)b * OTOT + o0 + to * 4 + i) * NDIM + n0 + tn * 4]) =
            make_float4(r0, r1, r2, r3);
    }
}

// ================= Kernel 2: BN stats =================
__global__ void __launch_bounds__(256) stats_kernel(
    const float* __restrict__ qg, const float* __restrict__ qbe,
    const float* __restrict__ kg, const float* __restrict__ kbe,
    const float* __restrict__ vg, const float* __restrict__ vbe)
{
    const int ch = blockIdx.x, tid = threadIdx.x;
    __shared__ float red[256];
    const float* base = g_proj + (size_t)ch * NDIM;
    const float invM = 1.0f / (float)(BDIM * NDIM);

    float s = 0.0f;
    for (int b = 0; b < BDIM; b++) {
        const float* p = base + (size_t)b * OTOT * NDIM;
        for (int n = tid; n < NDIM; n += 256) s += p[n];
    }
    red[tid] = s; __syncthreads();
    for (int off = 128; off; off >>= 1) { if (tid < off) red[tid] += red[tid + off]; __syncthreads(); }
    float mean = red[0] * invM;
    __syncthreads();

    float v = 0.0f;
    for (int b = 0; b < BDIM; b++) {
        const float* p = base + (size_t)b * OTOT * NDIM;
        for (int n = tid; n < NDIM; n += 256) { float d = p[n] - mean; v += d * d; }
    }
    red[tid] = v; __syncthreads();
    for (int off = 128; off; off >>= 1) { if (tid < off) red[tid] += red[tid + off]; __syncthreads(); }
    if (tid == 0) {
        float var = red[0] * invM, gamma, beta;
        if (ch < 32)      { gamma = qg[ch];      beta = qbe[ch]; }
        else if (ch < 64) { gamma = kg[ch - 32]; beta = kbe[ch - 32]; }
        else              { gamma = vg[ch - 64]; beta = vbe[ch - 64]; }
        float sc = gamma * rsqrtf(var + EPSV);
        g_scale[ch] = sc;
        g_shift[ch] = beta - mean * sc;
    }
}

// ================= Kernel 3: normalize in place; K->hi/lo; V->leaky+tf32 =================
__global__ void __launch_bounds__(256) norm_kernel()
{
    const size_t total4 = (size_t)BDIM * OTOT * NDIM / 4;
    float4* p4 = reinterpret_cast<float4*>(g_proj);
    float4* klo4 = reinterpret_cast<float4*>(g_klo);
    for (size_t i = (size_t)blockIdx.x * blockDim.x + threadIdx.x; i < total4;
         i += (size_t)gridDim.x * blockDim.x) {
        int ch = (int)((i >> 9) % OTOT);
        float sc = g_scale[ch], sh = g_shift[ch];
        float4 v = p4[i];
        v.x = v.x * sc + sh; v.y = v.y * sc + sh;
        v.z = v.z * sc + sh; v.w = v.w * sc + sh;
        if (ch < 32) {
            p4[i] = v;                       // Q: normalized fp32
        } else if (ch < 64) {                // K: tf32 hi in place, lo aside
            float4 hi, lo;
            hi.x = __uint_as_float(f2tf(v.x)); lo.x = __uint_as_float(f2tf(v.x - hi.x));
            hi.y = __uint_as_float(f2tf(v.y)); lo.y = __uint_as_float(f2tf(v.y - hi.y));
            hi.z = __uint_as_float(f2tf(v.z)); lo.z = __uint_as_float(f2tf(v.z - hi.z));
            hi.w = __uint_as_float(f2tf(v.w)); lo.w = __uint_as_float(f2tf(v.w - hi.w));
            p4[i] = hi;
            size_t b = i / ((size_t)OTOT * 512);
            size_t rem = i - b * OTOT * 512;            // (ch,n4) within batch
            klo4[b * 32 * 512 + (rem - (size_t)32 * 512)] = lo;
        } else {                             // V: leaky + tf32 round
            v.x = v.x > 0.f ? v.x : 0.2f * v.x;
            v.y = v.y > 0.f ? v.y : 0.2f * v.y;
            v.z = v.z > 0.f ? v.z : 0.2f * v.z;
            v.w = v.w > 0.f ? v.w : 0.2f * v.w;
            v.x = __uint_as_float(f2tf(v.x)); v.y = __uint_as_float(f2tf(v.y));
            v.z = __uint_as_float(f2tf(v.z)); v.w = __uint_as_float(f2tf(v.w));
            p4[i] = v;
        }
    }
}

// ================= Kernel 4: mhat = |q_n| * max_m |k_m| =================
__global__ void __launch_bounds__(256) mh_kernel()
{
    const int b = blockIdx.x, tid = threadIdx.x;
    __shared__ float red[256];
    const float* pj = g_proj + (size_t)b * OTOT * NDIM;
    const float* kl = g_klo + (size_t)b * 32 * NDIM;
    float km = 0.0f;
    for (int n = tid; n < NDIM; n += 256) {
        float s = 0.0f;
#pragma unroll
        for (int d = 0; d < 32; d++) {
            float kv = pj[(size_t)(32 + d) * NDIM + n] + kl[(size_t)d * NDIM + n];
            s += kv * kv;
        }
        km = fmaxf(km, s);
    }
    red[tid] = km; __syncthreads();
    for (int off = 128; off; off >>= 1) { if (tid < off) red[tid] = fmaxf(red[tid], red[tid + off]); __syncthreads(); }
    const float kmax = sqrtf(red[0]) * 1.00001f;
    for (int n = tid; n < NDIM; n += 256) {
        float s = 0.0f;
#pragma unroll
        for (int d = 0; d < 32; d++) { float qv = pj[(size_t)d * NDIM + n]; s += qv * qv; }
        g_mhat[b * NDIM + n] = sqrtf(s) * kmax;
    }
}

// ================= Kernel 5: mma.sync tf32 flash attention =================
// smem floats: khi[2][32][72] | klo[2][32][72] | v[2][256][68] | p[64][72] | L[64]
#define KHI_F 0
#define KLO_F 4608
#define V_F   9216
#define P_F   44032
#define L_F   48640
#define SM_FLOATS 48704

__global__ void __launch_bounds__(256, 1) attn_kernel(
    const float* __restrict__ x, float* __restrict__ out)
{
    extern __shared__ __align__(16) float sm[];
    const u32 sb = smem_u32(sm);
    const int tid = threadIdx.x, wid = tid >> 5, lane = tid & 31;
    const int wm = wid & 3, wc = wid >> 2;
    const int tg = lane >> 2, tq = lane & 3;
    const int n0 = blockIdx.x * 64, b = blockIdx.y;
    const float* pj = g_proj + (size_t)b * OTOT * NDIM;
    const float* klg = g_klo + (size_t)b * 32 * NDIM;
    const int r0 = 16 * wm + tg;

    if (tid < 64) sm[L_F + tid] = 0.0f;

    // Q A-fragments (hi/lo tf32), kept in registers for all 32 tiles
    u32 qh[4][4], ql[4][4];
#pragma unroll
    for (int kk = 0; kk < 4; kk++) {
#pragma unroll
        for (int j = 0; j < 4; j++) {
            int r = r0 + (j & 1) * 8;
            int d = 8 * kk + tq + (j >> 1) * 4;
            float qv = pj[(size_t)d * NDIM + n0 + r];
            qh[kk][j] = f2tf(qv);
            ql[kk][j] = f2tf(qv - __uint_as_float(qh[kk][j]));
        }
    }
    const float mh0 = g_mhat[b * NDIM + n0 + r0];
    const float mh1 = g_mhat[b * NDIM + n0 + r0 + 8];

    float acc[16][4];
#pragma unroll
    for (int nf = 0; nf < 16; nf++)
#pragma unroll
        for (int j = 0; j < 4; j++) acc[nf][j] = 0.0f;
    float Lp0 = 0.0f, Lp1 = 0.0f;

    // cp.async tile issuer: 5120 16B chunks (Khi 512, Klo 512, V 4096)
    auto issue_tile = [&](int m0, int buf) {
        u32 kh = sb + (KHI_F + buf * 2304) * 4;
        u32 kl = sb + (KLO_F + buf * 2304) * 4;
        u32 vv = sb + (V_F + buf * 17408) * 4;
#pragma unroll
        for (int i = 0; i < 20; i++) {
            int id = tid + i * 256;
            const float* src; u32 dst;
            if (id < 512) {
                int d = id >> 4, ch = id & 15;
                src = pj + (size_t)(32 + d) * NDIM + m0 + ch * 4;
                dst = kh + d * 288 + ch * 16;
            } else if (id < 1024) {
                int j = id - 512, d = j >> 4, ch = j & 15;
                src = klg + (size_t)d * NDIM + m0 + ch * 4;
                dst = kl + d * 288 + ch * 16;
            } else {
                int j = id - 1024, c = j >> 4, ch = j & 15;
                src = pj + (size_t)(64 + c) * NDIM + m0 + ch * 4;
                dst = vv + c * 272 + ch * 16;
            }
            CP16(dst, src);
        }
        CP_COMMIT();
    };

    issue_tile(0, 0);

    for (int t = 0; t < 32; t++) {
        const int buf = t & 1;
        if (t < 31) { issue_tile((t + 1) * 64, buf ^ 1); CP_WAIT1(); }
        else        { CP_WAIT0(); }
        __syncthreads();

        // ---- S = Q K^T (3-pass hi/lo tf32) ----
        const float* KH = sm + KHI_F + buf * 2304;
        const float* KL = sm + KLO_F + buf * 2304;
        float sf[4][4];
#pragma unroll
        for (int nf = 0; nf < 4; nf++) {
#pragma unroll
            for (int j = 0; j < 4; j++) sf[nf][j] = 0.0f;
            const int mcol = 32 * wc + 8 * nf + tg;
#pragma unroll
            for (int kk = 0; kk < 4; kk++) {
                const int d = 8 * kk + tq;
                u32 bh0 = __float_as_uint(KH[d * 72 + mcol]);
                u32 bh1 = __float_as_uint(KH[(d + 4) * 72 + mcol]);
                u32 bl0 = __float_as_uint(KL[d * 72 + mcol]);
                u32 bl1 = __float_as_uint(KL[(d + 4) * 72 + mcol]);
                mma8(sf[nf], qh[kk], bh0, bh1);
                mma8(sf[nf], ql[kk], bh0, bh1);
                mma8(sf[nf], qh[kk], bl0, bl1);
            }
        }

        // ---- softmax with fixed upper-bound max ----
#pragma unroll
        for (int nf = 0; nf < 4; nf++) {
            const int col = 32 * wc + 8 * nf + 2 * tq;
            float p0 = __uint_as_float(f2tf(__expf(sf[nf][0] - mh0)));
            float p1 = __uint_as_float(f2tf(__expf(sf[nf][1] - mh0)));
            float p2 = __uint_as_float(f2tf(__expf(sf[nf][2] - mh1)));
            float p3 = __uint_as_float(f2tf(__expf(sf[nf][3] - mh1)));
            Lp0 += p0 + p1; Lp1 += p2 + p3;
            sm[P_F + r0 * 72 + col] = p0;
            sm[P_F + r0 * 72 + col + 1] = p1;
            sm[P_F + (r0 + 8) * 72 + col] = p2;
            sm[P_F + (r0 + 8) * 72 + col + 1] = p3;
        }
        __syncthreads();

        // ---- PV: O += P V^T ----
        const float* V = sm + V_F + buf * 17408;
#pragma unroll
        for (int kk = 0; kk < 8; kk++) {
            u32 af[4];
            af[0] = __float_as_uint(sm[P_F + r0 * 72 + 8 * kk + tq]);
            af[1] = __float_as_uint(sm[P_F + (r0 + 8) * 72 + 8 * kk + tq]);
            af[2] = __float_as_uint(sm[P_F + r0 * 72 + 8 * kk + tq + 4]);
            af[3] = __float_as_uint(sm[P_F + (r0 + 8) * 72 + 8 * kk + tq + 4]);
#pragma unroll
            for (int nf = 0; nf < 16; nf++) {
                const int c = 128 * wc + 8 * nf + tg;
                u32 b0 = __float_as_uint(V[c * 68 + 8 * kk + tq]);
                u32 b1 = __float_as_uint(V[c * 68 + 8 * kk + tq + 4]);
                mma8(acc[nf], af, b0, b1);
            }
        }
        __syncthreads();
    }

    // ---- L reduction ----
    Lp0 += __shfl_xor_sync(0xffffffffu, Lp0, 1);
    Lp0 += __shfl_xor_sync(0xffffffffu, Lp0, 2);
    Lp1 += __shfl_xor_sync(0xffffffffu, Lp1, 1);
    Lp1 += __shfl_xor_sync(0xffffffffu, Lp1, 2);
    if (tq == 0) {
        atomicAdd(&sm[L_F + r0], Lp0);
        atomicAdd(&sm[L_F + r0 + 8], Lp1);
    }
    __syncthreads();

    // ---- epilogue: O/L + residual ----
    const float il0 = 1.0f / sm[L_F + r0];
    const float il1 = 1.0f / sm[L_F + r0 + 8];
#pragma unroll
    for (int nf = 0; nf < 16; nf++) {
        const int c = 128 * wc + 8 * nf + 2 * tq;
        size_t g00 = ((size_t)b * CDIM + c) * NDIM + n0 + r0;
        size_t g01 = g00 + NDIM;          // c+1
        size_t g10 = g00 + 8;             // r0+8
        size_t g11 = g01 + 8;
        out[g00] = acc[nf][0] * il0 + x[g00];
        out[g01] = acc[nf][1] * il0 + x[g01];
        out[g10] = acc[nf][2] * il1 + x[g10];
        out[g11] = acc[nf][3] * il1 + x[g11];
    }
}

extern "C" void kernel_launch(void* const* d_in, const int* in_sizes, int n_in,
                              void* d_out, int out_size) {
    const float* x    = (const float*)d_in[0];
    const float* q_w  = (const float*)d_in[1];
    const float* q_g  = (const float*)d_in[3];
    const float* q_be = (const float*)d_in[4];
    const float* k_w  = (const float*)d_in[5];
    const float* k_g  = (const float*)d_in[7];
    const float* k_be = (const float*)d_in[8];
    const float* v_w  = (const float*)d_in[9];
    const float* v_g  = (const float*)d_in[11];
    const float* v_be = (const float*)d_in[12];
    float* out = (float*)d_out;

    proj_kernel<<<dim3(5, 32, 16), 256>>>(x, q_w, k_w, v_w);
    stats_kernel<<<320, 256>>>(q_g, q_be, k_g, k_be, v_g, v_be);
    norm_kernel<<<2048, 256>>>();
    mh_kernel<<<16, 256>>>();

    static int smem_set = 0;
    if (!smem_set) {
        cudaFuncSetAttribute(attn_kernel, cudaFuncAttributeMaxDynamicSharedMemorySize,
                             SM_FLOATS * (int)sizeof(float));
        smem_set = 1;
    }
    attn_kernel<<<dim3(32, 16), 256, SM_FLOATS * sizeof(float)>>>(x, out);
}

// round 5
// speedup vs baseline: 2.6041x; 1.0630x over previous
#include <cuda_runtime.h>
#include <math.h>
#include <stdint.h>

typedef unsigned int u32;
typedef unsigned long long u64;

#define BDIM 16
#define CDIM 256
#define NDIM 2048
#define OTOT 320
#define EPSV 1e-5f

__device__ __align__(16) float g_proj[(size_t)BDIM * OTOT * NDIM];
__device__ __align__(16) float g_klo[(size_t)BDIM * 32 * NDIM];
__device__ float g_mhat[BDIM * NDIM];
__device__ float g_kpart[BDIM * 16];
__device__ float g_scale[OTOT];
__device__ float g_shift[OTOT];

// ---------------- helpers ----------------
__device__ __forceinline__ u64 dup2(float v) {
    u64 r; asm("mov.b64 %0, {%1, %1};" : "=l"(r) : "f"(v)); return r;
}
__device__ __forceinline__ void up2(u64 a, float& lo, float& hi) {
    asm("mov.b64 {%0, %1}, %2;" : "=f"(lo), "=f"(hi) : "l"(a));
}
__device__ __forceinline__ void fma2(u64& d, u64 a, u64 b) {
    asm("fma.rn.f32x2 %0, %1, %2, %3;" : "=l"(d) : "l"(a), "l"(b), "l"(d));
}
__device__ __forceinline__ u32 f2tf(float f) {
    u32 r; asm("cvt.rna.tf32.f32 %0, %1;" : "=r"(r) : "f"(f)); return r;
}
__device__ __forceinline__ u32 smem_u32(const void* p) {
    u32 a; asm("{ .reg .u64 t; cvta.to.shared.u64 t, %1; cvt.u32.u64 %0, t; }" : "=r"(a) : "l"(p));
    return a;
}
__device__ __forceinline__ void mma8(float d[4], const u32 a[4], u32 b0, u32 b1) {
    asm volatile("mma.sync.aligned.m16n8k8.row.col.f32.tf32.tf32.f32 "
                 "{%0,%1,%2,%3}, {%4,%5,%6,%7}, {%8,%9}, {%0,%1,%2,%3};"
                 : "+f"(d[0]), "+f"(d[1]), "+f"(d[2]), "+f"(d[3])
                 : "r"(a[0]), "r"(a[1]), "r"(a[2]), "r"(a[3]), "r"(b0), "r"(b1));
}
#define CP16(dst, src) asm volatile("cp.async.cg.shared.global [%0], [%1], 16;" :: "r"(dst), "l"(src))
#define CP_COMMIT()    asm volatile("cp.async.commit_group;" ::: "memory")
#define CP_WAIT1()     asm volatile("cp.async.wait_group 1;" ::: "memory")
#define CP_WAIT0()     asm volatile("cp.async.wait_group 0;" ::: "memory")

// ================= Kernel 1: fused QKV projection (f32x2) =================
__global__ void __launch_bounds__(256) proj_kernel(
    const float* __restrict__ x, const float* __restrict__ qw,
    const float* __restrict__ kw, const float* __restrict__ vw)
{
    __shared__ float w_s[64 * 17];
    __shared__ __align__(16) float x_s[16 * 64];
    const int tid = threadIdx.x;
    const int o0 = blockIdx.x * 64, n0 = blockIdx.y * 64, b = blockIdx.z;
    const int to = tid >> 4, tn = tid & 15;

    u64 acc[4][2];
#pragma unroll
    for (int i = 0; i < 4; i++) { acc[i][0] = 0ULL; acc[i][1] = 0ULL; }

    for (int c0 = 0; c0 < CDIM; c0 += 16) {
        __syncthreads();
#pragma unroll
        for (int p = 0; p < 4; p++) {
            int o = (tid >> 4) + p * 16, cc = tid & 15, og = o0 + o;
            const float* wr;
            if (og < 32)      wr = qw + (size_t)og * CDIM;
            else if (og < 64) wr = kw + (size_t)(og - 32) * CDIM;
            else              wr = vw + (size_t)(og - 64) * CDIM;
            w_s[o * 17 + cc] = wr[c0 + cc];
        }
#pragma unroll
        for (int p = 0; p < 4; p++) {
            int cc = (tid >> 6) + p * 4, nn = tid & 63;
            x_s[cc * 64 + nn] = x[((size_t)b * CDIM + c0 + cc) * NDIM + n0 + nn];
        }
        __syncthreads();
#pragma unroll
        for (int cc = 0; cc < 16; cc++) {
            const u64* xp = reinterpret_cast<const u64*>(&x_s[cc * 64 + tn * 4]);
            u64 x01 = xp[0], x23 = xp[1];
#pragma unroll
            for (int i = 0; i < 4; i++) {
                u64 ad = dup2(w_s[(to * 4 + i) * 17 + cc]);
                fma2(acc[i][0], ad, x01);
                fma2(acc[i][1], ad, x23);
            }
        }
    }
#pragma unroll
    for (int i = 0; i < 4; i++) {
        float r0, r1, r2, r3;
        up2(acc[i][0], r0, r1); up2(acc[i][1], r2, r3);
        *reinterpret_cast<float4*>(
            &g_proj[((size_t)b * OTOT + o0 + to * 4 + i) * NDIM + n0 + tn * 4]) =
            make_float4(r0, r1, r2, r3);
    }
}

// ================= Kernel 2: BN stats (single pass) =================
__global__ void __launch_bounds__(256) stats_kernel(
    const float* __restrict__ qg, const float* __restrict__ qbe,
    const float* __restrict__ kg, const float* __restrict__ kbe,
    const float* __restrict__ vg, const float* __restrict__ vbe)
{
    const int ch = blockIdx.x, tid = threadIdx.x;
    __shared__ float r1[256], r2[256];
    const float* base = g_proj + (size_t)ch * NDIM;
    const float invM = 1.0f / (float)(BDIM * NDIM);

    float s = 0.0f, s2 = 0.0f;
    for (int b = 0; b < BDIM; b++) {
        const float4* p = reinterpret_cast<const float4*>(base + (size_t)b * OTOT * NDIM);
        for (int n = tid; n < NDIM / 4; n += 256) {
            float4 v = p[n];
            s += (v.x + v.y) + (v.z + v.w);
            s2 += (v.x * v.x + v.y * v.y) + (v.z * v.z + v.w * v.w);
        }
    }
    r1[tid] = s; r2[tid] = s2; __syncthreads();
    for (int off = 128; off; off >>= 1) {
        if (tid < off) { r1[tid] += r1[tid + off]; r2[tid] += r2[tid + off]; }
        __syncthreads();
    }
    if (tid == 0) {
        float mean = r1[0] * invM;
        float var = r2[0] * invM - mean * mean;
        float gamma, beta;
        if (ch < 32)      { gamma = qg[ch];      beta = qbe[ch]; }
        else if (ch < 64) { gamma = kg[ch - 32]; beta = kbe[ch - 32]; }
        else              { gamma = vg[ch - 64]; beta = vbe[ch - 64]; }
        float sc = gamma * rsqrtf(var + EPSV);
        g_scale[ch] = sc;
        g_shift[ch] = beta - mean * sc;
    }
}

// ================= Kernel 3: normalize in place; K->hi/lo; V->leaky+tf32 =================
__global__ void __launch_bounds__(256) norm_kernel()
{
    const size_t total4 = (size_t)BDIM * OTOT * NDIM / 4;
    float4* p4 = reinterpret_cast<float4*>(g_proj);
    float4* klo4 = reinterpret_cast<float4*>(g_klo);
    for (size_t i = (size_t)blockIdx.x * blockDim.x + threadIdx.x; i < total4;
         i += (size_t)gridDim.x * blockDim.x) {
        int ch = (int)((i >> 9) % OTOT);
        float sc = g_scale[ch], sh = g_shift[ch];
        float4 v = p4[i];
        v.x = v.x * sc + sh; v.y = v.y * sc + sh;
        v.z = v.z * sc + sh; v.w = v.w * sc + sh;
        if (ch < 32) {
            p4[i] = v;
        } else if (ch < 64) {
            float4 hi, lo;
            hi.x = __uint_as_float(f2tf(v.x)); lo.x = __uint_as_float(f2tf(v.x - hi.x));
            hi.y = __uint_as_float(f2tf(v.y)); lo.y = __uint_as_float(f2tf(v.y - hi.y));
            hi.z = __uint_as_float(f2tf(v.z)); lo.z = __uint_as_float(f2tf(v.z - hi.z));
            hi.w = __uint_as_float(f2tf(v.w)); lo.w = __uint_as_float(f2tf(v.w - hi.w));
            p4[i] = hi;
            size_t b = i / ((size_t)OTOT * 512);
            size_t rem = i - b * OTOT * 512;
            klo4[b * 32 * 512 + (rem - (size_t)32 * 512)] = lo;
        } else {
            v.x = v.x > 0.f ? v.x : 0.2f * v.x;
            v.y = v.y > 0.f ? v.y : 0.2f * v.y;
            v.z = v.z > 0.f ? v.z : 0.2f * v.z;
            v.w = v.w > 0.f ? v.w : 0.2f * v.w;
            v.x = __uint_as_float(f2tf(v.x)); v.y = __uint_as_float(f2tf(v.y));
            v.z = __uint_as_float(f2tf(v.z)); v.w = __uint_as_float(f2tf(v.w));
            p4[i] = v;
        }
    }
}

// ================= Kernel 4a: partial max ||k||^2 =================
__global__ void __launch_bounds__(128) mh1_kernel()
{
    const int b = blockIdx.x, sl = blockIdx.y, tid = threadIdx.x;
    __shared__ float red[128];
    const float* pj = g_proj + (size_t)b * OTOT * NDIM;
    const float* kl = g_klo + (size_t)b * 32 * NDIM;
    const int n = sl * 128 + tid;
    float s = 0.0f;
#pragma unroll
    for (int d = 0; d < 32; d++) {
        float kv = pj[(size_t)(32 + d) * NDIM + n] + kl[(size_t)d * NDIM + n];
        s += kv * kv;
    }
    red[tid] = s; __syncthreads();
    for (int off = 64; off; off >>= 1) {
        if (tid < off) red[tid] = fmaxf(red[tid], red[tid + off]);
        __syncthreads();
    }
    if (tid == 0) g_kpart[b * 16 + sl] = red[0];
}

// ================= Kernel 4b: mhat = |q_n| * max|k| =================
__global__ void __launch_bounds__(256) mh2_kernel()
{
    const int b = blockIdx.y, tid = threadIdx.x;
    const int n = blockIdx.x * 256 + tid;
    float km = 0.0f;
#pragma unroll
    for (int i = 0; i < 16; i++) km = fmaxf(km, g_kpart[b * 16 + i]);
    const float kmax = sqrtf(km) * 1.00001f;
    const float* pj = g_proj + (size_t)b * OTOT * NDIM;
    float s = 0.0f;
#pragma unroll
    for (int d = 0; d < 32; d++) { float qv = pj[(size_t)d * NDIM + n]; s += qv * qv; }
    g_mhat[b * NDIM + n] = sqrtf(s) * kmax;
}

// ================= Kernel 5: mma.sync tf32 flash attention =================
// smem floats: khi[2][32][72] | klo[2][32][72] | v[2][256][68] | p[64][76] | L[64]
#define KHI_F 0
#define KLO_F 4608
#define V_F   9216
#define P_F   44032
#define PSTR  76
#define L_F   48896
#define SM_FLOATS 48960

__global__ void __launch_bounds__(256, 1) attn_kernel(
    const float* __restrict__ x, float* __restrict__ out)
{
    extern __shared__ __align__(16) float sm[];
    const u32 sb = smem_u32(sm);
    const int tid = threadIdx.x, wid = tid >> 5, lane = tid & 31;
    const int wm = wid & 3, wc = wid >> 2;       // S-phase mapping
    const int tg = lane >> 2, tq = lane & 3;
    const int n0 = blockIdx.x * 64, b = blockIdx.y;
    const float* pj = g_proj + (size_t)b * OTOT * NDIM;
    const float* klg = g_klo + (size_t)b * 32 * NDIM;
    const int r0 = 16 * wm + tg;

    if (tid < 64) sm[L_F + tid] = 0.0f;

    // Q A-fragments (hi/lo tf32), registers for all tiles
    u32 qh[4][4], ql[4][4];
#pragma unroll
    for (int kk = 0; kk < 4; kk++) {
#pragma unroll
        for (int j = 0; j < 4; j++) {
            int r = r0 + (j & 1) * 8;
            int d = 8 * kk + tq + (j >> 1) * 4;
            float qv = pj[(size_t)d * NDIM + n0 + r];
            qh[kk][j] = f2tf(qv);
            ql[kk][j] = f2tf(qv - __uint_as_float(qh[kk][j]));
        }
    }
    const float mh0 = g_mhat[b * NDIM + n0 + r0];
    const float mh1 = g_mhat[b * NDIM + n0 + r0 + 8];

    // PV accumulators: warp covers ALL 64 rows x 32 channels (c = 32*wid..)
    float acc[4][4][4];   // [mj][nf][frag]
#pragma unroll
    for (int mj = 0; mj < 4; mj++)
#pragma unroll
        for (int nf = 0; nf < 4; nf++)
#pragma unroll
            for (int j = 0; j < 4; j++) acc[mj][nf][j] = 0.0f;
    float Lp0 = 0.0f, Lp1 = 0.0f;

    auto issue_tile = [&](int m0, int buf) {
        u32 kh = sb + (KHI_F + buf * 2304) * 4;
        u32 kl = sb + (KLO_F + buf * 2304) * 4;
        u32 vv = sb + (V_F + buf * 17408) * 4;
#pragma unroll
        for (int i = 0; i < 20; i++) {
            int id = tid + i * 256;
            const float* src; u32 dst;
            if (id < 512) {
                int d = id >> 4, ch = id & 15;
                src = pj + (size_t)(32 + d) * NDIM + m0 + ch * 4;
                dst = kh + d * 288 + ch * 16;
            } else if (id < 1024) {
                int j = id - 512, d = j >> 4, ch = j & 15;
                src = klg + (size_t)d * NDIM + m0 + ch * 4;
                dst = kl + d * 288 + ch * 16;
            } else {
                int j = id - 1024, c = j >> 4, ch = j & 15;
                src = pj + (size_t)(64 + c) * NDIM + m0 + ch * 4;
                dst = vv + c * 272 + ch * 16;
            }
            CP16(dst, src);
        }
        CP_COMMIT();
    };

    issue_tile(0, 0);

    for (int t = 0; t < 32; t++) {
        const int buf = t & 1;
        if (t < 31) { issue_tile((t + 1) * 64, buf ^ 1); CP_WAIT1(); }
        else        { CP_WAIT0(); }
        __syncthreads();

        // ---- S = Q K^T (3-pass hi/lo tf32), warp: rows 16wm..+15, cols 32wc..+31
        const float* KH = sm + KHI_F + buf * 2304;
        const float* KL = sm + KLO_F + buf * 2304;
        float sf[4][4];
#pragma unroll
        for (int nf = 0; nf < 4; nf++) {
#pragma unroll
            for (int j = 0; j < 4; j++) sf[nf][j] = 0.0f;
            const int mcol = 32 * wc + 8 * nf + tg;
#pragma unroll
            for (int kk = 0; kk < 4; kk++) {
                const int d = 8 * kk + tq;
                u32 bh0 = __float_as_uint(KH[d * 72 + mcol]);
                u32 bh1 = __float_as_uint(KH[(d + 4) * 72 + mcol]);
                u32 bl0 = __float_as_uint(KL[d * 72 + mcol]);
                u32 bl1 = __float_as_uint(KL[(d + 4) * 72 + mcol]);
                mma8(sf[nf], qh[kk], bh0, bh1);
                mma8(sf[nf], ql[kk], bh0, bh1);
                mma8(sf[nf], qh[kk], bl0, bl1);
            }
        }

        // ---- softmax with fixed upper-bound max ----
#pragma unroll
        for (int nf = 0; nf < 4; nf++) {
            const int col = 32 * wc + 8 * nf + 2 * tq;
            float p0 = __uint_as_float(f2tf(__expf(sf[nf][0] - mh0)));
            float p1 = __uint_as_float(f2tf(__expf(sf[nf][1] - mh0)));
            float p2 = __uint_as_float(f2tf(__expf(sf[nf][2] - mh1)));
            float p3 = __uint_as_float(f2tf(__expf(sf[nf][3] - mh1)));
            Lp0 += p0 + p1; Lp1 += p2 + p3;
            sm[P_F + r0 * PSTR + col] = p0;
            sm[P_F + r0 * PSTR + col + 1] = p1;
            sm[P_F + (r0 + 8) * PSTR + col] = p2;
            sm[P_F + (r0 + 8) * PSTR + col + 1] = p3;
        }
        __syncthreads();

        // ---- PV: warp = 64 rows x 32 channels; A-frags share B-frags ----
        const float* V = sm + V_F + buf * 17408;
#pragma unroll
        for (int kk = 0; kk < 8; kk++) {
            u32 af[4][4];
#pragma unroll
            for (int mj = 0; mj < 4; mj++) {
                const int rr = 16 * mj + tg;
                af[mj][0] = __float_as_uint(sm[P_F + rr * PSTR + 8 * kk + tq]);
                af[mj][1] = __float_as_uint(sm[P_F + (rr + 8) * PSTR + 8 * kk + tq]);
                af[mj][2] = __float_as_uint(sm[P_F + rr * PSTR + 8 * kk + tq + 4]);
                af[mj][3] = __float_as_uint(sm[P_F + (rr + 8) * PSTR + 8 * kk + tq + 4]);
            }
#pragma unroll
            for (int nf = 0; nf < 4; nf++) {
                const int c = 32 * wid + 8 * nf + tg;
                u32 b0 = __float_as_uint(V[c * 68 + 8 * kk + tq]);
                u32 b1 = __float_as_uint(V[c * 68 + 8 * kk + tq + 4]);
#pragma unroll
                for (int mj = 0; mj < 4; mj++)
                    mma8(acc[mj][nf], af[mj], b0, b1);
            }
        }
        __syncthreads();
    }

    // ---- L reduction (S-phase row ownership) ----
    Lp0 += __shfl_xor_sync(0xffffffffu, Lp0, 1);
    Lp0 += __shfl_xor_sync(0xffffffffu, Lp0, 2);
    Lp1 += __shfl_xor_sync(0xffffffffu, Lp1, 1);
    Lp1 += __shfl_xor_sync(0xffffffffu, Lp1, 2);
    if (tq == 0) {
        atomicAdd(&sm[L_F + r0], Lp0);
        atomicAdd(&sm[L_F + r0 + 8], Lp1);
    }
    __syncthreads();

    // ---- epilogue: O/L + residual (PV mapping) ----
#pragma unroll
    for (int mj = 0; mj < 4; mj++) {
        const int rr = 16 * mj + tg;
        const float il0 = 1.0f / sm[L_F + rr];
        const float il1 = 1.0f / sm[L_F + rr + 8];
#pragma unroll
        for (int nf = 0; nf < 4; nf++) {
            const int c = 32 * wid + 8 * nf + 2 * tq;
            size_t g00 = ((size_t)b * CDIM + c) * NDIM + n0 + rr;
            size_t g01 = g00 + NDIM;
            size_t g10 = g00 + 8;
            size_t g11 = g01 + 8;
            out[g00] = acc[mj][nf][0] * il0 + x[g00];
            out[g01] = acc[mj][nf][1] * il0 + x[g01];
            out[g10] = acc[mj][nf][2] * il1 + x[g10];
            out[g11] = acc[mj][nf][3] * il1 + x[g11];
        }
    }
}

extern "C" void kernel_launch(void* const* d_in, const int* in_sizes, int n_in,
                              void* d_out, int out_size) {
    const float* x    = (const float*)d_in[0];
    const float* q_w  = (const float*)d_in[1];
    const float* q_g  = (const float*)d_in[3];
    const float* q_be = (const float*)d_in[4];
    const float* k_w  = (const float*)d_in[5];
    const float* k_g  = (const float*)d_in[7];
    const float* k_be = (const float*)d_in[8];
    const float* v_w  = (const float*)d_in[9];
    const float* v_g  = (const float*)d_in[11];
    const float* v_be = (const float*)d_in[12];
    float* out = (float*)d_out;

    proj_kernel<<<dim3(5, 32, 16), 256>>>(x, q_w, k_w, v_w);
    stats_kernel<<<320, 256>>>(q_g, q_be, k_g, k_be, v_g, v_be);
    norm_kernel<<<2048, 256>>>();
    mh1_kernel<<<dim3(16, 16), 128>>>();
    mh2_kernel<<<dim3(8, 16), 256>>>();

    static int smem_set = 0;
    if (!smem_set) {
        cudaFuncSetAttribute(attn_kernel, cudaFuncAttributeMaxDynamicSharedMemorySize,
                             SM_FLOATS * (int)sizeof(float));
        smem_set = 1;
    }
    attn_kernel<<<dim3(32, 16), 256, SM_FLOATS * sizeof(float)>>>(x, out);
}

// round 7
// speedup vs baseline: 3.6732x; 1.4105x over previous
#include <cuda_runtime.h>
#include <cuda_fp16.h>
#include <math.h>
#include <stdint.h>

typedef unsigned int u32;
typedef unsigned long long u64;

#define BDIM 16
#define CDIM 256
#define NDIM 2048
#define OTOT 320
#define EPSV 1e-5f

__device__ __align__(16) float g_proj[(size_t)BDIM * OTOT * NDIM];
__device__ __align__(16) __half g_q16[(size_t)BDIM * NDIM * 64];  // [b][n][hi32|lo32]
__device__ __align__(16) __half g_k16[(size_t)BDIM * NDIM * 64];  // [b][m][hi32|lo32]
__device__ __align__(16) __half g_v16[(size_t)BDIM * CDIM * NDIM]; // [b][c][m]
__device__ float g_scale[OTOT];
__device__ float g_shift[OTOT];

// ---------------- helpers ----------------
__device__ __forceinline__ u64 dup2(float v) {
    u64 r; asm("mov.b64 %0, {%1, %1};" : "=l"(r) : "f"(v)); return r;
}
__device__ __forceinline__ void up2(u64 a, float& lo, float& hi) {
    asm("mov.b64 {%0, %1}, %2;" : "=f"(lo), "=f"(hi) : "l"(a));
}
__device__ __forceinline__ void fma2(u64& d, u64 a, u64 b) {
    asm("fma.rn.f32x2 %0, %1, %2, %3;" : "=l"(d) : "l"(a), "l"(b), "l"(d));
}
__device__ __forceinline__ u32 smem_u32(const void* p) {
    u32 a; asm("{ .reg .u64 t; cvta.to.shared.u64 t, %1; cvt.u32.u64 %0, t; }" : "=r"(a) : "l"(p));
    return a;
}
__device__ __forceinline__ void mma16(float d[4], const u32 a[4], u32 b0, u32 b1) {
    asm volatile("mma.sync.aligned.m16n8k16.row.col.f32.f16.f16.f32 "
                 "{%0,%1,%2,%3}, {%4,%5,%6,%7}, {%8,%9}, {%0,%1,%2,%3};"
                 : "+f"(d[0]), "+f"(d[1]), "+f"(d[2]), "+f"(d[3])
                 : "r"(a[0]), "r"(a[1]), "r"(a[2]), "r"(a[3]), "r"(b0), "r"(b1));
}
#define CP16(dst, src) asm volatile("cp.async.cg.shared.global [%0], [%1], 16;" :: "r"(dst), "l"(src))
#define CP_COMMIT()    asm volatile("cp.async.commit_group;" ::: "memory")
#define CP_WAIT1()     asm volatile("cp.async.wait_group 1;" ::: "memory")
#define CP_WAIT0()     asm volatile("cp.async.wait_group 0;" ::: "memory")

// ================= Kernel 1: fused QKV projection (f32x2) =================
__global__ void __launch_bounds__(256) proj_kernel(
    const float* __restrict__ x, const float* __restrict__ qw,
    const float* __restrict__ kw, const float* __restrict__ vw)
{
    __shared__ float w_s[64 * 17];
    __shared__ __align__(16) float x_s[16 * 64];
    const int tid = threadIdx.x;
    const int o0 = blockIdx.x * 64, n0 = blockIdx.y * 64, b = blockIdx.z;
    const int to = tid >> 4, tn = tid & 15;

    u64 acc[4][2];
#pragma unroll
    for (int i = 0; i < 4; i++) { acc[i][0] = 0ULL; acc[i][1] = 0ULL; }

    for (int c0 = 0; c0 < CDIM; c0 += 16) {
        __syncthreads();
#pragma unroll
        for (int p = 0; p < 4; p++) {
            int o = (tid >> 4) + p * 16, cc = tid & 15, og = o0 + o;
            const float* wr;
            if (og < 32)      wr = qw + (size_t)og * CDIM;
            else if (og < 64) wr = kw + (size_t)(og - 32) * CDIM;
            else              wr = vw + (size_t)(og - 64) * CDIM;
            w_s[o * 17 + cc] = wr[c0 + cc];
        }
#pragma unroll
        for (int p = 0; p < 4; p++) {
            int cc = (tid >> 6) + p * 4, nn = tid & 63;
            x_s[cc * 64 + nn] = x[((size_t)b * CDIM + c0 + cc) * NDIM + n0 + nn];
        }
        __syncthreads();
#pragma unroll
        for (int cc = 0; cc < 16; cc++) {
            const u64* xp = reinterpret_cast<const u64*>(&x_s[cc * 64 + tn * 4]);
            u64 x01 = xp[0], x23 = xp[1];
#pragma unroll
            for (int i = 0; i < 4; i++) {
                u64 ad = dup2(w_s[(to * 4 + i) * 17 + cc]);
                fma2(acc[i][0], ad, x01);
                fma2(acc[i][1], ad, x23);
            }
        }
    }
#pragma unroll
    for (int i = 0; i < 4; i++) {
        float r0, r1, r2, r3;
        up2(acc[i][0], r0, r1); up2(acc[i][1], r2, r3);
        *reinterpret_cast<float4*>(
            &g_proj[((size_t)b * OTOT + o0 + to * 4 + i) * NDIM + n0 + tn * 4]) =
            make_float4(r0, r1, r2, r3);
    }
}

// ================= Kernel 2: BN stats (single pass) =================
__global__ void __launch_bounds__(256) stats_kernel(
    const float* __restrict__ qg, const float* __restrict__ qbe,
    const float* __restrict__ kg, const float* __restrict__ kbe,
    const float* __restrict__ vg, const float* __restrict__ vbe)
{
    const int ch = blockIdx.x, tid = threadIdx.x;
    __shared__ float r1[256], r2[256];
    const float* base = g_proj + (size_t)ch * NDIM;
    const float invM = 1.0f / (float)(BDIM * NDIM);

    float s = 0.0f, s2 = 0.0f;
    for (int b = 0; b < BDIM; b++) {
        const float4* p = reinterpret_cast<const float4*>(base + (size_t)b * OTOT * NDIM);
        for (int n = tid; n < NDIM / 4; n += 256) {
            float4 v = p[n];
            s += (v.x + v.y) + (v.z + v.w);
            s2 += (v.x * v.x + v.y * v.y) + (v.z * v.z + v.w * v.w);
        }
    }
    r1[tid] = s; r2[tid] = s2; __syncthreads();
    for (int off = 128; off; off >>= 1) {
        if (tid < off) { r1[tid] += r1[tid + off]; r2[tid] += r2[tid + off]; }
        __syncthreads();
    }
    if (tid == 0) {
        float mean = r1[0] * invM;
        float var = r2[0] * invM - mean * mean;
        float gamma, beta;
        if (ch < 32)      { gamma = qg[ch];      beta = qbe[ch]; }
        else if (ch < 64) { gamma = kg[ch - 32]; beta = kbe[ch - 32]; }
        else              { gamma = vg[ch - 64]; beta = vbe[ch - 64]; }
        float sc = gamma * rsqrtf(var + EPSV);
        g_scale[ch] = sc;
        g_shift[ch] = beta - mean * sc;
    }
}

// ================= Kernel 3: Q/K normalize + transpose -> fp16 hi/lo =================
__global__ void __launch_bounds__(256) qkt_kernel()
{
    __shared__ float s[64][65];
    const int tid = threadIdx.x;
    const int n0 = blockIdx.x * 64, b = blockIdx.y;
    for (int idx = tid; idx < 4096; idx += 256) {
        int ch = idx >> 6, nn = idx & 63;
        s[ch][nn] = g_proj[((size_t)b * OTOT + ch) * NDIM + n0 + nn] * g_scale[ch] + g_shift[ch];
    }
    __syncthreads();
    const int n = tid >> 2, d0 = (tid & 3) * 8;
    const size_t row = ((size_t)b * NDIM + n0 + n) * 64;
#pragma unroll
    for (int qk = 0; qk < 2; qk++) {
        __half* dst = (qk ? g_k16 : g_q16) + row;
        u32 wh[4], wl[4];
#pragma unroll
        for (int j = 0; j < 4; j++) {
            float v0 = s[qk * 32 + d0 + 2 * j][n];
            float v1 = s[qk * 32 + d0 + 2 * j + 1][n];
            __half h0 = __float2half_rn(v0), h1 = __float2half_rn(v1);
            __half l0 = __float2half_rn(v0 - __half2float(h0));
            __half l1 = __float2half_rn(v1 - __half2float(h1));
            wh[j] = (u32)*(unsigned short*)&h0 | ((u32)*(unsigned short*)&h1 << 16);
            wl[j] = (u32)*(unsigned short*)&l0 | ((u32)*(unsigned short*)&l1 << 16);
        }
        *reinterpret_cast<uint4*>(dst + d0)      = make_uint4(wh[0], wh[1], wh[2], wh[3]);
        *reinterpret_cast<uint4*>(dst + 32 + d0) = make_uint4(wl[0], wl[1], wl[2], wl[3]);
    }
}

// ================= Kernel 4: V normalize + leaky -> fp16 =================
__global__ void __launch_bounds__(256) v16_kernel()
{
    const int b = blockIdx.y;
    const int i4 = blockIdx.x * 256 + threadIdx.x;
    const int i = i4 * 4;
    const int c = i >> 11, n = i & 2047;
    float4 v = *reinterpret_cast<const float4*>(&g_proj[((size_t)b * OTOT + 64 + c) * NDIM + n]);
    float sc = g_scale[64 + c], sh = g_shift[64 + c];
    float a0 = v.x * sc + sh, a1 = v.y * sc + sh, a2 = v.z * sc + sh, a3 = v.w * sc + sh;
    a0 = a0 > 0.f ? a0 : 0.2f * a0; a1 = a1 > 0.f ? a1 : 0.2f * a1;
    a2 = a2 > 0.f ? a2 : 0.2f * a2; a3 = a3 > 0.f ? a3 : 0.2f * a3;
    __half2 p0 = __floats2half2_rn(a0, a1), p1 = __floats2half2_rn(a2, a3);
    uint2 w = make_uint2(*(u32*)&p0, *(u32*)&p1);
    *reinterpret_cast<uint2*>(&g_v16[((size_t)b * CDIM + c) * NDIM + n]) = w;
}

// ================= Kernel 5: fp16 mma flash attention (online softmax) =================
#define OFF_K0 0
#define OFF_K1 9216
#define OFF_V0 18432
#define OFF_V1 55296
#define OFF_P  92160
#define OFF_M  101376
#define OFF_L  101888
#define OFF_A  102144
#define OFF_RM 102400
#define OFF_PS 102912
#define SMEM_TOTAL 103424

__global__ void __launch_bounds__(256, 2) attn_kernel(
    const float* __restrict__ x, float* __restrict__ out)
{
    extern __shared__ __align__(16) char smc[];
    const u32 sb = smem_u32(smc);
    float* Mbuf = (float*)(smc + OFF_M);
    float* Lbuf = (float*)(smc + OFF_L);
    float* Abuf = (float*)(smc + OFF_A);
    float* Rm   = (float*)(smc + OFF_RM);
    float* Psum = (float*)(smc + OFF_PS);

    const int tid = threadIdx.x, wid = tid >> 5, lane = tid & 31;
    const int wm = wid & 3, wc = wid >> 2;
    const int tg = lane >> 2, tq = lane & 3;
    const int n0 = blockIdx.x * 64, b = blockIdx.y;
    const int r0 = 16 * wm + tg;
    const bool owner = (wc == 0 && tq == 0);

    if (tid < 64) { Mbuf[tid] = -INFINITY; Lbuf[tid] = 0.0f; }

    // Q A-fragments (hi/lo fp16), registers for all tiles
    u32 qh[2][4], ql[2][4];
    {
        const __half* Qg = g_q16 + ((size_t)b * NDIM + n0) * 64;
#pragma unroll
        for (int kk = 0; kk < 2; kk++) {
            int d = kk * 16 + 2 * tq;
            qh[kk][0] = *(const u32*)(Qg + (size_t)r0 * 64 + d);
            qh[kk][1] = *(const u32*)(Qg + (size_t)(r0 + 8) * 64 + d);
            qh[kk][2] = *(const u32*)(Qg + (size_t)r0 * 64 + d + 8);
            qh[kk][3] = *(const u32*)(Qg + (size_t)(r0 + 8) * 64 + d + 8);
            ql[kk][0] = *(const u32*)(Qg + (size_t)r0 * 64 + 32 + d);
            ql[kk][1] = *(const u32*)(Qg + (size_t)(r0 + 8) * 64 + 32 + d);
            ql[kk][2] = *(const u32*)(Qg + (size_t)r0 * 64 + 32 + d + 8);
            ql[kk][3] = *(const u32*)(Qg + (size_t)(r0 + 8) * 64 + 32 + d + 8);
        }
    }

    float acc[4][4][4];
#pragma unroll
    for (int mj = 0; mj < 4; mj++)
#pragma unroll
        for (int nf = 0; nf < 4; nf++)
#pragma unroll
            for (int j = 0; j < 4; j++) acc[mj][nf][j] = 0.0f;

    auto issue_tile = [&](int m0, int buf) {
        u32 kb = sb + (buf ? OFF_K1 : OFF_K0);
        u32 vb = sb + (buf ? OFF_V1 : OFF_V0);
        const __half* Kg = g_k16 + ((size_t)b * NDIM + m0) * 64;
        const __half* Vg = g_v16 + (size_t)b * CDIM * NDIM + m0;
#pragma unroll
        for (int i = 0; i < 10; i++) {
            int id = tid + i * 256;
            if (id < 512) {
                int m = id >> 3, ch = id & 7;
                CP16(kb + m * 144 + ch * 16, Kg + (size_t)m * 64 + ch * 8);
            } else {
                int j = id - 512, c = j >> 3, ch = j & 7;
                CP16(vb + c * 144 + ch * 16, Vg + (size_t)c * NDIM + ch * 8);
            }
        }
        CP_COMMIT();
    };

    issue_tile(0, 0);

    for (int t = 0; t < 32; t++) {
        const int buf = t & 1, par = t & 1;
        if (t < 31) { issue_tile((t + 1) * 64, buf ^ 1); CP_WAIT1(); }
        else        { CP_WAIT0(); }
        __syncthreads();   // K/V of tile t visible to all threads

        // ---- S = Q K^T, fp16 3-pass hi/lo ----
        const char* K = smc + (buf ? OFF_K1 : OFF_K0);
        float sf[4][4];
#pragma unroll
        for (int nf = 0; nf < 4; nf++) {
#pragma unroll
            for (int j = 0; j < 4; j++) sf[nf][j] = 0.0f;
            const char* krow = K + (32 * wc + 8 * nf + tg) * 144;
#pragma unroll
            for (int kk = 0; kk < 2; kk++) {
                int d = kk * 16 + 2 * tq;
                u32 bh0 = *(const u32*)(krow + d * 2);
                u32 bh1 = *(const u32*)(krow + (d + 8) * 2);
                u32 bl0 = *(const u32*)(krow + (32 + d) * 2);
                u32 bl1 = *(const u32*)(krow + (32 + d + 8) * 2);
                mma16(sf[nf], qh[kk], bh0, bh1);
                mma16(sf[nf], ql[kk], bh0, bh1);
                mma16(sf[nf], qh[kk], bl0, bl1);
            }
        }

        // ---- row max (cross-warp via smem) ----
        float rm0 = fmaxf(fmaxf(sf[0][0], sf[0][1]), fmaxf(sf[1][0], sf[1][1]));
        rm0 = fmaxf(rm0, fmaxf(fmaxf(sf[2][0], sf[2][1]), fmaxf(sf[3][0], sf[3][1])));
        float rm1 = fmaxf(fmaxf(sf[0][2], sf[0][3]), fmaxf(sf[1][2], sf[1][3]));
        rm1 = fmaxf(rm1, fmaxf(fmaxf(sf[2][2], sf[2][3]), fmaxf(sf[3][2], sf[3][3])));
        rm0 = fmaxf(rm0, __shfl_xor_sync(0xffffffffu, rm0, 1));
        rm0 = fmaxf(rm0, __shfl_xor_sync(0xffffffffu, rm0, 2));
        rm1 = fmaxf(rm1, __shfl_xor_sync(0xffffffffu, rm1, 1));
        rm1 = fmaxf(rm1, __shfl_xor_sync(0xffffffffu, rm1, 2));
        if (tq == 0) { Rm[wc * 64 + r0] = rm0; Rm[wc * 64 + r0 + 8] = rm1; }
        __syncthreads();

        // ---- softmax: p = exp(s - newM), fp16 round; owner updates M,A ----
        const float mo0 = Mbuf[par * 64 + r0], mo1 = Mbuf[par * 64 + r0 + 8];
        const float nm0 = fmaxf(mo0, fmaxf(Rm[r0], Rm[64 + r0]));
        const float nm1 = fmaxf(mo1, fmaxf(Rm[r0 + 8], Rm[64 + r0 + 8]));
        float lp0 = 0.0f, lp1 = 0.0f;
#pragma unroll
        for (int nf = 0; nf < 4; nf++) {
            __half2 h01 = __floats2half2_rn(__expf(sf[nf][0] - nm0), __expf(sf[nf][1] - nm0));
            __half2 h23 = __floats2half2_rn(__expf(sf[nf][2] - nm1), __expf(sf[nf][3] - nm1));
            float2 f01 = __half22float2(h01), f23 = __half22float2(h23);
            lp0 += f01.x + f01.y; lp1 += f23.x + f23.y;
            const int col = 32 * wc + 8 * nf + 2 * tq;
            *(u32*)(smc + OFF_P + r0 * 144 + col * 2) = *(u32*)&h01;
            *(u32*)(smc + OFF_P + (r0 + 8) * 144 + col * 2) = *(u32*)&h23;
        }
        lp0 += __shfl_xor_sync(0xffffffffu, lp0, 1);
        lp0 += __shfl_xor_sync(0xffffffffu, lp0, 2);
        lp1 += __shfl_xor_sync(0xffffffffu, lp1, 1);
        lp1 += __shfl_xor_sync(0xffffffffu, lp1, 2);
        if (tq == 0) { Psum[wc * 64 + r0] = lp0; Psum[wc * 64 + r0 + 8] = lp1; }
        if (owner) {
            Abuf[r0] = __expf(mo0 - nm0);
            Abuf[r0 + 8] = __expf(mo1 - nm1);
            Mbuf[(par ^ 1) * 64 + r0] = nm0;
            Mbuf[(par ^ 1) * 64 + r0 + 8] = nm1;
        }
        __syncthreads();

        if (owner) {
            Lbuf[r0]     = Lbuf[r0]     * Abuf[r0]     + Psum[r0]     + Psum[64 + r0];
            Lbuf[r0 + 8] = Lbuf[r0 + 8] * Abuf[r0 + 8] + Psum[r0 + 8] + Psum[64 + r0 + 8];
        }

        // ---- PV: rescale acc then O += P V^T ----
        const char* V = smc + (buf ? OFF_V1 : OFF_V0);
#pragma unroll
        for (int mj = 0; mj < 4; mj++) {
            const float a0 = Abuf[16 * mj + tg], a1 = Abuf[16 * mj + tg + 8];
#pragma unroll
            for (int nf = 0; nf < 4; nf++) {
                acc[mj][nf][0] *= a0; acc[mj][nf][1] *= a0;
                acc[mj][nf][2] *= a1; acc[mj][nf][3] *= a1;
            }
        }
#pragma unroll
        for (int kk = 0; kk < 4; kk++) {
            const int m = kk * 16 + 2 * tq;
            u32 af[4][4];
#pragma unroll
            for (int mj = 0; mj < 4; mj++) {
                const int rr = 16 * mj + tg;
                af[mj][0] = *(const u32*)(smc + OFF_P + rr * 144 + m * 2);
                af[mj][1] = *(const u32*)(smc + OFF_P + (rr + 8) * 144 + m * 2);
                af[mj][2] = *(const u32*)(smc + OFF_P + rr * 144 + (m + 8) * 2);
                af[mj][3] = *(const u32*)(smc + OFF_P + (rr + 8) * 144 + (m + 8) * 2);
            }
#pragma unroll
            for (int nf = 0; nf < 4; nf++) {
                const char* vrow = V + (32 * wid + 8 * nf + tg) * 144;
                u32 b0 = *(const u32*)(vrow + m * 2);
                u32 b1 = *(const u32*)(vrow + (m + 8) * 2);
#pragma unroll
                for (int mj = 0; mj < 4; mj++)
                    mma16(acc[mj][nf], af[mj], b0, b1);
            }
        }
        // Order ALL warps' PV reads of buffer (t&1) before the cp.async
        // overwrite issued at the top of iteration t+1. Removing this barrier
        // was the R6 correctness bug (DMA raced LDS reads of V/K).
        __syncthreads();
    }

    // ---- epilogue: O/L + residual ----
#pragma unroll
    for (int mj = 0; mj < 4; mj++) {
        const int rr = 16 * mj + tg;
        const float il0 = 1.0f / Lbuf[rr];
        const float il1 = 1.0f / Lbuf[rr + 8];
#pragma unroll
        for (int nf = 0; nf < 4; nf++) {
            const int c = 32 * wid + 8 * nf + 2 * tq;
            size_t g00 = ((size_t)b * CDIM + c) * NDIM + n0 + rr;
            size_t g01 = g00 + NDIM;
            size_t g10 = g00 + 8;
            size_t g11 = g01 + 8;
            out[g00] = acc[mj][nf][0] * il0 + x[g00];
            out[g01] = acc[mj][nf][1] * il0 + x[g01];
            out[g10] = acc[mj][nf][2] * il1 + x[g10];
            out[g11] = acc[mj][nf][3] * il1 + x[g11];
        }
    }
}

extern "C" void kernel_launch(void* const* d_in, const int* in_sizes, int n_in,
                              void* d_out, int out_size) {
    const float* x    = (const float*)d_in[0];
    const float* q_w  = (const float*)d_in[1];
    const float* q_g  = (const float*)d_in[3];
    const float* q_be = (const float*)d_in[4];
    const float* k_w  = (const float*)d_in[5];
    const float* k_g  = (const float*)d_in[7];
    const float* k_be = (const float*)d_in[8];
    const float* v_w  = (const float*)d_in[9];
    const float* v_g  = (const float*)d_in[11];
    const float* v_be = (const float*)d_in[12];
    float* out = (float*)d_out;

    proj_kernel<<<dim3(5, 32, 16), 256>>>(x, q_w, k_w, v_w);
    stats_kernel<<<320, 256>>>(q_g, q_be, k_g, k_be, v_g, v_be);
    qkt_kernel<<<dim3(32, 16), 256>>>();
    v16_kernel<<<dim3(512, 16), 256>>>();

    static int smem_set = 0;
    if (!smem_set) {
        cudaFuncSetAttribute(attn_kernel, cudaFuncAttributeMaxDynamicSharedMemorySize, SMEM_TOTAL);
        smem_set = 1;
    }
    attn_kernel<<<dim3(32, 16), 256, SMEM_TOTAL>>>(x, out);
}

// round 8
// speedup vs baseline: 4.3897x; 1.1950x over previous
#include <cuda_runtime.h>
#include <cuda_fp16.h>
#include <math.h>
#include <stdint.h>

typedef unsigned int u32;
typedef unsigned long long u64;

#define BDIM 16
#define CDIM 256
#define NDIM 2048
#define OTOT 320
#define EPSV 1e-5f

__device__ __align__(16) float g_proj[(size_t)BDIM * OTOT * NDIM];
__device__ __align__(16) u32 g_w16h[OTOT * 128];
__device__ __align__(16) u32 g_w16l[OTOT * 128];
__device__ __align__(16) __half g_q16[(size_t)BDIM * NDIM * 64];   // [b][n][hi32|lo32]
__device__ __align__(16) __half g_k16[(size_t)BDIM * NDIM * 64];   // [b][m][hi32|lo32]
__device__ __align__(16) __half g_v16[(size_t)BDIM * CDIM * NDIM]; // [b][c][m]
__device__ float g_ps1[OTOT * 4];
__device__ float g_ps2[OTOT * 4];
__device__ float g_scale[OTOT];
__device__ float g_shift[OTOT];

// ---------------- helpers ----------------
__device__ __forceinline__ u64 dup2(float v) {
    u64 r; asm("mov.b64 %0, {%1, %1};" : "=l"(r) : "f"(v)); return r;
}
__device__ __forceinline__ u64 mul2(u64 a, u64 b) {
    u64 r; asm("mul.rn.f32x2 %0, %1, %2;" : "=l"(r) : "l"(a), "l"(b)); return r;
}
__device__ __forceinline__ u32 smem_u32(const void* p) {
    u32 a; asm("{ .reg .u64 t; cvta.to.shared.u64 t, %1; cvt.u32.u64 %0, t; }" : "=r"(a) : "l"(p));
    return a;
}
__device__ __forceinline__ void mma16(float d[4], const u32 a[4], u32 b0, u32 b1) {
    asm volatile("mma.sync.aligned.m16n8k16.row.col.f32.f16.f16.f32 "
                 "{%0,%1,%2,%3}, {%4,%5,%6,%7}, {%8,%9}, {%0,%1,%2,%3};"
                 : "+f"(d[0]), "+f"(d[1]), "+f"(d[2]), "+f"(d[3])
                 : "r"(a[0]), "r"(a[1]), "r"(a[2]), "r"(a[3]), "r"(b0), "r"(b1));
}
#define CP16(dst, src) asm volatile("cp.async.cg.shared.global [%0], [%1], 16;" :: "r"(dst), "l"(src))
#define CP_COMMIT()    asm volatile("cp.async.commit_group;" ::: "memory")
#define CP_WAIT1()     asm volatile("cp.async.wait_group 1;" ::: "memory")
#define CP_WAIT0()     asm volatile("cp.async.wait_group 0;" ::: "memory")

// ================= Kernel 0: W -> fp16 hi/lo split =================
__global__ void __launch_bounds__(128) w16_kernel(
    const float* __restrict__ qw, const float* __restrict__ kw, const float* __restrict__ vw)
{
    const int o = blockIdx.x, t = threadIdx.x;
    const float* row = o < 32 ? qw + (size_t)o * CDIM
                     : o < 64 ? kw + (size_t)(o - 32) * CDIM
                              : vw + (size_t)(o - 64) * CDIM;
    float v0 = row[2 * t], v1 = row[2 * t + 1];
    __half h0 = __float2half_rn(v0), h1 = __float2half_rn(v1);
    __half l0 = __float2half_rn(v0 - __half2float(h0));
    __half l1 = __float2half_rn(v1 - __half2float(h1));
    __half2 hh = __halves2half2(h0, h1), ll = __halves2half2(l0, l1);
    g_w16h[o * 128 + t] = *(u32*)&hh;
    g_w16l[o * 128 + t] = *(u32*)&ll;
}

// ================= Kernel 1: QKV projection via fp16 mma (3-pass hi/lo) =====
// CTA: 64 o-rows x 128 n-cols; 8 warps = 4 o-subtiles x 2 n-halves.
// X staged per 16-c chunk in smem hi/lo, XOR-swizzled, double buffered.
__global__ void __launch_bounds__(256) proj16_kernel(const float* __restrict__ x)
{
    __shared__ u32 xs_h[2][1024];
    __shared__ u32 xs_l[2][1024];
    const int tid = threadIdx.x, wid = tid >> 5, lane = tid & 31;
    const int tg = lane >> 2, tq = lane & 3;
    const int wo = wid & 3, wn = wid >> 2;
    const int ob = blockIdx.x * 64 + wo * 16;
    const int gn0 = blockIdx.y * 128, b = blockIdx.z;
    const float* xb = x + (size_t)b * CDIM * NDIM + gn0;

    const int pn = tid & 127, pg = (tid >> 7) * 4;   // producer: n, cp-base

    float acc[8][4];
#pragma unroll
    for (int nf = 0; nf < 8; nf++)
#pragma unroll
        for (int j = 0; j < 4; j++) acc[nf][j] = 0.0f;

    float stg[4][2];
    auto ldg = [&](int t1) {
#pragma unroll
        for (int i = 0; i < 4; i++) {
            int c = t1 * 16 + 2 * (pg + i);
            stg[i][0] = xb[(size_t)c * NDIM + pn];
            stg[i][1] = xb[(size_t)(c + 1) * NDIM + pn];
        }
    };
    auto sts = [&](int buf) {
#pragma unroll
        for (int i = 0; i < 4; i++) {
            int cp = pg + i;
            __half h0 = __float2half_rn(stg[i][0]), h1 = __float2half_rn(stg[i][1]);
            __half l0 = __float2half_rn(stg[i][0] - __half2float(h0));
            __half l1 = __float2half_rn(stg[i][1] - __half2float(h1));
            __half2 hh = __halves2half2(h0, h1), ll = __halves2half2(l0, l1);
            int a = cp * 128 + (pn ^ (cp << 3));
            xs_h[buf][a] = *(u32*)&hh;
            xs_l[buf][a] = *(u32*)&ll;
        }
    };

    ldg(0); sts(0);
    __syncthreads();

    for (int t = 0; t < 16; t++) {
        if (t < 15) ldg(t + 1);
        const int buf = t & 1;
        // A fragments (w hi/lo) from global (L1/L2-resident)
        u32 ah[4], al[4];
        {
            size_t r = (size_t)(ob + tg) * 128 + 8 * t + tq;
            ah[0] = g_w16h[r];            ah[1] = g_w16h[r + 8 * 128];
            ah[2] = g_w16h[r + 4];        ah[3] = g_w16h[r + 8 * 128 + 4];
            al[0] = g_w16l[r];            al[1] = g_w16l[r + 8 * 128];
            al[2] = g_w16l[r + 4];        al[3] = g_w16l[r + 8 * 128 + 4];
        }
#pragma unroll
        for (int nf = 0; nf < 8; nf++) {
            const int nl = wn * 64 + 8 * nf + tg;
            u32 bh0 = xs_h[buf][tq * 128 + (nl ^ (tq << 3))];
            u32 bh1 = xs_h[buf][(tq + 4) * 128 + (nl ^ ((tq + 4) << 3))];
            u32 bl0 = xs_l[buf][tq * 128 + (nl ^ (tq << 3))];
            u32 bl1 = xs_l[buf][(tq + 4) * 128 + (nl ^ ((tq + 4) << 3))];
            mma16(acc[nf], ah, bh0, bh1);
            mma16(acc[nf], al, bh0, bh1);
            mma16(acc[nf], ah, bl0, bl1);
        }
        if (t < 15) sts((t + 1) & 1);
        __syncthreads();
    }

#pragma unroll
    for (int nf = 0; nf < 8; nf++) {
        const int n = gn0 + wn * 64 + 8 * nf + 2 * tq;
        size_t base = ((size_t)b * OTOT + ob + tg) * NDIM + n;
        *reinterpret_cast<float2*>(&g_proj[base]) = make_float2(acc[nf][0], acc[nf][1]);
        *reinterpret_cast<float2*>(&g_proj[base + (size_t)8 * NDIM]) = make_float2(acc[nf][2], acc[nf][3]);
    }
}

// ================= Kernel 2a/2b: BN stats (deterministic 2-phase) ==========
__global__ void __launch_bounds__(256) stats_part()
{
    const int ch = blockIdx.x, p = blockIdx.y, tid = threadIdx.x;
    __shared__ float r1[256], r2[256];
    float s = 0.0f, s2 = 0.0f;
    for (int bb = 0; bb < 4; bb++) {
        const float4* q = reinterpret_cast<const float4*>(
            g_proj + ((size_t)(4 * p + bb) * OTOT + ch) * NDIM);
        for (int n = tid; n < NDIM / 4; n += 256) {
            float4 v = q[n];
            s += (v.x + v.y) + (v.z + v.w);
            s2 += (v.x * v.x + v.y * v.y) + (v.z * v.z + v.w * v.w);
        }
    }
    r1[tid] = s; r2[tid] = s2; __syncthreads();
    for (int off = 128; off; off >>= 1) {
        if (tid < off) { r1[tid] += r1[tid + off]; r2[tid] += r2[tid + off]; }
        __syncthreads();
    }
    if (tid == 0) { g_ps1[ch * 4 + p] = r1[0]; g_ps2[ch * 4 + p] = r2[0]; }
}

__global__ void __launch_bounds__(OTOT) stats_fin(
    const float* __restrict__ qg, const float* __restrict__ qbe,
    const float* __restrict__ kg, const float* __restrict__ kbe,
    const float* __restrict__ vg, const float* __restrict__ vbe)
{
    const int ch = threadIdx.x;
    const float invM = 1.0f / (float)(BDIM * NDIM);
    float s = ((g_ps1[ch * 4] + g_ps1[ch * 4 + 1]) + (g_ps1[ch * 4 + 2] + g_ps1[ch * 4 + 3]));
    float s2 = ((g_ps2[ch * 4] + g_ps2[ch * 4 + 1]) + (g_ps2[ch * 4 + 2] + g_ps2[ch * 4 + 3]));
    float mean = s * invM;
    float var = s2 * invM - mean * mean;
    float gamma, beta;
    if (ch < 32)      { gamma = qg[ch];      beta = qbe[ch]; }
    else if (ch < 64) { gamma = kg[ch - 32]; beta = kbe[ch - 32]; }
    else              { gamma = vg[ch - 64]; beta = vbe[ch - 64]; }
    float sc = gamma * rsqrtf(var + EPSV);
    g_scale[ch] = sc;
    g_shift[ch] = beta - mean * sc;
}

// ================= Kernel 3: Q/K normalize + transpose -> fp16 hi/lo =======
__global__ void __launch_bounds__(256) qkt_kernel()
{
    __shared__ float s[64][65];
    const int tid = threadIdx.x;
    const int n0 = blockIdx.x * 64, b = blockIdx.y;
    for (int idx = tid; idx < 4096; idx += 256) {
        int ch = idx >> 6, nn = idx & 63;
        s[ch][nn] = g_proj[((size_t)b * OTOT + ch) * NDIM + n0 + nn] * g_scale[ch] + g_shift[ch];
    }
    __syncthreads();
    const int n = tid >> 2, d0 = (tid & 3) * 8;
    const size_t row = ((size_t)b * NDIM + n0 + n) * 64;
#pragma unroll
    for (int qk = 0; qk < 2; qk++) {
        __half* dst = (qk ? g_k16 : g_q16) + row;
        u32 wh[4], wl[4];
#pragma unroll
        for (int j = 0; j < 4; j++) {
            float v0 = s[qk * 32 + d0 + 2 * j][n];
            float v1 = s[qk * 32 + d0 + 2 * j + 1][n];
            __half h0 = __float2half_rn(v0), h1 = __float2half_rn(v1);
            __half l0 = __float2half_rn(v0 - __half2float(h0));
            __half l1 = __float2half_rn(v1 - __half2float(h1));
            wh[j] = (u32)*(unsigned short*)&h0 | ((u32)*(unsigned short*)&h1 << 16);
            wl[j] = (u32)*(unsigned short*)&l0 | ((u32)*(unsigned short*)&l1 << 16);
        }
        *reinterpret_cast<uint4*>(dst + d0)      = make_uint4(wh[0], wh[1], wh[2], wh[3]);
        *reinterpret_cast<uint4*>(dst + 32 + d0) = make_uint4(wl[0], wl[1], wl[2], wl[3]);
    }
}

// ================= Kernel 4: V normalize + leaky -> fp16 =================
__global__ void __launch_bounds__(256) v16_kernel()
{
    const int b = blockIdx.y;
    const int i4 = blockIdx.x * 256 + threadIdx.x;
    const int i = i4 * 4;
    const int c = i >> 11, n = i & 2047;
    float4 v = *reinterpret_cast<const float4*>(&g_proj[((size_t)b * OTOT + 64 + c) * NDIM + n]);
    float sc = g_scale[64 + c], sh = g_shift[64 + c];
    float a0 = v.x * sc + sh, a1 = v.y * sc + sh, a2 = v.z * sc + sh, a3 = v.w * sc + sh;
    a0 = a0 > 0.f ? a0 : 0.2f * a0; a1 = a1 > 0.f ? a1 : 0.2f * a1;
    a2 = a2 > 0.f ? a2 : 0.2f * a2; a3 = a3 > 0.f ? a3 : 0.2f * a3;
    __half2 p0 = __floats2half2_rn(a0, a1), p1 = __floats2half2_rn(a2, a3);
    uint2 w = make_uint2(*(u32*)&p0, *(u32*)&p1);
    *reinterpret_cast<uint2*>(&g_v16[((size_t)b * CDIM + c) * NDIM + n]) = w;
}

// ================= Kernel 5: fp16 mma flash attention (online softmax) =====
#define OFF_K0 0
#define OFF_K1 9216
#define OFF_V0 18432
#define OFF_V1 55296
#define OFF_P  92160
#define OFF_M  101376
#define OFF_L  101888
#define OFF_A  102144
#define OFF_RM 102400
#define OFF_PS 102912
#define SMEM_TOTAL 103424

__global__ void __launch_bounds__(256, 2) attn_kernel(
    const float* __restrict__ x, float* __restrict__ out)
{
    extern __shared__ __align__(16) char smc[];
    const u32 sb = smem_u32(smc);
    float* Mbuf = (float*)(smc + OFF_M);
    float* Lbuf = (float*)(smc + OFF_L);
    float* Abuf = (float*)(smc + OFF_A);
    float* Rm   = (float*)(smc + OFF_RM);
    float* Psum = (float*)(smc + OFF_PS);

    const int tid = threadIdx.x, wid = tid >> 5, lane = tid & 31;
    const int wm = wid & 3, wc = wid >> 2;
    const int tg = lane >> 2, tq = lane & 3;
    const int n0 = blockIdx.x * 64, b = blockIdx.y;
    const int r0 = 16 * wm + tg;
    const bool owner = (wc == 0 && tq == 0);

    if (tid < 64) { Mbuf[tid] = -INFINITY; Lbuf[tid] = 0.0f; }

    u32 qh[2][4], ql[2][4];
    {
        const __half* Qg = g_q16 + ((size_t)b * NDIM + n0) * 64;
#pragma unroll
        for (int kk = 0; kk < 2; kk++) {
            int d = kk * 16 + 2 * tq;
            qh[kk][0] = *(const u32*)(Qg + (size_t)r0 * 64 + d);
            qh[kk][1] = *(const u32*)(Qg + (size_t)(r0 + 8) * 64 + d);
            qh[kk][2] = *(const u32*)(Qg + (size_t)r0 * 64 + d + 8);
            qh[kk][3] = *(const u32*)(Qg + (size_t)(r0 + 8) * 64 + d + 8);
            ql[kk][0] = *(const u32*)(Qg + (size_t)r0 * 64 + 32 + d);
            ql[kk][1] = *(const u32*)(Qg + (size_t)(r0 + 8) * 64 + 32 + d);
            ql[kk][2] = *(const u32*)(Qg + (size_t)r0 * 64 + 32 + d + 8);
            ql[kk][3] = *(const u32*)(Qg + (size_t)(r0 + 8) * 64 + 32 + d + 8);
        }
    }

    float acc[4][4][4];
#pragma unroll
    for (int mj = 0; mj < 4; mj++)
#pragma unroll
        for (int nf = 0; nf < 4; nf++)
#pragma unroll
            for (int j = 0; j < 4; j++) acc[mj][nf][j] = 0.0f;

    auto issue_tile = [&](int m0, int buf) {
        u32 kb = sb + (buf ? OFF_K1 : OFF_K0);
        u32 vb = sb + (buf ? OFF_V1 : OFF_V0);
        const __half* Kg = g_k16 + ((size_t)b * NDIM + m0) * 64;
        const __half* Vg = g_v16 + (size_t)b * CDIM * NDIM + m0;
#pragma unroll
        for (int i = 0; i < 10; i++) {
            int id = tid + i * 256;
            if (id < 512) {
                int m = id >> 3, ch = id & 7;
                CP16(kb + m * 144 + ch * 16, Kg + (size_t)m * 64 + ch * 8);
            } else {
                int j = id - 512, c = j >> 3, ch = j & 7;
                CP16(vb + c * 144 + ch * 16, Vg + (size_t)c * NDIM + ch * 8);
            }
        }
        CP_COMMIT();
    };

    issue_tile(0, 0);

    for (int t = 0; t < 32; t++) {
        const int buf = t & 1, par = t & 1;
        if (t < 31) { issue_tile((t + 1) * 64, buf ^ 1); CP_WAIT1(); }
        else        { CP_WAIT0(); }
        __syncthreads();

        // ---- S = Q K^T, fp16 3-pass hi/lo ----
        const char* K = smc + (buf ? OFF_K1 : OFF_K0);
        float sf[4][4];
#pragma unroll
        for (int nf = 0; nf < 4; nf++) {
#pragma unroll
            for (int j = 0; j < 4; j++) sf[nf][j] = 0.0f;
            const char* krow = K + (32 * wc + 8 * nf + tg) * 144;
#pragma unroll
            for (int kk = 0; kk < 2; kk++) {
                int d = kk * 16 + 2 * tq;
                u32 bh0 = *(const u32*)(krow + d * 2);
                u32 bh1 = *(const u32*)(krow + (d + 8) * 2);
                u32 bl0 = *(const u32*)(krow + (32 + d) * 2);
                u32 bl1 = *(const u32*)(krow + (32 + d + 8) * 2);
                mma16(sf[nf], qh[kk], bh0, bh1);
                mma16(sf[nf], ql[kk], bh0, bh1);
                mma16(sf[nf], qh[kk], bl0, bl1);
            }
        }

        // ---- row max (cross-warp via smem) ----
        float rm0 = fmaxf(fmaxf(sf[0][0], sf[0][1]), fmaxf(sf[1][0], sf[1][1]));
        rm0 = fmaxf(rm0, fmaxf(fmaxf(sf[2][0], sf[2][1]), fmaxf(sf[3][0], sf[3][1])));
        float rm1 = fmaxf(fmaxf(sf[0][2], sf[0][3]), fmaxf(sf[1][2], sf[1][3]));
        rm1 = fmaxf(rm1, fmaxf(fmaxf(sf[2][2], sf[2][3]), fmaxf(sf[3][2], sf[3][3])));
        rm0 = fmaxf(rm0, __shfl_xor_sync(0xffffffffu, rm0, 1));
        rm0 = fmaxf(rm0, __shfl_xor_sync(0xffffffffu, rm0, 2));
        rm1 = fmaxf(rm1, __shfl_xor_sync(0xffffffffu, rm1, 1));
        rm1 = fmaxf(rm1, __shfl_xor_sync(0xffffffffu, rm1, 2));
        if (tq == 0) { Rm[wc * 64 + r0] = rm0; Rm[wc * 64 + r0 + 8] = rm1; }
        __syncthreads();

        // ---- softmax ----
        const float mo0 = Mbuf[par * 64 + r0], mo1 = Mbuf[par * 64 + r0 + 8];
        const float nm0 = fmaxf(mo0, fmaxf(Rm[r0], Rm[64 + r0]));
        const float nm1 = fmaxf(mo1, fmaxf(Rm[r0 + 8], Rm[64 + r0 + 8]));
        float lp0 = 0.0f, lp1 = 0.0f;
#pragma unroll
        for (int nf = 0; nf < 4; nf++) {
            __half2 h01 = __floats2half2_rn(__expf(sf[nf][0] - nm0), __expf(sf[nf][1] - nm0));
            __half2 h23 = __floats2half2_rn(__expf(sf[nf][2] - nm1), __expf(sf[nf][3] - nm1));
            float2 f01 = __half22float2(h01), f23 = __half22float2(h23);
            lp0 += f01.x + f01.y; lp1 += f23.x + f23.y;
            const int col = 32 * wc + 8 * nf + 2 * tq;
            *(u32*)(smc + OFF_P + r0 * 144 + col * 2) = *(u32*)&h01;
            *(u32*)(smc + OFF_P + (r0 + 8) * 144 + col * 2) = *(u32*)&h23;
        }
        lp0 += __shfl_xor_sync(0xffffffffu, lp0, 1);
        lp0 += __shfl_xor_sync(0xffffffffu, lp0, 2);
        lp1 += __shfl_xor_sync(0xffffffffu, lp1, 1);
        lp1 += __shfl_xor_sync(0xffffffffu, lp1, 2);
        if (tq == 0) { Psum[wc * 64 + r0] = lp0; Psum[wc * 64 + r0 + 8] = lp1; }
        if (owner) {
            Abuf[r0] = __expf(mo0 - nm0);
            Abuf[r0 + 8] = __expf(mo1 - nm1);
            Mbuf[(par ^ 1) * 64 + r0] = nm0;
            Mbuf[(par ^ 1) * 64 + r0 + 8] = nm1;
        }
        __syncthreads();

        if (owner) {
            Lbuf[r0]     = Lbuf[r0]     * Abuf[r0]     + Psum[r0]     + Psum[64 + r0];
            Lbuf[r0 + 8] = Lbuf[r0 + 8] * Abuf[r0 + 8] + Psum[r0 + 8] + Psum[64 + r0 + 8];
        }

        // ---- PV: rescale (f32x2, skip when alpha==1 warp-wide) then O += P V^T ----
        const char* V = smc + (buf ? OFF_V1 : OFF_V0);
#pragma unroll
        for (int mj = 0; mj < 4; mj++) {
            const float a0 = Abuf[16 * mj + tg], a1 = Abuf[16 * mj + tg + 8];
            if (__all_sync(0xffffffffu, (a0 == 1.0f) && (a1 == 1.0f))) continue;
            const u64 A0 = dup2(a0), A1 = dup2(a1);
#pragma unroll
            for (int nf = 0; nf < 4; nf++) {
                u64* pa = reinterpret_cast<u64*>(acc[mj][nf]);
                pa[0] = mul2(pa[0], A0);
                pa[1] = mul2(pa[1], A1);
            }
        }
#pragma unroll
        for (int kk = 0; kk < 4; kk++) {
            const int m = kk * 16 + 2 * tq;
            u32 af[4][4];
#pragma unroll
            for (int mj = 0; mj < 4; mj++) {
                const int rr = 16 * mj + tg;
                af[mj][0] = *(const u32*)(smc + OFF_P + rr * 144 + m * 2);
                af[mj][1] = *(const u32*)(smc + OFF_P + (rr + 8) * 144 + m * 2);
                af[mj][2] = *(const u32*)(smc + OFF_P + rr * 144 + (m + 8) * 2);
                af[mj][3] = *(const u32*)(smc + OFF_P + (rr + 8) * 144 + (m + 8) * 2);
            }
#pragma unroll
            for (int nf = 0; nf < 4; nf++) {
                const char* vrow = V + (32 * wid + 8 * nf + tg) * 144;
                u32 b0 = *(const u32*)(vrow + m * 2);
                u32 b1 = *(const u32*)(vrow + (m + 8) * 2);
#pragma unroll
                for (int mj = 0; mj < 4; mj++)
                    mma16(acc[mj][nf], af[mj], b0, b1);
            }
        }
        // Order all warps' PV reads of buffer (t&1) before its overwrite at t+1.
        __syncthreads();
    }

    // ---- epilogue: O/L + residual ----
#pragma unroll
    for (int mj = 0; mj < 4; mj++) {
        const int rr = 16 * mj + tg;
        const float il0 = 1.0f / Lbuf[rr];
        const float il1 = 1.0f / Lbuf[rr + 8];
#pragma unroll
        for (int nf = 0; nf < 4; nf++) {
            const int c = 32 * wid + 8 * nf + 2 * tq;
            size_t g00 = ((size_t)b * CDIM + c) * NDIM + n0 + rr;
            size_t g01 = g00 + NDIM;
            size_t g10 = g00 + 8;
            size_t g11 = g01 + 8;
            out[g00] = acc[mj][nf][0] * il0 + x[g00];
            out[g01] = acc[mj][nf][1] * il0 + x[g01];
            out[g10] = acc[mj][nf][2] * il1 + x[g10];
            out[g11] = acc[mj][nf][3] * il1 + x[g11];
        }
    }
}

extern "C" void kernel_launch(void* const* d_in, const int* in_sizes, int n_in,
                              void* d_out, int out_size) {
    const float* x    = (const float*)d_in[0];
    const float* q_w  = (const float*)d_in[1];
    const float* q_g  = (const float*)d_in[3];
    const float* q_be = (const float*)d_in[4];
    const float* k_w  = (const float*)d_in[5];
    const float* k_g  = (const float*)d_in[7];
    const float* k_be = (const float*)d_in[8];
    const float* v_w  = (const float*)d_in[9];
    const float* v_g  = (const float*)d_in[11];
    const float* v_be = (const float*)d_in[12];
    float* out = (float*)d_out;

    w16_kernel<<<OTOT, 128>>>(q_w, k_w, v_w);
    proj16_kernel<<<dim3(5, 16, 16), 256>>>(x);
    stats_part<<<dim3(OTOT, 4), 256>>>();
    stats_fin<<<1, OTOT>>>(q_g, q_be, k_g, k_be, v_g, v_be);
    qkt_kernel<<<dim3(32, 16), 256>>>();
    v16_kernel<<<dim3(512, 16), 256>>>();

    static int smem_set = 0;
    if (!smem_set) {
        cudaFuncSetAttribute(attn_kernel, cudaFuncAttributeMaxDynamicSharedMemorySize, SMEM_TOTAL);
        smem_set = 1;
    }
    attn_kernel<<<dim3(32, 16), 256, SMEM_TOTAL>>>(x, out);
}

// round 10
// speedup vs baseline: 4.4638x; 1.0169x over previous
#include <cuda_runtime.h>
#include <cuda_fp16.h>
#include <math.h>
#include <stdint.h>

typedef unsigned int u32;
typedef unsigned long long u64;

#define BDIM 16
#define CDIM 256
#define NDIM 2048
#define OTOT 320
#define EPSV 1e-5f

__device__ __align__(16) float g_proj[(size_t)BDIM * OTOT * NDIM];
__device__ __align__(16) u32 g_w16h[OTOT * 128];
__device__ __align__(16) u32 g_w16l[OTOT * 128];
__device__ __align__(16) __half g_q16[(size_t)BDIM * NDIM * 64];   // [b][n][hi32|lo32]
__device__ __align__(16) __half g_k16[(size_t)BDIM * NDIM * 64];   // [b][m][hi32|lo32]
__device__ __align__(16) __half g_v16[(size_t)BDIM * CDIM * NDIM]; // [b][c][m]
__device__ float g_ps1[OTOT * 4];
__device__ float g_ps2[OTOT * 4];

// ---------------- helpers ----------------
__device__ __forceinline__ u64 dup2(float v) {
    u64 r; asm("mov.b64 %0, {%1, %1};" : "=l"(r) : "f"(v)); return r;
}
__device__ __forceinline__ u64 mul2(u64 a, u64 b) {
    u64 r; asm("mul.rn.f32x2 %0, %1, %2;" : "=l"(r) : "l"(a), "l"(b)); return r;
}
__device__ __forceinline__ u32 smem_u32(const void* p) {
    u32 a; asm("{ .reg .u64 t; cvta.to.shared.u64 t, %1; cvt.u32.u64 %0, t; }" : "=r"(a) : "l"(p));
    return a;
}
__device__ __forceinline__ void mma16(float d[4], const u32 a[4], u32 b0, u32 b1) {
    asm volatile("mma.sync.aligned.m16n8k16.row.col.f32.f16.f16.f32 "
                 "{%0,%1,%2,%3}, {%4,%5,%6,%7}, {%8,%9}, {%0,%1,%2,%3};"
                 : "+f"(d[0]), "+f"(d[1]), "+f"(d[2]), "+f"(d[3])
                 : "r"(a[0]), "r"(a[1]), "r"(a[2]), "r"(a[3]), "r"(b0), "r"(b1));
}
#define CP16(dst, src) asm volatile("cp.async.cg.shared.global [%0], [%1], 16;" :: "r"(dst), "l"(src))
#define CP_COMMIT()    asm volatile("cp.async.commit_group;" ::: "memory")
#define CP_WAIT0()     asm volatile("cp.async.wait_group 0;" ::: "memory")

// gamma/beta lookup: g0/b0 for ch<split (index ch), g1/b1 for ch>=split (index ch-split)
__device__ __forceinline__ float2 bn_coef(int ch,
    const float* g0, const float* b0, const float* g1, const float* b1, int split)
{
    const float invM = 1.0f / (float)(BDIM * NDIM);
    float s1 = (g_ps1[ch * 4] + g_ps1[ch * 4 + 1]) + (g_ps1[ch * 4 + 2] + g_ps1[ch * 4 + 3]);
    float s2 = (g_ps2[ch * 4] + g_ps2[ch * 4 + 1]) + (g_ps2[ch * 4 + 2] + g_ps2[ch * 4 + 3]);
    float mean = s1 * invM;
    float var = s2 * invM - mean * mean;
    float gamma = ch < split ? g0[ch] : g1[ch - split];
    float beta  = ch < split ? b0[ch] : b1[ch - split];
    float sc = gamma * rsqrtf(var + EPSV);
    return make_float2(sc, beta - mean * sc);
}

// ================= Kernel 0: W -> fp16 hi/lo split =================
__global__ void __launch_bounds__(128) w16_kernel(
    const float* __restrict__ qw, const float* __restrict__ kw, const float* __restrict__ vw)
{
    const int o = blockIdx.x, t = threadIdx.x;
    const float* row = o < 32 ? qw + (size_t)o * CDIM
                     : o < 64 ? kw + (size_t)(o - 32) * CDIM
                              : vw + (size_t)(o - 64) * CDIM;
    float v0 = row[2 * t], v1 = row[2 * t + 1];
    __half h0 = __float2half_rn(v0), h1 = __float2half_rn(v1);
    __half l0 = __float2half_rn(v0 - __half2float(h0));
    __half l1 = __float2half_rn(v1 - __half2float(h1));
    __half2 hh = __halves2half2(h0, h1), ll = __halves2half2(l0, l1);
    g_w16h[o * 128 + t] = *(u32*)&hh;
    g_w16l[o * 128 + t] = *(u32*)&ll;
}

// ================= Kernel 1: QKV projection via fp16 mma (3-pass hi/lo) =====
__global__ void __launch_bounds__(256) proj16_kernel(const float* __restrict__ x)
{
    __shared__ u32 xs_h[2][2048];
    __shared__ u32 xs_l[2][2048];
    const int tid = threadIdx.x, wid = tid >> 5, lane = tid & 31;
    const int tg = lane >> 2, tq = lane & 3;
    const int wo = wid & 3, wn = wid >> 2;
    const int ob = blockIdx.x * 64 + wo * 16;
    const int gn0 = blockIdx.y * 256, b = blockIdx.z;
    const float* xb = x + (size_t)b * CDIM * NDIM + gn0;
    const int pn = tid;

    float acc[16][4];
#pragma unroll
    for (int nf = 0; nf < 16; nf++)
#pragma unroll
        for (int j = 0; j < 4; j++) acc[nf][j] = 0.0f;

    float stg[8][2];
    auto ldg = [&](int t1) {
#pragma unroll
        for (int cp = 0; cp < 8; cp++) {
            int c = t1 * 16 + 2 * cp;
            stg[cp][0] = xb[(size_t)c * NDIM + pn];
            stg[cp][1] = xb[(size_t)(c + 1) * NDIM + pn];
        }
    };
    auto sts = [&](int buf) {
#pragma unroll
        for (int cp = 0; cp < 8; cp++) {
            __half h0 = __float2half_rn(stg[cp][0]), h1 = __float2half_rn(stg[cp][1]);
            __half l0 = __float2half_rn(stg[cp][0] - __half2float(h0));
            __half l1 = __float2half_rn(stg[cp][1] - __half2float(h1));
            __half2 hh = __halves2half2(h0, h1), ll = __halves2half2(l0, l1);
            int a = cp * 256 + (pn ^ (cp << 3));
            xs_h[buf][a] = *(u32*)&hh;
            xs_l[buf][a] = *(u32*)&ll;
        }
    };

    ldg(0); sts(0);
    __syncthreads();

    for (int t = 0; t < 16; t++) {
        if (t < 15) ldg(t + 1);
        const int buf = t & 1;
        u32 ah[4], al[4];
        {
            size_t r = (size_t)(ob + tg) * 128 + 8 * t + tq;
            ah[0] = g_w16h[r];            ah[1] = g_w16h[r + 8 * 128];
            ah[2] = g_w16h[r + 4];        ah[3] = g_w16h[r + 8 * 128 + 4];
            al[0] = g_w16l[r];            al[1] = g_w16l[r + 8 * 128];
            al[2] = g_w16l[r + 4];        al[3] = g_w16l[r + 8 * 128 + 4];
        }
#pragma unroll
        for (int nf = 0; nf < 16; nf++) {
            const int nl = wn * 128 + 8 * nf + tg;
            u32 bh0 = xs_h[buf][tq * 256 + (nl ^ (tq << 3))];
            u32 bh1 = xs_h[buf][(tq + 4) * 256 + (nl ^ ((tq + 4) << 3))];
            u32 bl0 = xs_l[buf][tq * 256 + (nl ^ (tq << 3))];
            u32 bl1 = xs_l[buf][(tq + 4) * 256 + (nl ^ ((tq + 4) << 3))];
            mma16(acc[nf], ah, bh0, bh1);
            mma16(acc[nf], al, bh0, bh1);
            mma16(acc[nf], ah, bl0, bl1);
        }
        if (t < 15) sts((t + 1) & 1);
        __syncthreads();
    }

#pragma unroll
    for (int nf = 0; nf < 16; nf++) {
        const int n = gn0 + wn * 128 + 8 * nf + 2 * tq;
        size_t base = ((size_t)b * OTOT + ob + tg) * NDIM + n;
        *reinterpret_cast<float2*>(&g_proj[base]) = make_float2(acc[nf][0], acc[nf][1]);
        *reinterpret_cast<float2*>(&g_proj[base + (size_t)8 * NDIM]) = make_float2(acc[nf][2], acc[nf][3]);
    }
}

// ================= Kernel 2: BN partial sums (deterministic) ==========
__global__ void __launch_bounds__(256) stats_part()
{
    const int ch = blockIdx.x, p = blockIdx.y, tid = threadIdx.x;
    __shared__ float r1[256], r2[256];
    float s = 0.0f, s2 = 0.0f;
    for (int bb = 0; bb < 4; bb++) {
        const float4* q = reinterpret_cast<const float4*>(
            g_proj + ((size_t)(4 * p + bb) * OTOT + ch) * NDIM);
        for (int n = tid; n < NDIM / 4; n += 256) {
            float4 v = q[n];
            s += (v.x + v.y) + (v.z + v.w);
            s2 += (v.x * v.x + v.y * v.y) + (v.z * v.z + v.w * v.w);
        }
    }
    r1[tid] = s; r2[tid] = s2; __syncthreads();
    for (int off = 128; off; off >>= 1) {
        if (tid < off) { r1[tid] += r1[tid + off]; r2[tid] += r2[tid + off]; }
        __syncthreads();
    }
    if (tid == 0) { g_ps1[ch * 4 + p] = r1[0]; g_ps2[ch * 4 + p] = r2[0]; }
}

// ================= Kernel 3: Q/K normalize + transpose -> fp16 hi/lo =======
__global__ void __launch_bounds__(256) qkt_kernel(
    const float* __restrict__ qg, const float* __restrict__ qbe,
    const float* __restrict__ kg, const float* __restrict__ kbe)
{
    __shared__ float s[64][65];
    __shared__ float scl[64], shf[64];
    const int tid = threadIdx.x;
    const int n0 = blockIdx.x * 64, b = blockIdx.y;
    if (tid < 64) {
        float2 c = bn_coef(tid, qg, qbe, kg, kbe, 32);
        scl[tid] = c.x; shf[tid] = c.y;
    }
    __syncthreads();
    for (int idx = tid; idx < 4096; idx += 256) {
        int ch = idx >> 6, nn = idx & 63;
        s[ch][nn] = g_proj[((size_t)b * OTOT + ch) * NDIM + n0 + nn] * scl[ch] + shf[ch];
    }
    __syncthreads();
    const int n = tid >> 2, d0 = (tid & 3) * 8;
    const size_t row = ((size_t)b * NDIM + n0 + n) * 64;
#pragma unroll
    for (int qk = 0; qk < 2; qk++) {
        __half* dst = (qk ? g_k16 : g_q16) + row;
        u32 wh[4], wl[4];
#pragma unroll
        for (int j = 0; j < 4; j++) {
            float v0 = s[qk * 32 + d0 + 2 * j][n];
            float v1 = s[qk * 32 + d0 + 2 * j + 1][n];
            __half h0 = __float2half_rn(v0), h1 = __float2half_rn(v1);
            __half l0 = __float2half_rn(v0 - __half2float(h0));
            __half l1 = __float2half_rn(v1 - __half2float(h1));
            wh[j] = (u32)*(unsigned short*)&h0 | ((u32)*(unsigned short*)&h1 << 16);
            wl[j] = (u32)*(unsigned short*)&l0 | ((u32)*(unsigned short*)&l1 << 16);
        }
        *reinterpret_cast<uint4*>(dst + d0)      = make_uint4(wh[0], wh[1], wh[2], wh[3]);
        *reinterpret_cast<uint4*>(dst + 32 + d0) = make_uint4(wl[0], wl[1], wl[2], wl[3]);
    }
}

// ================= Kernel 4: V normalize + leaky -> fp16 =================
__global__ void __launch_bounds__(256) v16_kernel(
    const float* __restrict__ vg, const float* __restrict__ vbe)
{
    __shared__ float s_sc, s_sh;
    const int b = blockIdx.y, tid = threadIdx.x;
    const int c = blockIdx.x >> 1;
    if (tid == 0) {
        // ch = 64+c >= split=64  ->  gamma = vg[c], beta = vbe[c]   (R9 bug: split was 400)
        float2 co = bn_coef(64 + c, vg, vbe, vg, vbe, 64);
        s_sc = co.x; s_sh = co.y;
    }
    __syncthreads();
    const int i4 = blockIdx.x * 256 + tid;
    const int n = (i4 * 4) & 2047;
    float4 v = *reinterpret_cast<const float4*>(&g_proj[((size_t)b * OTOT + 64 + c) * NDIM + n]);
    float sc = s_sc, sh = s_sh;
    float a0 = v.x * sc + sh, a1 = v.y * sc + sh, a2 = v.z * sc + sh, a3 = v.w * sc + sh;
    a0 = a0 > 0.f ? a0 : 0.2f * a0; a1 = a1 > 0.f ? a1 : 0.2f * a1;
    a2 = a2 > 0.f ? a2 : 0.2f * a2; a3 = a3 > 0.f ? a3 : 0.2f * a3;
    __half2 p0 = __floats2half2_rn(a0, a1), p1 = __floats2half2_rn(a2, a3);
    uint2 w = make_uint2(*(u32*)&p0, *(u32*)&p1);
    *reinterpret_cast<uint2*>(&g_v16[((size_t)b * CDIM + c) * NDIM + n]) = w;
}

// ================= Kernel 5: fp16 mma flash attention (online softmax) =====
#define OFF_K0 0
#define OFF_K1 9216
#define OFF_V0 18432
#define OFF_V1 55296
#define OFF_P  92160
#define OFF_M  101376
#define OFF_L  101888
#define OFF_A  102144
#define OFF_RM 102400
#define OFF_PS 102912
#define SMEM_TOTAL 103424

__global__ void __launch_bounds__(256, 2) attn_kernel(
    const float* __restrict__ x, float* __restrict__ out)
{
    extern __shared__ __align__(16) char smc[];
    const u32 sb = smem_u32(smc);
    float* Mbuf = (float*)(smc + OFF_M);
    float* Lbuf = (float*)(smc + OFF_L);
    float* Abuf = (float*)(smc + OFF_A);
    float* Rm   = (float*)(smc + OFF_RM);
    float* Psum = (float*)(smc + OFF_PS);

    const int tid = threadIdx.x, wid = tid >> 5, lane = tid & 31;
    const int wm = wid & 3, wc = wid >> 2;
    const int tg = lane >> 2, tq = lane & 3;
    const int n0 = blockIdx.x * 64, b = blockIdx.y;
    const int r0 = 16 * wm + tg;
    const bool owner = (wc == 0 && tq == 0);

    if (tid < 64) { Mbuf[tid] = -INFINITY; Lbuf[tid] = 0.0f; }

    u32 qh[2][4], ql[2][4];
    {
        const __half* Qg = g_q16 + ((size_t)b * NDIM + n0) * 64;
#pragma unroll
        for (int kk = 0; kk < 2; kk++) {
            int d = kk * 16 + 2 * tq;
            qh[kk][0] = *(const u32*)(Qg + (size_t)r0 * 64 + d);
            qh[kk][1] = *(const u32*)(Qg + (size_t)(r0 + 8) * 64 + d);
            qh[kk][2] = *(const u32*)(Qg + (size_t)r0 * 64 + d + 8);
            qh[kk][3] = *(const u32*)(Qg + (size_t)(r0 + 8) * 64 + d + 8);
            ql[kk][0] = *(const u32*)(Qg + (size_t)r0 * 64 + 32 + d);
            ql[kk][1] = *(const u32*)(Qg + (size_t)(r0 + 8) * 64 + 32 + d);
            ql[kk][2] = *(const u32*)(Qg + (size_t)r0 * 64 + 32 + d + 8);
            ql[kk][3] = *(const u32*)(Qg + (size_t)(r0 + 8) * 64 + 32 + d + 8);
        }
    }

    float acc[4][4][4];
#pragma unroll
    for (int mj = 0; mj < 4; mj++)
#pragma unroll
        for (int nf = 0; nf < 4; nf++)
#pragma unroll
            for (int j = 0; j < 4; j++) acc[mj][nf][j] = 0.0f;

    auto issue_tile = [&](int m0, int bf) {
        u32 kb = sb + (bf ? OFF_K1 : OFF_K0);
        u32 vb = sb + (bf ? OFF_V1 : OFF_V0);
        const __half* Kg = g_k16 + ((size_t)b * NDIM + m0) * 64;
        const __half* Vg = g_v16 + (size_t)b * CDIM * NDIM + m0;
#pragma unroll
        for (int i = 0; i < 10; i++) {
            int id = tid + i * 256;
            if (id < 512) {
                int m = id >> 3, ch = id & 7;
                CP16(kb + m * 144 + ch * 16, Kg + (size_t)m * 64 + ch * 8);
            } else {
                int j = id - 512, c = j >> 3, ch = j & 7;
                CP16(vb + c * 144 + ch * 16, Vg + (size_t)c * NDIM + ch * 8);
            }
        }
        CP_COMMIT();
    };

    issue_tile(0, 0);

    for (int t = 0; t < 32; t++) {
        const int buf = t & 1, par = t & 1;
        CP_WAIT0();
        __syncthreads();   // bar1: K/V(t) visible; all warps done with tile t-1
        if (t < 31) issue_tile((t + 1) * 64, buf ^ 1);

        // ---- S = Q K^T, fp16 3-pass hi/lo ----
        const char* K = smc + (buf ? OFF_K1 : OFF_K0);
        float sf[4][4];
#pragma unroll
        for (int nf = 0; nf < 4; nf++) {
#pragma unroll
            for (int j = 0; j < 4; j++) sf[nf][j] = 0.0f;
            const char* krow = K + (32 * wc + 8 * nf + tg) * 144;
#pragma unroll
            for (int kk = 0; kk < 2; kk++) {
                int d = kk * 16 + 2 * tq;
                u32 bh0 = *(const u32*)(krow + d * 2);
                u32 bh1 = *(const u32*)(krow + (d + 8) * 2);
                u32 bl0 = *(const u32*)(krow + (32 + d) * 2);
                u32 bl1 = *(const u32*)(krow + (32 + d + 8) * 2);
                mma16(sf[nf], qh[kk], bh0, bh1);
                mma16(sf[nf], ql[kk], bh0, bh1);
                mma16(sf[nf], qh[kk], bl0, bl1);
            }
        }

        // ---- row max; exchange within warp pair via named barrier ----
        float rm0 = fmaxf(fmaxf(sf[0][0], sf[0][1]), fmaxf(sf[1][0], sf[1][1]));
        rm0 = fmaxf(rm0, fmaxf(fmaxf(sf[2][0], sf[2][1]), fmaxf(sf[3][0], sf[3][1])));
        float rm1 = fmaxf(fmaxf(sf[0][2], sf[0][3]), fmaxf(sf[1][2], sf[1][3]));
        rm1 = fmaxf(rm1, fmaxf(fmaxf(sf[2][2], sf[2][3]), fmaxf(sf[3][2], sf[3][3])));
        rm0 = fmaxf(rm0, __shfl_xor_sync(0xffffffffu, rm0, 1));
        rm0 = fmaxf(rm0, __shfl_xor_sync(0xffffffffu, rm0, 2));
        rm1 = fmaxf(rm1, __shfl_xor_sync(0xffffffffu, rm1, 1));
        rm1 = fmaxf(rm1, __shfl_xor_sync(0xffffffffu, rm1, 2));
        if (tq == 0) { Rm[wc * 64 + r0] = rm0; Rm[wc * 64 + r0 + 8] = rm1; }
        asm volatile("bar.sync %0, 64;" :: "r"(wm + 1) : "memory");

        // ---- softmax ----
        const float mo0 = Mbuf[par * 64 + r0], mo1 = Mbuf[par * 64 + r0 + 8];
        const float nm0 = fmaxf(mo0, fmaxf(Rm[r0], Rm[64 + r0]));
        const float nm1 = fmaxf(mo1, fmaxf(Rm[r0 + 8], Rm[64 + r0 + 8]));
        float lp0 = 0.0f, lp1 = 0.0f;
#pragma unroll
        for (int nf = 0; nf < 4; nf++) {
            __half2 h01 = __floats2half2_rn(__expf(sf[nf][0] - nm0), __expf(sf[nf][1] - nm0));
            __half2 h23 = __floats2half2_rn(__expf(sf[nf][2] - nm1), __expf(sf[nf][3] - nm1));
            float2 f01 = __half22float2(h01), f23 = __half22float2(h23);
            lp0 += f01.x + f01.y; lp1 += f23.x + f23.y;
            const int col = 32 * wc + 8 * nf + 2 * tq;
            *(u32*)(smc + OFF_P + r0 * 144 + col * 2) = *(u32*)&h01;
            *(u32*)(smc + OFF_P + (r0 + 8) * 144 + col * 2) = *(u32*)&h23;
        }
        lp0 += __shfl_xor_sync(0xffffffffu, lp0, 1);
        lp0 += __shfl_xor_sync(0xffffffffu, lp0, 2);
        lp1 += __shfl_xor_sync(0xffffffffu, lp1, 1);
        lp1 += __shfl_xor_sync(0xffffffffu, lp1, 2);
        if (tq == 0) { Psum[wc * 64 + r0] = lp0; Psum[wc * 64 + r0 + 8] = lp1; }
        if (owner) {
            Abuf[r0] = __expf(mo0 - nm0);
            Abuf[r0 + 8] = __expf(mo1 - nm1);
            Mbuf[(par ^ 1) * 64 + r0] = nm0;
            Mbuf[(par ^ 1) * 64 + r0 + 8] = nm1;
        }
        __syncthreads();   // bar3: P + A visible to all warps

        if (owner) {
            Lbuf[r0]     = Lbuf[r0]     * Abuf[r0]     + Psum[r0]     + Psum[64 + r0];
            Lbuf[r0 + 8] = Lbuf[r0 + 8] * Abuf[r0 + 8] + Psum[r0 + 8] + Psum[64 + r0 + 8];
        }

        // ---- PV ----
        const char* V = smc + (buf ? OFF_V1 : OFF_V0);
#pragma unroll
        for (int mj = 0; mj < 4; mj++) {
            const float a0 = Abuf[16 * mj + tg], a1 = Abuf[16 * mj + tg + 8];
            if (__all_sync(0xffffffffu, (a0 == 1.0f) && (a1 == 1.0f))) continue;
            const u64 A0 = dup2(a0), A1 = dup2(a1);
#pragma unroll
            for (int nf = 0; nf < 4; nf++) {
                u64* pa = reinterpret_cast<u64*>(acc[mj][nf]);
                pa[0] = mul2(pa[0], A0);
                pa[1] = mul2(pa[1], A1);
            }
        }
#pragma unroll
        for (int kk = 0; kk < 4; kk++) {
            const int m = kk * 16 + 2 * tq;
            u32 af[4][4];
#pragma unroll
            for (int mj = 0; mj < 4; mj++) {
                const int rr = 16 * mj + tg;
                af[mj][0] = *(const u32*)(smc + OFF_P + rr * 144 + m * 2);
                af[mj][1] = *(const u32*)(smc + OFF_P + (rr + 8) * 144 + m * 2);
                af[mj][2] = *(const u32*)(smc + OFF_P + rr * 144 + (m + 8) * 2);
                af[mj][3] = *(const u32*)(smc + OFF_P + (rr + 8) * 144 + (m + 8) * 2);
            }
#pragma unroll
            for (int nf = 0; nf < 4; nf++) {
                const char* vrow = V + (32 * wid + 8 * nf + tg) * 144;
                u32 b0 = *(const u32*)(vrow + m * 2);
                u32 b1 = *(const u32*)(vrow + (m + 8) * 2);
#pragma unroll
                for (int mj = 0; mj < 4; mj++)
                    mma16(acc[mj][nf], af[mj], b0, b1);
            }
        }
        // no end barrier: bar1 of iteration t+1 provides the ordering
    }
    __syncthreads();

    // ---- epilogue: O/L + residual ----
#pragma unroll
    for (int mj = 0; mj < 4; mj++) {
        const int rr = 16 * mj + tg;
        const float il0 = 1.0f / Lbuf[rr];
        const float il1 = 1.0f / Lbuf[rr + 8];
#pragma unroll
        for (int nf = 0; nf < 4; nf++) {
            const int c = 32 * wid + 8 * nf + 2 * tq;
            size_t g00 = ((size_t)b * CDIM + c) * NDIM + n0 + rr;
            size_t g01 = g00 + NDIM;
            size_t g10 = g00 + 8;
            size_t g11 = g01 + 8;
            out[g00] = acc[mj][nf][0] * il0 + x[g00];
            out[g01] = acc[mj][nf][1] * il0 + x[g01];
            out[g10] = acc[mj][nf][2] * il1 + x[g10];
            out[g11] = acc[mj][nf][3] * il1 + x[g11];
        }
    }
}

extern "C" void kernel_launch(void* const* d_in, const int* in_sizes, int n_in,
                              void* d_out, int out_size) {
    const float* x    = (const float*)d_in[0];
    const float* q_w  = (const float*)d_in[1];
    const float* q_g  = (const float*)d_in[3];
    const float* q_be = (const float*)d_in[4];
    const float* k_w  = (const float*)d_in[5];
    const float* k_g  = (const float*)d_in[7];
    const float* k_be = (const float*)d_in[8];
    const float* v_w  = (const float*)d_in[9];
    const float* v_g  = (const float*)d_in[11];
    const float* v_be = (const float*)d_in[12];
    float* out = (float*)d_out;

    w16_kernel<<<OTOT, 128>>>(q_w, k_w, v_w);
    proj16_kernel<<<dim3(5, 8, 16), 256>>>(x);
    stats_part<<<dim3(OTOT, 4), 256>>>();
    qkt_kernel<<<dim3(32, 16), 256>>>(q_g, q_be, k_g, k_be);
    v16_kernel<<<dim3(512, 16), 256>>>(v_g, v_be);

    static int smem_set = 0;
    if (!smem_set) {
        cudaFuncSetAttribute(attn_kernel, cudaFuncAttributeMaxDynamicSharedMemorySize, SMEM_TOTAL);
        smem_set = 1;
    }
    attn_kernel<<<dim3(32, 16), 256, SMEM_TOTAL>>>(x, out);
}

// round 11
// speedup vs baseline: 4.6813x; 1.0487x over previous
#include <cuda_runtime.h>
#include <cuda_fp16.h>
#include <math.h>
#include <stdint.h>

typedef unsigned int u32;
typedef unsigned long long u64;

#define BDIM 16
#define CDIM 256
#define NDIM 2048
#define OTOT 320
#define EPSV 1e-5f

__device__ __align__(16) float g_proj[(size_t)BDIM * OTOT * NDIM];
__device__ __align__(16) u32 g_w16h[OTOT * 128];
__device__ __align__(16) u32 g_w16l[OTOT * 128];
__device__ __align__(16) __half g_q16[(size_t)BDIM * NDIM * 64];   // [b][n][hi32|lo32]
__device__ __align__(16) __half g_k16[(size_t)BDIM * NDIM * 64];   // [b][m][hi32|lo32]
__device__ __align__(16) __half g_v16[(size_t)BDIM * CDIM * NDIM]; // [b][c][m]
__device__ float g_ps1[OTOT * 128];
__device__ float g_ps2[OTOT * 128];
__device__ float g_scale[OTOT];
__device__ float g_shift[OTOT];

// ---------------- helpers ----------------
__device__ __forceinline__ u64 dup2(float v) {
    u64 r; asm("mov.b64 %0, {%1, %1};" : "=l"(r) : "f"(v)); return r;
}
__device__ __forceinline__ u64 mul2(u64 a, u64 b) {
    u64 r; asm("mul.rn.f32x2 %0, %1, %2;" : "=l"(r) : "l"(a), "l"(b)); return r;
}
__device__ __forceinline__ u32 smem_u32(const void* p) {
    u32 a; asm("{ .reg .u64 t; cvta.to.shared.u64 t, %1; cvt.u32.u64 %0, t; }" : "=r"(a) : "l"(p));
    return a;
}
__device__ __forceinline__ void mma16(float d[4], const u32 a[4], u32 b0, u32 b1) {
    asm volatile("mma.sync.aligned.m16n8k16.row.col.f32.f16.f16.f32 "
                 "{%0,%1,%2,%3}, {%4,%5,%6,%7}, {%8,%9}, {%0,%1,%2,%3};"
                 : "+f"(d[0]), "+f"(d[1]), "+f"(d[2]), "+f"(d[3])
                 : "r"(a[0]), "r"(a[1]), "r"(a[2]), "r"(a[3]), "r"(b0), "r"(b1));
}
#define CP16(dst, src) asm volatile("cp.async.cg.shared.global [%0], [%1], 16;" :: "r"(dst), "l"(src))
#define CP_COMMIT()    asm volatile("cp.async.commit_group;" ::: "memory")
#define CP_WAIT0()     asm volatile("cp.async.wait_group 0;" ::: "memory")

// ================= Kernel 0: W -> fp16 hi/lo split =================
__global__ void __launch_bounds__(128) w16_kernel(
    const float* __restrict__ qw, const float* __restrict__ kw, const float* __restrict__ vw)
{
    const int o = blockIdx.x, t = threadIdx.x;
    const float* row = o < 32 ? qw + (size_t)o * CDIM
                     : o < 64 ? kw + (size_t)(o - 32) * CDIM
                              : vw + (size_t)(o - 64) * CDIM;
    float v0 = row[2 * t], v1 = row[2 * t + 1];
    __half h0 = __float2half_rn(v0), h1 = __float2half_rn(v1);
    __half l0 = __float2half_rn(v0 - __half2float(h0));
    __half l1 = __float2half_rn(v1 - __half2float(h1));
    __half2 hh = __halves2half2(h0, h1), ll = __halves2half2(l0, l1);
    g_w16h[o * 128 + t] = *(u32*)&hh;
    g_w16l[o * 128 + t] = *(u32*)&ll;
}

// ================= Kernel 1: QKV projection (fp16 mma, 3-pass) + fused stats =====
__global__ void __launch_bounds__(256) proj16_kernel(const float* __restrict__ x)
{
    __shared__ u32 xs_h[2][2048];
    __shared__ u32 xs_l[2][2048];
    __shared__ float2 sm_sp[128];   // [warp][16] channel partials
    const int tid = threadIdx.x, wid = tid >> 5, lane = tid & 31;
    const int tg = lane >> 2, tq = lane & 3;
    const int wo = wid & 3, wn = wid >> 2;
    const int ob = blockIdx.x * 64 + wo * 16;
    const int gn0 = blockIdx.y * 256, b = blockIdx.z;
    const float* xb = x + (size_t)b * CDIM * NDIM + gn0;
    const int pn = tid;

    float acc[16][4];
#pragma unroll
    for (int nf = 0; nf < 16; nf++)
#pragma unroll
        for (int j = 0; j < 4; j++) acc[nf][j] = 0.0f;

    float stg[8][2];
    auto ldg = [&](int t1) {
#pragma unroll
        for (int cp = 0; cp < 8; cp++) {
            int c = t1 * 16 + 2 * cp;
            stg[cp][0] = xb[(size_t)c * NDIM + pn];
            stg[cp][1] = xb[(size_t)(c + 1) * NDIM + pn];
        }
    };
    auto sts = [&](int buf) {
#pragma unroll
        for (int cp = 0; cp < 8; cp++) {
            __half h0 = __float2half_rn(stg[cp][0]), h1 = __float2half_rn(stg[cp][1]);
            __half l0 = __float2half_rn(stg[cp][0] - __half2float(h0));
            __half l1 = __float2half_rn(stg[cp][1] - __half2float(h1));
            __half2 hh = __halves2half2(h0, h1), ll = __halves2half2(l0, l1);
            int a = cp * 256 + (pn ^ (cp << 3));
            xs_h[buf][a] = *(u32*)&hh;
            xs_l[buf][a] = *(u32*)&ll;
        }
    };

    ldg(0); sts(0);
    __syncthreads();

    for (int t = 0; t < 16; t++) {
        if (t < 15) ldg(t + 1);
        const int buf = t & 1;
        u32 ah[4], al[4];
        {
            size_t r = (size_t)(ob + tg) * 128 + 8 * t + tq;
            ah[0] = g_w16h[r];            ah[1] = g_w16h[r + 8 * 128];
            ah[2] = g_w16h[r + 4];        ah[3] = g_w16h[r + 8 * 128 + 4];
            al[0] = g_w16l[r];            al[1] = g_w16l[r + 8 * 128];
            al[2] = g_w16l[r + 4];        al[3] = g_w16l[r + 8 * 128 + 4];
        }
#pragma unroll
        for (int nf = 0; nf < 16; nf++) {
            const int nl = wn * 128 + 8 * nf + tg;
            u32 bh0 = xs_h[buf][tq * 256 + (nl ^ (tq << 3))];
            u32 bh1 = xs_h[buf][(tq + 4) * 256 + (nl ^ ((tq + 4) << 3))];
            u32 bl0 = xs_l[buf][tq * 256 + (nl ^ (tq << 3))];
            u32 bl1 = xs_l[buf][(tq + 4) * 256 + (nl ^ ((tq + 4) << 3))];
            mma16(acc[nf], ah, bh0, bh1);
            mma16(acc[nf], al, bh0, bh1);
            mma16(acc[nf], ah, bl0, bl1);
        }
        if (t < 15) sts((t + 1) & 1);
        __syncthreads();
    }

    // ---- store proj ----
#pragma unroll
    for (int nf = 0; nf < 16; nf++) {
        const int n = gn0 + wn * 128 + 8 * nf + 2 * tq;
        size_t base = ((size_t)b * OTOT + ob + tg) * NDIM + n;
        *reinterpret_cast<float2*>(&g_proj[base]) = make_float2(acc[nf][0], acc[nf][1]);
        *reinterpret_cast<float2*>(&g_proj[base + (size_t)8 * NDIM]) = make_float2(acc[nf][2], acc[nf][3]);
    }

    // ---- fused per-channel stats partials (sum, sumsq) ----
    float s0 = 0.f, q0 = 0.f, s1 = 0.f, q1 = 0.f;
#pragma unroll
    for (int nf = 0; nf < 16; nf++) {
        s0 += acc[nf][0] + acc[nf][1];
        q0 += acc[nf][0] * acc[nf][0] + acc[nf][1] * acc[nf][1];
        s1 += acc[nf][2] + acc[nf][3];
        q1 += acc[nf][2] * acc[nf][2] + acc[nf][3] * acc[nf][3];
    }
#pragma unroll
    for (int off = 1; off < 4; off <<= 1) {
        s0 += __shfl_xor_sync(0xffffffffu, s0, off);
        q0 += __shfl_xor_sync(0xffffffffu, q0, off);
        s1 += __shfl_xor_sync(0xffffffffu, s1, off);
        q1 += __shfl_xor_sync(0xffffffffu, q1, off);
    }
    if (tq == 0) {
        sm_sp[wid * 16 + tg]     = make_float2(s0, q0);
        sm_sp[wid * 16 + 8 + tg] = make_float2(s1, q1);
    }
    __syncthreads();
    if (tid < 64) {
        int wo2 = tid >> 4, c = tid & 15;
        float2 a = sm_sp[wo2 * 16 + c];
        float2 e = sm_sp[(wo2 + 4) * 16 + c];
        int ch = blockIdx.x * 64 + wo2 * 16 + c;
        g_ps1[ch * 128 + b * 8 + blockIdx.y] = a.x + e.x;
        g_ps2[ch * 128 + b * 8 + blockIdx.y] = a.y + e.y;
    }
}

// ================= Kernel 2: finalize stats -> scale/shift =================
__global__ void __launch_bounds__(128) stats_fin(
    const float* __restrict__ qg, const float* __restrict__ qbe,
    const float* __restrict__ kg, const float* __restrict__ kbe,
    const float* __restrict__ vg, const float* __restrict__ vbe)
{
    const int ch = blockIdx.x, tid = threadIdx.x;
    __shared__ float r1[128], r2[128];
    r1[tid] = g_ps1[ch * 128 + tid];
    r2[tid] = g_ps2[ch * 128 + tid];
    __syncthreads();
    for (int off = 64; off; off >>= 1) {
        if (tid < off) { r1[tid] += r1[tid + off]; r2[tid] += r2[tid + off]; }
        __syncthreads();
    }
    if (tid == 0) {
        const float invM = 1.0f / (float)(BDIM * NDIM);
        float mean = r1[0] * invM;
        float var = r2[0] * invM - mean * mean;
        float gamma, beta;
        if (ch < 32)      { gamma = qg[ch];      beta = qbe[ch]; }
        else if (ch < 64) { gamma = kg[ch - 32]; beta = kbe[ch - 32]; }
        else              { gamma = vg[ch - 64]; beta = vbe[ch - 64]; }
        float sc = gamma * rsqrtf(var + EPSV);
        g_scale[ch] = sc;
        g_shift[ch] = beta - mean * sc;
    }
}

// ================= Kernel 3: Q/K normalize + transpose -> fp16 hi/lo =======
__global__ void __launch_bounds__(256) qkt_kernel()
{
    __shared__ float s[64][65];
    __shared__ float scl[64], shf[64];
    const int tid = threadIdx.x;
    const int n0 = blockIdx.x * 64, b = blockIdx.y;
    if (tid < 64) { scl[tid] = g_scale[tid]; shf[tid] = g_shift[tid]; }
    __syncthreads();
    for (int idx = tid; idx < 4096; idx += 256) {
        int ch = idx >> 6, nn = idx & 63;
        s[ch][nn] = g_proj[((size_t)b * OTOT + ch) * NDIM + n0 + nn] * scl[ch] + shf[ch];
    }
    __syncthreads();
    const int n = tid >> 2, d0 = (tid & 3) * 8;
    const size_t row = ((size_t)b * NDIM + n0 + n) * 64;
#pragma unroll
    for (int qk = 0; qk < 2; qk++) {
        __half* dst = (qk ? g_k16 : g_q16) + row;
        u32 wh[4], wl[4];
#pragma unroll
        for (int j = 0; j < 4; j++) {
            float v0 = s[qk * 32 + d0 + 2 * j][n];
            float v1 = s[qk * 32 + d0 + 2 * j + 1][n];
            __half h0 = __float2half_rn(v0), h1 = __float2half_rn(v1);
            __half l0 = __float2half_rn(v0 - __half2float(h0));
            __half l1 = __float2half_rn(v1 - __half2float(h1));
            wh[j] = (u32)*(unsigned short*)&h0 | ((u32)*(unsigned short*)&h1 << 16);
            wl[j] = (u32)*(unsigned short*)&l0 | ((u32)*(unsigned short*)&l1 << 16);
        }
        *reinterpret_cast<uint4*>(dst + d0)      = make_uint4(wh[0], wh[1], wh[2], wh[3]);
        *reinterpret_cast<uint4*>(dst + 32 + d0) = make_uint4(wl[0], wl[1], wl[2], wl[3]);
    }
}

// ================= Kernel 4: V normalize + leaky -> fp16 =================
__global__ void __launch_bounds__(256) v16_kernel()
{
    const int b = blockIdx.y, tid = threadIdx.x;
    const int c = blockIdx.x >> 1;
    const float sc = g_scale[64 + c], sh = g_shift[64 + c];
    const int i4 = blockIdx.x * 256 + tid;
    const int n = (i4 * 4) & 2047;
    float4 v = *reinterpret_cast<const float4*>(&g_proj[((size_t)b * OTOT + 64 + c) * NDIM + n]);
    float a0 = v.x * sc + sh, a1 = v.y * sc + sh, a2 = v.z * sc + sh, a3 = v.w * sc + sh;
    a0 = a0 > 0.f ? a0 : 0.2f * a0; a1 = a1 > 0.f ? a1 : 0.2f * a1;
    a2 = a2 > 0.f ? a2 : 0.2f * a2; a3 = a3 > 0.f ? a3 : 0.2f * a3;
    __half2 p0 = __floats2half2_rn(a0, a1), p1 = __floats2half2_rn(a2, a3);
    uint2 w = make_uint2(*(u32*)&p0, *(u32*)&p1);
    *reinterpret_cast<uint2*>(&g_v16[((size_t)b * CDIM + c) * NDIM + n]) = w;
}

// ================= Kernel 5: fp16 mma flash attention (2-pass S) =====
#define OFF_K0 0
#define OFF_K1 5120
#define OFF_V0 10240
#define OFF_V1 47104
#define OFF_P  83968
#define OFF_M  93184
#define OFF_L  93696
#define OFF_A  93952
#define OFF_RM 94208
#define OFF_PS 94720
#define SMEM_TOTAL 95232

__global__ void __launch_bounds__(256, 2) attn_kernel(
    const float* __restrict__ x, float* __restrict__ out)
{
    extern __shared__ __align__(16) char smc[];
    const u32 sb = smem_u32(smc);
    float* Mbuf = (float*)(smc + OFF_M);
    float* Lbuf = (float*)(smc + OFF_L);
    float* Abuf = (float*)(smc + OFF_A);
    float* Rm   = (float*)(smc + OFF_RM);
    float* Psum = (float*)(smc + OFF_PS);

    const int tid = threadIdx.x, wid = tid >> 5, lane = tid & 31;
    const int wm = wid & 3, wc = wid >> 2;
    const int tg = lane >> 2, tq = lane & 3;
    const int n0 = blockIdx.x * 64, b = blockIdx.y;
    const int r0 = 16 * wm + tg;
    const bool owner = (wc == 0 && tq == 0);

    if (tid < 64) { Mbuf[tid] = -INFINITY; Lbuf[tid] = 0.0f; }

    u32 qh[2][4], ql[2][4];
    {
        const __half* Qg = g_q16 + ((size_t)b * NDIM + n0) * 64;
#pragma unroll
        for (int kk = 0; kk < 2; kk++) {
            int d = kk * 16 + 2 * tq;
            qh[kk][0] = *(const u32*)(Qg + (size_t)r0 * 64 + d);
            qh[kk][1] = *(const u32*)(Qg + (size_t)(r0 + 8) * 64 + d);
            qh[kk][2] = *(const u32*)(Qg + (size_t)r0 * 64 + d + 8);
            qh[kk][3] = *(const u32*)(Qg + (size_t)(r0 + 8) * 64 + d + 8);
            ql[kk][0] = *(const u32*)(Qg + (size_t)r0 * 64 + 32 + d);
            ql[kk][1] = *(const u32*)(Qg + (size_t)(r0 + 8) * 64 + 32 + d);
            ql[kk][2] = *(const u32*)(Qg + (size_t)r0 * 64 + 32 + d + 8);
            ql[kk][3] = *(const u32*)(Qg + (size_t)(r0 + 8) * 64 + 32 + d + 8);
        }
    }

    float acc[4][4][4];
#pragma unroll
    for (int mj = 0; mj < 4; mj++)
#pragma unroll
        for (int nf = 0; nf < 4; nf++)
#pragma unroll
            for (int j = 0; j < 4; j++) acc[mj][nf][j] = 0.0f;

    // K tile: 64 rows x 80B (hi only). V tile: 256 rows x 144B.
    auto issue_tile = [&](int m0, int bf) {
        u32 kb = sb + (bf ? OFF_K1 : OFF_K0);
        u32 vb = sb + (bf ? OFF_V1 : OFF_V0);
        const __half* Kg = g_k16 + ((size_t)b * NDIM + m0) * 64;
        const __half* Vg = g_v16 + (size_t)b * CDIM * NDIM + m0;
#pragma unroll
        for (int i = 0; i < 9; i++) {
            int id = tid + i * 256;
            if (id < 256) {
                int m = id >> 2, ch = id & 3;
                CP16(kb + m * 80 + ch * 16, Kg + (size_t)m * 64 + ch * 8);
            } else {
                int j = id - 256, c = j >> 3, ch = j & 7;
                CP16(vb + c * 144 + ch * 16, Vg + (size_t)c * NDIM + ch * 8);
            }
        }
        CP_COMMIT();
    };

    issue_tile(0, 0);

    for (int t = 0; t < 32; t++) {
        const int buf = t & 1, par = t & 1;
        CP_WAIT0();
        __syncthreads();   // bar1: K/V(t) visible; all warps done with tile t-1
        if (t < 31) issue_tile((t + 1) * 64, buf ^ 1);

        // ---- S = Q K^T, fp16 2-pass hi/lo (qh*kh + ql*kh) ----
        const char* K = smc + (buf ? OFF_K1 : OFF_K0);
        float sf[4][4];
#pragma unroll
        for (int nf = 0; nf < 4; nf++) {
#pragma unroll
            for (int j = 0; j < 4; j++) sf[nf][j] = 0.0f;
            const char* krow = K + (32 * wc + 8 * nf + tg) * 80;
#pragma unroll
            for (int kk = 0; kk < 2; kk++) {
                int d = kk * 16 + 2 * tq;
                u32 bh0 = *(const u32*)(krow + d * 2);
                u32 bh1 = *(const u32*)(krow + (d + 8) * 2);
                mma16(sf[nf], qh[kk], bh0, bh1);
                mma16(sf[nf], ql[kk], bh0, bh1);
            }
        }

        // ---- row max; exchange within warp pair via named barrier ----
        float rm0 = fmaxf(fmaxf(sf[0][0], sf[0][1]), fmaxf(sf[1][0], sf[1][1]));
        rm0 = fmaxf(rm0, fmaxf(fmaxf(sf[2][0], sf[2][1]), fmaxf(sf[3][0], sf[3][1])));
        float rm1 = fmaxf(fmaxf(sf[0][2], sf[0][3]), fmaxf(sf[1][2], sf[1][3]));
        rm1 = fmaxf(rm1, fmaxf(fmaxf(sf[2][2], sf[2][3]), fmaxf(sf[3][2], sf[3][3])));
        rm0 = fmaxf(rm0, __shfl_xor_sync(0xffffffffu, rm0, 1));
        rm0 = fmaxf(rm0, __shfl_xor_sync(0xffffffffu, rm0, 2));
        rm1 = fmaxf(rm1, __shfl_xor_sync(0xffffffffu, rm1, 1));
        rm1 = fmaxf(rm1, __shfl_xor_sync(0xffffffffu, rm1, 2));
        if (tq == 0) { Rm[wc * 64 + r0] = rm0; Rm[wc * 64 + r0 + 8] = rm1; }
        asm volatile("bar.sync %0, 64;" :: "r"(wm + 1) : "memory");

        // ---- softmax ----
        const float mo0 = Mbuf[par * 64 + r0], mo1 = Mbuf[par * 64 + r0 + 8];
        const float nm0 = fmaxf(mo0, fmaxf(Rm[r0], Rm[64 + r0]));
        const float nm1 = fmaxf(mo1, fmaxf(Rm[r0 + 8], Rm[64 + r0 + 8]));
        float lp0 = 0.0f, lp1 = 0.0f;
#pragma unroll
        for (int nf = 0; nf < 4; nf++) {
            __half2 h01 = __floats2half2_rn(__expf(sf[nf][0] - nm0), __expf(sf[nf][1] - nm0));
            __half2 h23 = __floats2half2_rn(__expf(sf[nf][2] - nm1), __expf(sf[nf][3] - nm1));
            float2 f01 = __half22float2(h01), f23 = __half22float2(h23);
            lp0 += f01.x + f01.y; lp1 += f23.x + f23.y;
            const int col = 32 * wc + 8 * nf + 2 * tq;
            *(u32*)(smc + OFF_P + r0 * 144 + col * 2) = *(u32*)&h01;
            *(u32*)(smc + OFF_P + (r0 + 8) * 144 + col * 2) = *(u32*)&h23;
        }
        lp0 += __shfl_xor_sync(0xffffffffu, lp0, 1);
        lp0 += __shfl_xor_sync(0xffffffffu, lp0, 2);
        lp1 += __shfl_xor_sync(0xffffffffu, lp1, 1);
        lp1 += __shfl_xor_sync(0xffffffffu, lp1, 2);
        if (tq == 0) { Psum[wc * 64 + r0] = lp0; Psum[wc * 64 + r0 + 8] = lp1; }
        if (owner) {
            Abuf[r0] = __expf(mo0 - nm0);
            Abuf[r0 + 8] = __expf(mo1 - nm1);
            Mbuf[(par ^ 1) * 64 + r0] = nm0;
            Mbuf[(par ^ 1) * 64 + r0 + 8] = nm1;
        }
        __syncthreads();   // bar3: P + A visible to all warps

        if (owner) {
            Lbuf[r0]     = Lbuf[r0]     * Abuf[r0]     + Psum[r0]     + Psum[64 + r0];
            Lbuf[r0 + 8] = Lbuf[r0 + 8] * Abuf[r0 + 8] + Psum[r0 + 8] + Psum[64 + r0 + 8];
        }

        // ---- PV ----
        const char* V = smc + (buf ? OFF_V1 : OFF_V0);
#pragma unroll
        for (int mj = 0; mj < 4; mj++) {
            const float a0 = Abuf[16 * mj + tg], a1 = Abuf[16 * mj + tg + 8];
            if (__all_sync(0xffffffffu, (a0 == 1.0f) && (a1 == 1.0f))) continue;
            const u64 A0 = dup2(a0), A1 = dup2(a1);
#pragma unroll
            for (int nf = 0; nf < 4; nf++) {
                u64* pa = reinterpret_cast<u64*>(acc[mj][nf]);
                pa[0] = mul2(pa[0], A0);
                pa[1] = mul2(pa[1], A1);
            }
        }
#pragma unroll
        for (int kk = 0; kk < 4; kk++) {
            const int m = kk * 16 + 2 * tq;
            u32 af[4][4];
#pragma unroll
            for (int mj = 0; mj < 4; mj++) {
                const int rr = 16 * mj + tg;
                af[mj][0] = *(const u32*)(smc + OFF_P + rr * 144 + m * 2);
                af[mj][1] = *(const u32*)(smc + OFF_P + (rr + 8) * 144 + m * 2);
                af[mj][2] = *(const u32*)(smc + OFF_P + rr * 144 + (m + 8) * 2);
                af[mj][3] = *(const u32*)(smc + OFF_P + (rr + 8) * 144 + (m + 8) * 2);
            }
#pragma unroll
            for (int nf = 0; nf < 4; nf++) {
                const char* vrow = V + (32 * wid + 8 * nf + tg) * 144;
                u32 b0 = *(const u32*)(vrow + m * 2);
                u32 b1 = *(const u32*)(vrow + (m + 8) * 2);
#pragma unroll
                for (int mj = 0; mj < 4; mj++)
                    mma16(acc[mj][nf], af[mj], b0, b1);
            }
        }
        // no end barrier: bar1 of iteration t+1 provides the ordering
    }
    __syncthreads();

    // ---- epilogue: O/L + residual ----
#pragma unroll
    for (int mj = 0; mj < 4; mj++) {
        const int rr = 16 * mj + tg;
        const float il0 = 1.0f / Lbuf[rr];
        const float il1 = 1.0f / Lbuf[rr + 8];
#pragma unroll
        for (int nf = 0; nf < 4; nf++) {
            const int c = 32 * wid + 8 * nf + 2 * tq;
            size_t g00 = ((size_t)b * CDIM + c) * NDIM + n0 + rr;
            size_t g01 = g00 + NDIM;
            size_t g10 = g00 + 8;
            size_t g11 = g01 + 8;
            out[g00] = acc[mj][nf][0] * il0 + x[g00];
            out[g01] = acc[mj][nf][1] * il0 + x[g01];
            out[g10] = acc[mj][nf][2] * il1 + x[g10];
            out[g11] = acc[mj][nf][3] * il1 + x[g11];
        }
    }
}

extern "C" void kernel_launch(void* const* d_in, const int* in_sizes, int n_in,
                              void* d_out, int out_size) {
    const float* x    = (const float*)d_in[0];
    const float* q_w  = (const float*)d_in[1];
    const float* q_g  = (const float*)d_in[3];
    const float* q_be = (const float*)d_in[4];
    const float* k_w  = (const float*)d_in[5];
    const float* k_g  = (const float*)d_in[7];
    const float* k_be = (const float*)d_in[8];
    const float* v_w  = (const float*)d_in[9];
    const float* v_g  = (const float*)d_in[11];
    const float* v_be = (const float*)d_in[12];
    float* out = (float*)d_out;

    w16_kernel<<<OTOT, 128>>>(q_w, k_w, v_w);
    proj16_kernel<<<dim3(5, 8, 16), 256>>>(x);
    stats_fin<<<OTOT, 128>>>(q_g, q_be, k_g, k_be, v_g, v_be);
    qkt_kernel<<<dim3(32, 16), 256>>>();
    v16_kernel<<<dim3(512, 16), 256>>>();

    static int smem_set = 0;
    if (!smem_set) {
        cudaFuncSetAttribute(attn_kernel, cudaFuncAttributeMaxDynamicSharedMemorySize, SMEM_TOTAL);
        smem_set = 1;
    }
    attn_kernel<<<dim3(32, 16), 256, SMEM_TOTAL>>>(x, out);
}

// round 12
// speedup vs baseline: 4.8776x; 1.0419x over previous
#include <cuda_runtime.h>
#include <cuda_fp16.h>
#include <math.h>
#include <stdint.h>

typedef unsigned int u32;
typedef unsigned long long u64;

#define BDIM 16
#define CDIM 256
#define NDIM 2048
#define OTOT 320
#define EPSV 1e-5f

__device__ __align__(16) float g_proj[(size_t)BDIM * OTOT * NDIM];
__device__ __align__(16) u32 g_w16h[OTOT * 128];
__device__ __align__(16) u32 g_w16l[OTOT * 128];
__device__ __align__(16) __half g_q16[(size_t)BDIM * NDIM * 64];   // [b][n][hi32|lo32]
__device__ __align__(16) __half g_k16[(size_t)BDIM * NDIM * 64];   // [b][m][hi32|lo32]
__device__ __align__(16) __half g_v16[(size_t)BDIM * CDIM * NDIM]; // [b][c][m]
__device__ float g_ps1[OTOT * 128];
__device__ float g_ps2[OTOT * 128];
__device__ float g_scale[OTOT];
__device__ float g_shift[OTOT];

// ---------------- helpers ----------------
__device__ __forceinline__ u64 dup2(float v) {
    u64 r; asm("mov.b64 %0, {%1, %1};" : "=l"(r) : "f"(v)); return r;
}
__device__ __forceinline__ u64 mul2(u64 a, u64 b) {
    u64 r; asm("mul.rn.f32x2 %0, %1, %2;" : "=l"(r) : "l"(a), "l"(b)); return r;
}
__device__ __forceinline__ u32 smem_u32(const void* p) {
    u32 a; asm("{ .reg .u64 t; cvta.to.shared.u64 t, %1; cvt.u32.u64 %0, t; }" : "=r"(a) : "l"(p));
    return a;
}
__device__ __forceinline__ void mma16(float d[4], const u32 a[4], u32 b0, u32 b1) {
    asm volatile("mma.sync.aligned.m16n8k16.row.col.f32.f16.f16.f32 "
                 "{%0,%1,%2,%3}, {%4,%5,%6,%7}, {%8,%9}, {%0,%1,%2,%3};"
                 : "+f"(d[0]), "+f"(d[1]), "+f"(d[2]), "+f"(d[3])
                 : "r"(a[0]), "r"(a[1]), "r"(a[2]), "r"(a[3]), "r"(b0), "r"(b1));
}
#define CP16(dst, src) asm volatile("cp.async.cg.shared.global [%0], [%1], 16;" :: "r"(dst), "l"(src))
#define CP_COMMIT()    asm volatile("cp.async.commit_group;" ::: "memory")
#define CP_WAIT0()     asm volatile("cp.async.wait_group 0;" ::: "memory")

// ================= Kernel 0: W -> fp16 hi/lo split =================
__global__ void __launch_bounds__(128) w16_kernel(
    const float* __restrict__ qw, const float* __restrict__ kw, const float* __restrict__ vw)
{
    const int o = blockIdx.x, t = threadIdx.x;
    const float* row = o < 32 ? qw + (size_t)o * CDIM
                     : o < 64 ? kw + (size_t)(o - 32) * CDIM
                              : vw + (size_t)(o - 64) * CDIM;
    float v0 = row[2 * t], v1 = row[2 * t + 1];
    __half h0 = __float2half_rn(v0), h1 = __float2half_rn(v1);
    __half l0 = __float2half_rn(v0 - __half2float(h0));
    __half l1 = __float2half_rn(v1 - __half2float(h1));
    __half2 hh = __halves2half2(h0, h1), ll = __halves2half2(l0, l1);
    g_w16h[o * 128 + t] = *(u32*)&hh;
    g_w16l[o * 128 + t] = *(u32*)&ll;
}

// ================= Kernel 1: QKV projection (fp16 mma, 3-pass) + fused stats =====
__global__ void __launch_bounds__(256) proj16_kernel(const float* __restrict__ x)
{
    __shared__ u32 xs_h[2][2048];
    __shared__ u32 xs_l[2][2048];
    __shared__ float2 sm_sp[128];
    const int tid = threadIdx.x, wid = tid >> 5, lane = tid & 31;
    const int tg = lane >> 2, tq = lane & 3;
    const int wo = wid & 3, wn = wid >> 2;
    const int ob = blockIdx.x * 64 + wo * 16;
    const int gn0 = blockIdx.y * 256, b = blockIdx.z;
    const float* xb = x + (size_t)b * CDIM * NDIM + gn0;
    const int pn = tid;

    float acc[16][4];
#pragma unroll
    for (int nf = 0; nf < 16; nf++)
#pragma unroll
        for (int j = 0; j < 4; j++) acc[nf][j] = 0.0f;

    float stg[8][2];
    auto ldg = [&](int t1) {
#pragma unroll
        for (int cp = 0; cp < 8; cp++) {
            int c = t1 * 16 + 2 * cp;
            stg[cp][0] = xb[(size_t)c * NDIM + pn];
            stg[cp][1] = xb[(size_t)(c + 1) * NDIM + pn];
        }
    };
    auto sts = [&](int buf) {
#pragma unroll
        for (int cp = 0; cp < 8; cp++) {
            __half h0 = __float2half_rn(stg[cp][0]), h1 = __float2half_rn(stg[cp][1]);
            __half l0 = __float2half_rn(stg[cp][0] - __half2float(h0));
            __half l1 = __float2half_rn(stg[cp][1] - __half2float(h1));
            __half2 hh = __halves2half2(h0, h1), ll = __halves2half2(l0, l1);
            int a = cp * 256 + (pn ^ (cp << 3));
            xs_h[buf][a] = *(u32*)&hh;
            xs_l[buf][a] = *(u32*)&ll;
        }
    };

    ldg(0); sts(0);
    __syncthreads();

    for (int t = 0; t < 16; t++) {
        if (t < 15) ldg(t + 1);
        const int buf = t & 1;
        u32 ah[4], al[4];
        {
            size_t r = (size_t)(ob + tg) * 128 + 8 * t + tq;
            ah[0] = g_w16h[r];            ah[1] = g_w16h[r + 8 * 128];
            ah[2] = g_w16h[r + 4];        ah[3] = g_w16h[r + 8 * 128 + 4];
            al[0] = g_w16l[r];            al[1] = g_w16l[r + 8 * 128];
            al[2] = g_w16l[r + 4];        al[3] = g_w16l[r + 8 * 128 + 4];
        }
#pragma unroll
        for (int nf = 0; nf < 16; nf++) {
            const int nl = wn * 128 + 8 * nf + tg;
            u32 bh0 = xs_h[buf][tq * 256 + (nl ^ (tq << 3))];
            u32 bh1 = xs_h[buf][(tq + 4) * 256 + (nl ^ ((tq + 4) << 3))];
            u32 bl0 = xs_l[buf][tq * 256 + (nl ^ (tq << 3))];
            u32 bl1 = xs_l[buf][(tq + 4) * 256 + (nl ^ ((tq + 4) << 3))];
            mma16(acc[nf], ah, bh0, bh1);
            mma16(acc[nf], al, bh0, bh1);
            mma16(acc[nf], ah, bl0, bl1);
        }
        if (t < 15) sts((t + 1) & 1);
        __syncthreads();
    }

    // ---- store proj ----
#pragma unroll
    for (int nf = 0; nf < 16; nf++) {
        const int n = gn0 + wn * 128 + 8 * nf + 2 * tq;
        size_t base = ((size_t)b * OTOT + ob + tg) * NDIM + n;
        *reinterpret_cast<float2*>(&g_proj[base]) = make_float2(acc[nf][0], acc[nf][1]);
        *reinterpret_cast<float2*>(&g_proj[base + (size_t)8 * NDIM]) = make_float2(acc[nf][2], acc[nf][3]);
    }

    // ---- fused per-channel stats partials ----
    float s0 = 0.f, q0 = 0.f, s1 = 0.f, q1 = 0.f;
#pragma unroll
    for (int nf = 0; nf < 16; nf++) {
        s0 += acc[nf][0] + acc[nf][1];
        q0 += acc[nf][0] * acc[nf][0] + acc[nf][1] * acc[nf][1];
        s1 += acc[nf][2] + acc[nf][3];
        q1 += acc[nf][2] * acc[nf][2] + acc[nf][3] * acc[nf][3];
    }
#pragma unroll
    for (int off = 1; off < 4; off <<= 1) {
        s0 += __shfl_xor_sync(0xffffffffu, s0, off);
        q0 += __shfl_xor_sync(0xffffffffu, q0, off);
        s1 += __shfl_xor_sync(0xffffffffu, s1, off);
        q1 += __shfl_xor_sync(0xffffffffu, q1, off);
    }
    if (tq == 0) {
        sm_sp[wid * 16 + tg]     = make_float2(s0, q0);
        sm_sp[wid * 16 + 8 + tg] = make_float2(s1, q1);
    }
    __syncthreads();
    if (tid < 64) {
        int wo2 = tid >> 4, c = tid & 15;
        float2 a = sm_sp[wo2 * 16 + c];
        float2 e = sm_sp[(wo2 + 4) * 16 + c];
        int ch = blockIdx.x * 64 + wo2 * 16 + c;
        g_ps1[ch * 128 + b * 8 + blockIdx.y] = a.x + e.x;
        g_ps2[ch * 128 + b * 8 + blockIdx.y] = a.y + e.y;
    }
}

// ================= Kernel 2: finalize stats -> scale/shift =================
__global__ void __launch_bounds__(128) stats_fin(
    const float* __restrict__ qg, const float* __restrict__ qbe,
    const float* __restrict__ kg, const float* __restrict__ kbe,
    const float* __restrict__ vg, const float* __restrict__ vbe)
{
    const int ch = blockIdx.x, tid = threadIdx.x;
    __shared__ float r1[128], r2[128];
    r1[tid] = g_ps1[ch * 128 + tid];
    r2[tid] = g_ps2[ch * 128 + tid];
    __syncthreads();
    for (int off = 64; off; off >>= 1) {
        if (tid < off) { r1[tid] += r1[tid + off]; r2[tid] += r2[tid + off]; }
        __syncthreads();
    }
    if (tid == 0) {
        const float invM = 1.0f / (float)(BDIM * NDIM);
        float mean = r1[0] * invM;
        float var = r2[0] * invM - mean * mean;
        float gamma, beta;
        if (ch < 32)      { gamma = qg[ch];      beta = qbe[ch]; }
        else if (ch < 64) { gamma = kg[ch - 32]; beta = kbe[ch - 32]; }
        else              { gamma = vg[ch - 64]; beta = vbe[ch - 64]; }
        float sc = gamma * rsqrtf(var + EPSV);
        g_scale[ch] = sc;
        g_shift[ch] = beta - mean * sc;
    }
}

// ================= Kernel 3: Q/K normalize + transpose -> fp16 hi/lo =======
__global__ void __launch_bounds__(256) qkt_kernel()
{
    __shared__ float s[64][65];
    __shared__ float scl[64], shf[64];
    const int tid = threadIdx.x;
    const int n0 = blockIdx.x * 64, b = blockIdx.y;
    if (tid < 64) { scl[tid] = g_scale[tid]; shf[tid] = g_shift[tid]; }
    __syncthreads();
    for (int idx = tid; idx < 4096; idx += 256) {
        int ch = idx >> 6, nn = idx & 63;
        s[ch][nn] = g_proj[((size_t)b * OTOT + ch) * NDIM + n0 + nn] * scl[ch] + shf[ch];
    }
    __syncthreads();
    const int n = tid >> 2, d0 = (tid & 3) * 8;
    const size_t row = ((size_t)b * NDIM + n0 + n) * 64;
#pragma unroll
    for (int qk = 0; qk < 2; qk++) {
        __half* dst = (qk ? g_k16 : g_q16) + row;
        u32 wh[4], wl[4];
#pragma unroll
        for (int j = 0; j < 4; j++) {
            float v0 = s[qk * 32 + d0 + 2 * j][n];
            float v1 = s[qk * 32 + d0 + 2 * j + 1][n];
            __half h0 = __float2half_rn(v0), h1 = __float2half_rn(v1);
            __half l0 = __float2half_rn(v0 - __half2float(h0));
            __half l1 = __float2half_rn(v1 - __half2float(h1));
            wh[j] = (u32)*(unsigned short*)&h0 | ((u32)*(unsigned short*)&h1 << 16);
            wl[j] = (u32)*(unsigned short*)&l0 | ((u32)*(unsigned short*)&l1 << 16);
        }
        *reinterpret_cast<uint4*>(dst + d0)      = make_uint4(wh[0], wh[1], wh[2], wh[3]);
        *reinterpret_cast<uint4*>(dst + 32 + d0) = make_uint4(wl[0], wl[1], wl[2], wl[3]);
    }
}

// ================= Kernel 4: V normalize + leaky -> fp16 =================
__global__ void __launch_bounds__(256) v16_kernel()
{
    const int b = blockIdx.y, tid = threadIdx.x;
    const int c = blockIdx.x >> 1;
    const float sc = g_scale[64 + c], sh = g_shift[64 + c];
    const int i4 = blockIdx.x * 256 + tid;
    const int n = (i4 * 4) & 2047;
    float4 v = *reinterpret_cast<const float4*>(&g_proj[((size_t)b * OTOT + 64 + c) * NDIM + n]);
    float a0 = v.x * sc + sh, a1 = v.y * sc + sh, a2 = v.z * sc + sh, a3 = v.w * sc + sh;
    a0 = a0 > 0.f ? a0 : 0.2f * a0; a1 = a1 > 0.f ? a1 : 0.2f * a1;
    a2 = a2 > 0.f ? a2 : 0.2f * a2; a3 = a3 > 0.f ? a3 : 0.2f * a3;
    __half2 p0 = __floats2half2_rn(a0, a1), p1 = __floats2half2_rn(a2, a3);
    uint2 w = make_uint2(*(u32*)&p0, *(u32*)&p1);
    *reinterpret_cast<uint2*>(&g_v16[((size_t)b * CDIM + c) * NDIM + n]) = w;
}

// ================= Kernel 5: fp16 mma flash attention (1-pass S) =====
#define OFF_K0 0
#define OFF_K1 5120
#define OFF_V0 10240
#define OFF_V1 47104
#define OFF_P  83968
#define OFF_M  93184
#define OFF_L  93696
#define OFF_A  93952
#define OFF_RM 94208
#define OFF_PS 94720
#define SMEM_TOTAL 95232

__global__ void __launch_bounds__(256, 2) attn_kernel(
    const float* __restrict__ x, float* __restrict__ out)
{
    extern __shared__ __align__(16) char smc[];
    const u32 sb = smem_u32(smc);
    float* Mbuf = (float*)(smc + OFF_M);
    float* Lbuf = (float*)(smc + OFF_L);
    float* Abuf = (float*)(smc + OFF_A);
    float* Rm   = (float*)(smc + OFF_RM);
    float* Psum = (float*)(smc + OFF_PS);

    const int tid = threadIdx.x, wid = tid >> 5, lane = tid & 31;
    const int wm = wid & 3, wc = wid >> 2;
    const int tg = lane >> 2, tq = lane & 3;
    const int n0 = blockIdx.x * 64, b = blockIdx.y;
    const int r0 = 16 * wm + tg;
    const bool owner = (wc == 0 && tq == 0);

    if (tid < 64) { Mbuf[tid] = -INFINITY; Lbuf[tid] = 0.0f; }

    // Q A-fragments: hi only (1-pass S)
    u32 qh[2][4];
    {
        const __half* Qg = g_q16 + ((size_t)b * NDIM + n0) * 64;
#pragma unroll
        for (int kk = 0; kk < 2; kk++) {
            int d = kk * 16 + 2 * tq;
            qh[kk][0] = *(const u32*)(Qg + (size_t)r0 * 64 + d);
            qh[kk][1] = *(const u32*)(Qg + (size_t)(r0 + 8) * 64 + d);
            qh[kk][2] = *(const u32*)(Qg + (size_t)r0 * 64 + d + 8);
            qh[kk][3] = *(const u32*)(Qg + (size_t)(r0 + 8) * 64 + d + 8);
        }
    }

    float acc[4][4][4];
#pragma unroll
    for (int mj = 0; mj < 4; mj++)
#pragma unroll
        for (int nf = 0; nf < 4; nf++)
#pragma unroll
            for (int j = 0; j < 4; j++) acc[mj][nf][j] = 0.0f;

    // K tile: 64 rows x 80B (hi only). V tile: 256 rows x 144B.
    auto issue_tile = [&](int m0, int bf) {
        u32 kb = sb + (bf ? OFF_K1 : OFF_K0);
        u32 vb = sb + (bf ? OFF_V1 : OFF_V0);
        const __half* Kg = g_k16 + ((size_t)b * NDIM + m0) * 64;
        const __half* Vg = g_v16 + (size_t)b * CDIM * NDIM + m0;
#pragma unroll
        for (int i = 0; i < 9; i++) {
            int id = tid + i * 256;
            if (id < 256) {
                int m = id >> 2, ch = id & 3;
                CP16(kb + m * 80 + ch * 16, Kg + (size_t)m * 64 + ch * 8);
            } else {
                int j = id - 256, c = j >> 3, ch = j & 7;
                CP16(vb + c * 144 + ch * 16, Vg + (size_t)c * NDIM + ch * 8);
            }
        }
        CP_COMMIT();
    };

    issue_tile(0, 0);

    for (int t = 0; t < 32; t++) {
        const int buf = t & 1, par = t & 1;
        CP_WAIT0();
        __syncthreads();   // bar1: K/V(t) visible; all warps done with tile t-1
        if (t < 31) issue_tile((t + 1) * 64, buf ^ 1);

        // ---- S = Q K^T, fp16 single pass (qh*kh) ----
        const char* K = smc + (buf ? OFF_K1 : OFF_K0);
        float sf[4][4];
#pragma unroll
        for (int nf = 0; nf < 4; nf++) {
#pragma unroll
            for (int j = 0; j < 4; j++) sf[nf][j] = 0.0f;
            const char* krow = K + (32 * wc + 8 * nf + tg) * 80;
#pragma unroll
            for (int kk = 0; kk < 2; kk++) {
                int d = kk * 16 + 2 * tq;
                u32 bh0 = *(const u32*)(krow + d * 2);
                u32 bh1 = *(const u32*)(krow + (d + 8) * 2);
                mma16(sf[nf], qh[kk], bh0, bh1);
            }
        }

        // ---- row max; exchange within warp pair via named barrier ----
        float rm0 = fmaxf(fmaxf(sf[0][0], sf[0][1]), fmaxf(sf[1][0], sf[1][1]));
        rm0 = fmaxf(rm0, fmaxf(fmaxf(sf[2][0], sf[2][1]), fmaxf(sf[3][0], sf[3][1])));
        float rm1 = fmaxf(fmaxf(sf[0][2], sf[0][3]), fmaxf(sf[1][2], sf[1][3]));
        rm1 = fmaxf(rm1, fmaxf(fmaxf(sf[2][2], sf[2][3]), fmaxf(sf[3][2], sf[3][3])));
        rm0 = fmaxf(rm0, __shfl_xor_sync(0xffffffffu, rm0, 1));
        rm0 = fmaxf(rm0, __shfl_xor_sync(0xffffffffu, rm0, 2));
        rm1 = fmaxf(rm1, __shfl_xor_sync(0xffffffffu, rm1, 1));
        rm1 = fmaxf(rm1, __shfl_xor_sync(0xffffffffu, rm1, 2));
        if (tq == 0) { Rm[wc * 64 + r0] = rm0; Rm[wc * 64 + r0 + 8] = rm1; }
        asm volatile("bar.sync %0, 64;" :: "r"(wm + 1) : "memory");

        // ---- softmax ----
        const float mo0 = Mbuf[par * 64 + r0], mo1 = Mbuf[par * 64 + r0 + 8];
        const float nm0 = fmaxf(mo0, fmaxf(Rm[r0], Rm[64 + r0]));
        const float nm1 = fmaxf(mo1, fmaxf(Rm[r0 + 8], Rm[64 + r0 + 8]));
        float lp0 = 0.0f, lp1 = 0.0f;
#pragma unroll
        for (int nf = 0; nf < 4; nf++) {
            __half2 h01 = __floats2half2_rn(__expf(sf[nf][0] - nm0), __expf(sf[nf][1] - nm0));
            __half2 h23 = __floats2half2_rn(__expf(sf[nf][2] - nm1), __expf(sf[nf][3] - nm1));
            float2 f01 = __half22float2(h01), f23 = __half22float2(h23);
            lp0 += f01.x + f01.y; lp1 += f23.x + f23.y;
            const int col = 32 * wc + 8 * nf + 2 * tq;
            *(u32*)(smc + OFF_P + r0 * 144 + col * 2) = *(u32*)&h01;
            *(u32*)(smc + OFF_P + (r0 + 8) * 144 + col * 2) = *(u32*)&h23;
        }
        lp0 += __shfl_xor_sync(0xffffffffu, lp0, 1);
        lp0 += __shfl_xor_sync(0xffffffffu, lp0, 2);
        lp1 += __shfl_xor_sync(0xffffffffu, lp1, 1);
        lp1 += __shfl_xor_sync(0xffffffffu, lp1, 2);
        if (tq == 0) { Psum[wc * 64 + r0] = lp0; Psum[wc * 64 + r0 + 8] = lp1; }
        if (owner) {
            Abuf[r0] = __expf(mo0 - nm0);
            Abuf[r0 + 8] = __expf(mo1 - nm1);
            Mbuf[(par ^ 1) * 64 + r0] = nm0;
            Mbuf[(par ^ 1) * 64 + r0 + 8] = nm1;
        }
        __syncthreads();   // bar3: P + A visible to all warps

        if (owner) {
            Lbuf[r0]     = Lbuf[r0]     * Abuf[r0]     + Psum[r0]     + Psum[64 + r0];
            Lbuf[r0 + 8] = Lbuf[r0 + 8] * Abuf[r0 + 8] + Psum[r0 + 8] + Psum[64 + r0 + 8];
        }

        // ---- PV ----
        const char* V = smc + (buf ? OFF_V1 : OFF_V0);
#pragma unroll
        for (int mj = 0; mj < 4; mj++) {
            const float a0 = Abuf[16 * mj + tg], a1 = Abuf[16 * mj + tg + 8];
            if (__all_sync(0xffffffffu, (a0 == 1.0f) && (a1 == 1.0f))) continue;
            const u64 A0 = dup2(a0), A1 = dup2(a1);
#pragma unroll
            for (int nf = 0; nf < 4; nf++) {
                u64* pa = reinterpret_cast<u64*>(acc[mj][nf]);
                pa[0] = mul2(pa[0], A0);
                pa[1] = mul2(pa[1], A1);
            }
        }
#pragma unroll
        for (int kk = 0; kk < 4; kk++) {
            const int m = kk * 16 + 2 * tq;
            u32 af[4][4];
#pragma unroll
            for (int mj = 0; mj < 4; mj++) {
                const int rr = 16 * mj + tg;
                af[mj][0] = *(const u32*)(smc + OFF_P + rr * 144 + m * 2);
                af[mj][1] = *(const u32*)(smc + OFF_P + (rr + 8) * 144 + m * 2);
                af[mj][2] = *(const u32*)(smc + OFF_P + rr * 144 + (m + 8) * 2);
                af[mj][3] = *(const u32*)(smc + OFF_P + (rr + 8) * 144 + (m + 8) * 2);
            }
#pragma unroll
            for (int nf = 0; nf < 4; nf++) {
                const char* vrow = V + (32 * wid + 8 * nf + tg) * 144;
                u32 b0 = *(const u32*)(vrow + m * 2);
                u32 b1 = *(const u32*)(vrow + (m + 8) * 2);
#pragma unroll
                for (int mj = 0; mj < 4; mj++)
                    mma16(acc[mj][nf], af[mj], b0, b1);
            }
        }
        // no end barrier: bar1 of iteration t+1 provides the ordering
    }
    __syncthreads();

    // ---- epilogue: O/L + residual ----
#pragma unroll
    for (int mj = 0; mj < 4; mj++) {
        const int rr = 16 * mj + tg;
        const float il0 = 1.0f / Lbuf[rr];
        const float il1 = 1.0f / Lbuf[rr + 8];
#pragma unroll
        for (int nf = 0; nf < 4; nf++) {
            const int c = 32 * wid + 8 * nf + 2 * tq;
            size_t g00 = ((size_t)b * CDIM + c) * NDIM + n0 + rr;
            size_t g01 = g00 + NDIM;
            size_t g10 = g00 + 8;
            size_t g11 = g01 + 8;
            out[g00] = acc[mj][nf][0] * il0 + x[g00];
            out[g01] = acc[mj][nf][1] * il0 + x[g01];
            out[g10] = acc[mj][nf][2] * il1 + x[g10];
            out[g11] = acc[mj][nf][3] * il1 + x[g11];
        }
    }
}

extern "C" void kernel_launch(void* const* d_in, const int* in_sizes, int n_in,
                              void* d_out, int out_size) {
    const float* x    = (const float*)d_in[0];
    const float* q_w  = (const float*)d_in[1];
    const float* q_g  = (const float*)d_in[3];
    const float* q_be = (const float*)d_in[4];
    const float* k_w  = (const float*)d_in[5];
    const float* k_g  = (const float*)d_in[7];
    const float* k_be = (const float*)d_in[8];
    const float* v_w  = (const float*)d_in[9];
    const float* v_g  = (const float*)d_in[11];
    const float* v_be = (const float*)d_in[12];
    float* out = (float*)d_out;

    w16_kernel<<<OTOT, 128>>>(q_w, k_w, v_w);
    proj16_kernel<<<dim3(5, 8, 16), 256>>>(x);
    stats_fin<<<OTOT, 128>>>(q_g, q_be, k_g, k_be, v_g, v_be);
    qkt_kernel<<<dim3(32, 16), 256>>>();
    v16_kernel<<<dim3(512, 16), 256>>>();

    static int smem_set = 0;
    if (!smem_set) {
        cudaFuncSetAttribute(attn_kernel, cudaFuncAttributeMaxDynamicSharedMemorySize, SMEM_TOTAL);
        smem_set = 1;
    }
    attn_kernel<<<dim3(32, 16), 256, SMEM_TOTAL>>>(x, out);
}

// round 13
// speedup vs baseline: 5.3190x; 1.0905x over previous
#include <cuda_runtime.h>
#include <cuda_fp16.h>
#include <math.h>
#include <stdint.h>

typedef unsigned int u32;
typedef unsigned long long u64;

#define BDIM 16
#define CDIM 256
#define NDIM 2048
#define OTOT 320
#define EPSV 1e-5f

__device__ __align__(16) float g_proj[(size_t)BDIM * OTOT * NDIM];
__device__ __align__(16) u32 g_w16h[OTOT * 128];
__device__ __align__(16) u32 g_w16l[OTOT * 128];
__device__ __align__(16) __half g_q16[(size_t)BDIM * NDIM * 64];   // [b][n][hi32|lo32]
__device__ __align__(16) __half g_k16[(size_t)BDIM * NDIM * 64];   // [b][m][hi32|lo32]
__device__ __align__(16) __half g_v16[(size_t)BDIM * CDIM * NDIM]; // [b][c][m]
__device__ float g_ps1[OTOT * 128];
__device__ float g_ps2[OTOT * 128];
__device__ float g_scale[OTOT];
__device__ float g_shift[OTOT];

// ---------------- helpers ----------------
__device__ __forceinline__ u64 dup2(float v) {
    u64 r; asm("mov.b64 %0, {%1, %1};" : "=l"(r) : "f"(v)); return r;
}
__device__ __forceinline__ u64 mul2(u64 a, u64 b) {
    u64 r; asm("mul.rn.f32x2 %0, %1, %2;" : "=l"(r) : "l"(a), "l"(b)); return r;
}
__device__ __forceinline__ u32 smem_u32(const void* p) {
    u32 a; asm("{ .reg .u64 t; cvta.to.shared.u64 t, %1; cvt.u32.u64 %0, t; }" : "=r"(a) : "l"(p));
    return a;
}
__device__ __forceinline__ void mma16(float d[4], const u32 a[4], u32 b0, u32 b1) {
    asm volatile("mma.sync.aligned.m16n8k16.row.col.f32.f16.f16.f32 "
                 "{%0,%1,%2,%3}, {%4,%5,%6,%7}, {%8,%9}, {%0,%1,%2,%3};"
                 : "+f"(d[0]), "+f"(d[1]), "+f"(d[2]), "+f"(d[3])
                 : "r"(a[0]), "r"(a[1]), "r"(a[2]), "r"(a[3]), "r"(b0), "r"(b1));
}
#define CP16(dst, src) asm volatile("cp.async.cg.shared.global [%0], [%1], 16;" :: "r"(dst), "l"(src))
#define CP_COMMIT()    asm volatile("cp.async.commit_group;" ::: "memory")
#define CP_WAIT0()     asm volatile("cp.async.wait_group 0;" ::: "memory")

// ================= Kernel 0: W -> fp16 hi/lo split =================
__global__ void __launch_bounds__(128) w16_kernel(
    const float* __restrict__ qw, const float* __restrict__ kw, const float* __restrict__ vw)
{
    const int o = blockIdx.x, t = threadIdx.x;
    const float* row = o < 32 ? qw + (size_t)o * CDIM
                     : o < 64 ? kw + (size_t)(o - 32) * CDIM
                              : vw + (size_t)(o - 64) * CDIM;
    float v0 = row[2 * t], v1 = row[2 * t + 1];
    __half h0 = __float2half_rn(v0), h1 = __float2half_rn(v1);
    __half l0 = __float2half_rn(v0 - __half2float(h0));
    __half l1 = __float2half_rn(v1 - __half2float(h1));
    __half2 hh = __halves2half2(h0, h1), ll = __halves2half2(l0, l1);
    g_w16h[o * 128 + t] = *(u32*)&hh;
    g_w16l[o * 128 + t] = *(u32*)&ll;
}

// ================= Kernel 1: QKV projection (fp16 mma, 2-pass: Wh*Xh + Wl*Xh) + fused stats =====
__global__ void __launch_bounds__(256) proj16_kernel(const float* __restrict__ x)
{
    __shared__ u32 xs_h[2][2048];
    __shared__ float2 sm_sp[128];
    const int tid = threadIdx.x, wid = tid >> 5, lane = tid & 31;
    const int tg = lane >> 2, tq = lane & 3;
    const int wo = wid & 3, wn = wid >> 2;
    const int ob = blockIdx.x * 64 + wo * 16;
    const int gn0 = blockIdx.y * 256, b = blockIdx.z;
    const float* xb = x + (size_t)b * CDIM * NDIM + gn0;
    const int pn = tid;

    float acc[16][4];
#pragma unroll
    for (int nf = 0; nf < 16; nf++)
#pragma unroll
        for (int j = 0; j < 4; j++) acc[nf][j] = 0.0f;

    float stg[8][2];
    auto ldg = [&](int t1) {
#pragma unroll
        for (int cp = 0; cp < 8; cp++) {
            int c = t1 * 16 + 2 * cp;
            stg[cp][0] = xb[(size_t)c * NDIM + pn];
            stg[cp][1] = xb[(size_t)(c + 1) * NDIM + pn];
        }
    };
    auto sts = [&](int buf) {
#pragma unroll
        for (int cp = 0; cp < 8; cp++) {
            __half2 hh = __floats2half2_rn(stg[cp][0], stg[cp][1]);
            xs_h[buf][cp * 256 + (pn ^ (cp << 3))] = *(u32*)&hh;
        }
    };

    ldg(0); sts(0);
    __syncthreads();

    for (int t = 0; t < 16; t++) {
        if (t < 15) ldg(t + 1);
        const int buf = t & 1;
        u32 ah[4], al[4];
        {
            size_t r = (size_t)(ob + tg) * 128 + 8 * t + tq;
            ah[0] = g_w16h[r];            ah[1] = g_w16h[r + 8 * 128];
            ah[2] = g_w16h[r + 4];        ah[3] = g_w16h[r + 8 * 128 + 4];
            al[0] = g_w16l[r];            al[1] = g_w16l[r + 8 * 128];
            al[2] = g_w16l[r + 4];        al[3] = g_w16l[r + 8 * 128 + 4];
        }
#pragma unroll
        for (int nf = 0; nf < 16; nf++) {
            const int nl = wn * 128 + 8 * nf + tg;
            u32 bh0 = xs_h[buf][tq * 256 + (nl ^ (tq << 3))];
            u32 bh1 = xs_h[buf][(tq + 4) * 256 + (nl ^ ((tq + 4) << 3))];
            mma16(acc[nf], ah, bh0, bh1);
            mma16(acc[nf], al, bh0, bh1);
        }
        if (t < 15) sts((t + 1) & 1);
        __syncthreads();
    }

    // ---- store proj ----
#pragma unroll
    for (int nf = 0; nf < 16; nf++) {
        const int n = gn0 + wn * 128 + 8 * nf + 2 * tq;
        size_t base = ((size_t)b * OTOT + ob + tg) * NDIM + n;
        *reinterpret_cast<float2*>(&g_proj[base]) = make_float2(acc[nf][0], acc[nf][1]);
        *reinterpret_cast<float2*>(&g_proj[base + (size_t)8 * NDIM]) = make_float2(acc[nf][2], acc[nf][3]);
    }

    // ---- fused per-channel stats partials ----
    float s0 = 0.f, q0 = 0.f, s1 = 0.f, q1 = 0.f;
#pragma unroll
    for (int nf = 0; nf < 16; nf++) {
        s0 += acc[nf][0] + acc[nf][1];
        q0 += acc[nf][0] * acc[nf][0] + acc[nf][1] * acc[nf][1];
        s1 += acc[nf][2] + acc[nf][3];
        q1 += acc[nf][2] * acc[nf][2] + acc[nf][3] * acc[nf][3];
    }
#pragma unroll
    for (int off = 1; off < 4; off <<= 1) {
        s0 += __shfl_xor_sync(0xffffffffu, s0, off);
        q0 += __shfl_xor_sync(0xffffffffu, q0, off);
        s1 += __shfl_xor_sync(0xffffffffu, s1, off);
        q1 += __shfl_xor_sync(0xffffffffu, q1, off);
    }
    if (tq == 0) {
        sm_sp[wid * 16 + tg]     = make_float2(s0, q0);
        sm_sp[wid * 16 + 8 + tg] = make_float2(s1, q1);
    }
    __syncthreads();
    if (tid < 64) {
        int wo2 = tid >> 4, c = tid & 15;
        float2 a = sm_sp[wo2 * 16 + c];
        float2 e = sm_sp[(wo2 + 4) * 16 + c];
        int ch = blockIdx.x * 64 + wo2 * 16 + c;
        g_ps1[ch * 128 + b * 8 + blockIdx.y] = a.x + e.x;
        g_ps2[ch * 128 + b * 8 + blockIdx.y] = a.y + e.y;
    }
}

// ================= Kernel 2: finalize stats -> scale/shift =================
__global__ void __launch_bounds__(128) stats_fin(
    const float* __restrict__ qg, const float* __restrict__ qbe,
    const float* __restrict__ kg, const float* __restrict__ kbe,
    const float* __restrict__ vg, const float* __restrict__ vbe)
{
    const int ch = blockIdx.x, tid = threadIdx.x;
    __shared__ float r1[128], r2[128];
    r1[tid] = g_ps1[ch * 128 + tid];
    r2[tid] = g_ps2[ch * 128 + tid];
    __syncthreads();
    for (int off = 64; off; off >>= 1) {
        if (tid < off) { r1[tid] += r1[tid + off]; r2[tid] += r2[tid + off]; }
        __syncthreads();
    }
    if (tid == 0) {
        const float invM = 1.0f / (float)(BDIM * NDIM);
        float mean = r1[0] * invM;
        float var = r2[0] * invM - mean * mean;
        float gamma, beta;
        if (ch < 32)      { gamma = qg[ch];      beta = qbe[ch]; }
        else if (ch < 64) { gamma = kg[ch - 32]; beta = kbe[ch - 32]; }
        else              { gamma = vg[ch - 64]; beta = vbe[ch - 64]; }
        float sc = gamma * rsqrtf(var + EPSV);
        g_scale[ch] = sc;
        g_shift[ch] = beta - mean * sc;
    }
}

// ================= Kernel 3: Q/K normalize + transpose -> fp16 hi/lo =======
__global__ void __launch_bounds__(256) qkt_kernel()
{
    __shared__ float s[64][65];
    __shared__ float scl[64], shf[64];
    const int tid = threadIdx.x;
    const int n0 = blockIdx.x * 64, b = blockIdx.y;
    if (tid < 64) { scl[tid] = g_scale[tid]; shf[tid] = g_shift[tid]; }
    __syncthreads();
    for (int idx = tid; idx < 4096; idx += 256) {
        int ch = idx >> 6, nn = idx & 63;
        s[ch][nn] = g_proj[((size_t)b * OTOT + ch) * NDIM + n0 + nn] * scl[ch] + shf[ch];
    }
    __syncthreads();
    const int n = tid >> 2, d0 = (tid & 3) * 8;
    const size_t row = ((size_t)b * NDIM + n0 + n) * 64;
#pragma unroll
    for (int qk = 0; qk < 2; qk++) {
        __half* dst = (qk ? g_k16 : g_q16) + row;
        u32 wh[4], wl[4];
#pragma unroll
        for (int j = 0; j < 4; j++) {
            float v0 = s[qk * 32 + d0 + 2 * j][n];
            float v1 = s[qk * 32 + d0 + 2 * j + 1][n];
            __half h0 = __float2half_rn(v0), h1 = __float2half_rn(v1);
            __half l0 = __float2half_rn(v0 - __half2float(h0));
            __half l1 = __float2half_rn(v1 - __half2float(h1));
            wh[j] = (u32)*(unsigned short*)&h0 | ((u32)*(unsigned short*)&h1 << 16);
            wl[j] = (u32)*(unsigned short*)&l0 | ((u32)*(unsigned short*)&l1 << 16);
        }
        *reinterpret_cast<uint4*>(dst + d0)      = make_uint4(wh[0], wh[1], wh[2], wh[3]);
        *reinterpret_cast<uint4*>(dst + 32 + d0) = make_uint4(wl[0], wl[1], wl[2], wl[3]);
    }
}

// ================= Kernel 4: V normalize + leaky -> fp16 =================
__global__ void __launch_bounds__(256) v16_kernel()
{
    const int b = blockIdx.y, tid = threadIdx.x;
    const int c = blockIdx.x >> 1;
    const float sc = g_scale[64 + c], sh = g_shift[64 + c];
    const int i4 = blockIdx.x * 256 + tid;
    const int n = (i4 * 4) & 2047;
    float4 v = *reinterpret_cast<const float4*>(&g_proj[((size_t)b * OTOT + 64 + c) * NDIM + n]);
    float a0 = v.x * sc + sh, a1 = v.y * sc + sh, a2 = v.z * sc + sh, a3 = v.w * sc + sh;
    a0 = a0 > 0.f ? a0 : 0.2f * a0; a1 = a1 > 0.f ? a1 : 0.2f * a1;
    a2 = a2 > 0.f ? a2 : 0.2f * a2; a3 = a3 > 0.f ? a3 : 0.2f * a3;
    __half2 p0 = __floats2half2_rn(a0, a1), p1 = __floats2half2_rn(a2, a3);
    uint2 w = make_uint2(*(u32*)&p0, *(u32*)&p1);
    *reinterpret_cast<uint2*>(&g_v16[((size_t)b * CDIM + c) * NDIM + n]) = w;
}

// ================= Kernel 5: fp16 mma flash attention (1-pass S) =====
#define OFF_K0 0
#define OFF_K1 5120
#define OFF_V0 10240
#define OFF_V1 47104
#define OFF_P  83968
#define OFF_M  93184
#define OFF_L  93696
#define OFF_A  93952
#define OFF_RM 94208
#define OFF_PS 94720
#define SMEM_TOTAL 95232

__global__ void __launch_bounds__(256, 2) attn_kernel(
    const float* __restrict__ x, float* __restrict__ out)
{
    extern __shared__ __align__(16) char smc[];
    const u32 sb = smem_u32(smc);
    float* Mbuf = (float*)(smc + OFF_M);
    float* Lbuf = (float*)(smc + OFF_L);
    float* Abuf = (float*)(smc + OFF_A);
    float* Rm   = (float*)(smc + OFF_RM);
    float* Psum = (float*)(smc + OFF_PS);

    const int tid = threadIdx.x, wid = tid >> 5, lane = tid & 31;
    const int wm = wid & 3, wc = wid >> 2;
    const int tg = lane >> 2, tq = lane & 3;
    const int n0 = blockIdx.x * 64, b = blockIdx.y;
    const int r0 = 16 * wm + tg;
    const bool owner = (wc == 0 && tq == 0);

    if (tid < 64) { Mbuf[tid] = -INFINITY; Lbuf[tid] = 0.0f; }

    u32 qh[2][4];
    {
        const __half* Qg = g_q16 + ((size_t)b * NDIM + n0) * 64;
#pragma unroll
        for (int kk = 0; kk < 2; kk++) {
            int d = kk * 16 + 2 * tq;
            qh[kk][0] = *(const u32*)(Qg + (size_t)r0 * 64 + d);
            qh[kk][1] = *(const u32*)(Qg + (size_t)(r0 + 8) * 64 + d);
            qh[kk][2] = *(const u32*)(Qg + (size_t)r0 * 64 + d + 8);
            qh[kk][3] = *(const u32*)(Qg + (size_t)(r0 + 8) * 64 + d + 8);
        }
    }

    float acc[4][4][4];
#pragma unroll
    for (int mj = 0; mj < 4; mj++)
#pragma unroll
        for (int nf = 0; nf < 4; nf++)
#pragma unroll
            for (int j = 0; j < 4; j++) acc[mj][nf][j] = 0.0f;

    auto issue_tile = [&](int m0, int bf) {
        u32 kb = sb + (bf ? OFF_K1 : OFF_K0);
        u32 vb = sb + (bf ? OFF_V1 : OFF_V0);
        const __half* Kg = g_k16 + ((size_t)b * NDIM + m0) * 64;
        const __half* Vg = g_v16 + (size_t)b * CDIM * NDIM + m0;
#pragma unroll
        for (int i = 0; i < 9; i++) {
            int id = tid + i * 256;
            if (id < 256) {
                int m = id >> 2, ch = id & 3;
                CP16(kb + m * 80 + ch * 16, Kg + (size_t)m * 64 + ch * 8);
            } else {
                int j = id - 256, c = j >> 3, ch = j & 7;
                CP16(vb + c * 144 + ch * 16, Vg + (size_t)c * NDIM + ch * 8);
            }
        }
        CP_COMMIT();
    };

    issue_tile(0, 0);

    for (int t = 0; t < 32; t++) {
        const int buf = t & 1, par = t & 1;
        CP_WAIT0();
        __syncthreads();   // bar1
        if (t < 31) issue_tile((t + 1) * 64, buf ^ 1);

        // ---- S = Q K^T, fp16 single pass ----
        const char* K = smc + (buf ? OFF_K1 : OFF_K0);
        float sf[4][4];
#pragma unroll
        for (int nf = 0; nf < 4; nf++) {
#pragma unroll
            for (int j = 0; j < 4; j++) sf[nf][j] = 0.0f;
            const char* krow = K + (32 * wc + 8 * nf + tg) * 80;
#pragma unroll
            for (int kk = 0; kk < 2; kk++) {
                int d = kk * 16 + 2 * tq;
                u32 bh0 = *(const u32*)(krow + d * 2);
                u32 bh1 = *(const u32*)(krow + (d + 8) * 2);
                mma16(sf[nf], qh[kk], bh0, bh1);
            }
        }

        // ---- row max; warp-pair exchange via named barrier ----
        float rm0 = fmaxf(fmaxf(sf[0][0], sf[0][1]), fmaxf(sf[1][0], sf[1][1]));
        rm0 = fmaxf(rm0, fmaxf(fmaxf(sf[2][0], sf[2][1]), fmaxf(sf[3][0], sf[3][1])));
        float rm1 = fmaxf(fmaxf(sf[0][2], sf[0][3]), fmaxf(sf[1][2], sf[1][3]));
        rm1 = fmaxf(rm1, fmaxf(fmaxf(sf[2][2], sf[2][3]), fmaxf(sf[3][2], sf[3][3])));
        rm0 = fmaxf(rm0, __shfl_xor_sync(0xffffffffu, rm0, 1));
        rm0 = fmaxf(rm0, __shfl_xor_sync(0xffffffffu, rm0, 2));
        rm1 = fmaxf(rm1, __shfl_xor_sync(0xffffffffu, rm1, 1));
        rm1 = fmaxf(rm1, __shfl_xor_sync(0xffffffffu, rm1, 2));
        if (tq == 0) { Rm[wc * 64 + r0] = rm0; Rm[wc * 64 + r0 + 8] = rm1; }
        asm volatile("bar.sync %0, 64;" :: "r"(wm + 1) : "memory");

        // ---- softmax ----
        const float mo0 = Mbuf[par * 64 + r0], mo1 = Mbuf[par * 64 + r0 + 8];
        const float nm0 = fmaxf(mo0, fmaxf(Rm[r0], Rm[64 + r0]));
        const float nm1 = fmaxf(mo1, fmaxf(Rm[r0 + 8], Rm[64 + r0 + 8]));
        float lp0 = 0.0f, lp1 = 0.0f;
#pragma unroll
        for (int nf = 0; nf < 4; nf++) {
            __half2 h01 = __floats2half2_rn(__expf(sf[nf][0] - nm0), __expf(sf[nf][1] - nm0));
            __half2 h23 = __floats2half2_rn(__expf(sf[nf][2] - nm1), __expf(sf[nf][3] - nm1));
            float2 f01 = __half22float2(h01), f23 = __half22float2(h23);
            lp0 += f01.x + f01.y; lp1 += f23.x + f23.y;
            const int col = 32 * wc + 8 * nf + 2 * tq;
            *(u32*)(smc + OFF_P + r0 * 144 + col * 2) = *(u32*)&h01;
            *(u32*)(smc + OFF_P + (r0 + 8) * 144 + col * 2) = *(u32*)&h23;
        }
        lp0 += __shfl_xor_sync(0xffffffffu, lp0, 1);
        lp0 += __shfl_xor_sync(0xffffffffu, lp0, 2);
        lp1 += __shfl_xor_sync(0xffffffffu, lp1, 1);
        lp1 += __shfl_xor_sync(0xffffffffu, lp1, 2);
        if (tq == 0) { Psum[wc * 64 + r0] = lp0; Psum[wc * 64 + r0 + 8] = lp1; }
        if (owner) {
            Abuf[r0] = __expf(mo0 - nm0);
            Abuf[r0 + 8] = __expf(mo1 - nm1);
            Mbuf[(par ^ 1) * 64 + r0] = nm0;
            Mbuf[(par ^ 1) * 64 + r0 + 8] = nm1;
        }
        __syncthreads();   // bar3

        if (owner) {
            Lbuf[r0]     = Lbuf[r0]     * Abuf[r0]     + Psum[r0]     + Psum[64 + r0];
            Lbuf[r0 + 8] = Lbuf[r0 + 8] * Abuf[r0 + 8] + Psum[r0 + 8] + Psum[64 + r0 + 8];
        }

        // ---- PV ----
        const char* V = smc + (buf ? OFF_V1 : OFF_V0);
#pragma unroll
        for (int mj = 0; mj < 4; mj++) {
            const float a0 = Abuf[16 * mj + tg], a1 = Abuf[16 * mj + tg + 8];
            if (__all_sync(0xffffffffu, (a0 == 1.0f) && (a1 == 1.0f))) continue;
            const u64 A0 = dup2(a0), A1 = dup2(a1);
#pragma unroll
            for (int nf = 0; nf < 4; nf++) {
                u64* pa = reinterpret_cast<u64*>(acc[mj][nf]);
                pa[0] = mul2(pa[0], A0);
                pa[1] = mul2(pa[1], A1);
            }
        }
#pragma unroll
        for (int kk = 0; kk < 4; kk++) {
            const int m = kk * 16 + 2 * tq;
            u32 af[4][4];
#pragma unroll
            for (int mj = 0; mj < 4; mj++) {
                const int rr = 16 * mj + tg;
                af[mj][0] = *(const u32*)(smc + OFF_P + rr * 144 + m * 2);
                af[mj][1] = *(const u32*)(smc + OFF_P + (rr + 8) * 144 + m * 2);
                af[mj][2] = *(const u32*)(smc + OFF_P + rr * 144 + (m + 8) * 2);
                af[mj][3] = *(const u32*)(smc + OFF_P + (rr + 8) * 144 + (m + 8) * 2);
            }
#pragma unroll
            for (int nf = 0; nf < 4; nf++) {
                const char* vrow = V + (32 * wid + 8 * nf + tg) * 144;
                u32 b0 = *(const u32*)(vrow + m * 2);
                u32 b1 = *(const u32*)(vrow + (m + 8) * 2);
#pragma unroll
                for (int mj = 0; mj < 4; mj++)
                    mma16(acc[mj][nf], af[mj], b0, b1);
            }
        }
        // no end barrier: bar1 of iteration t+1 provides the ordering
    }
    __syncthreads();

    // ---- epilogue: O/L + residual ----
#pragma unroll
    for (int mj = 0; mj < 4; mj++) {
        const int rr = 16 * mj + tg;
        const float il0 = 1.0f / Lbuf[rr];
        const float il1 = 1.0f / Lbuf[rr + 8];
#pragma unroll
        for (int nf = 0; nf < 4; nf++) {
            const int c = 32 * wid + 8 * nf + 2 * tq;
            size_t g00 = ((size_t)b * CDIM + c) * NDIM + n0 + rr;
            size_t g01 = g00 + NDIM;
            size_t g10 = g00 + 8;
            size_t g11 = g01 + 8;
            out[g00] = acc[mj][nf][0] * il0 + x[g00];
            out[g01] = acc[mj][nf][1] * il0 + x[g01];
            out[g10] = acc[mj][nf][2] * il1 + x[g10];
            out[g11] = acc[mj][nf][3] * il1 + x[g11];
        }
    }
}

extern "C" void kernel_launch(void* const* d_in, const int* in_sizes, int n_in,
                              void* d_out, int out_size) {
    const float* x    = (const float*)d_in[0];
    const float* q_w  = (const float*)d_in[1];
    const float* q_g  = (const float*)d_in[3];
    const float* q_be = (const float*)d_in[4];
    const float* k_w  = (const float*)d_in[5];
    const float* k_g  = (const float*)d_in[7];
    const float* k_be = (const float*)d_in[8];
    const float* v_w  = (const float*)d_in[9];
    const float* v_g  = (const float*)d_in[11];
    const float* v_be = (const float*)d_in[12];
    float* out = (float*)d_out;

    w16_kernel<<<OTOT, 128>>>(q_w, k_w, v_w);
    proj16_kernel<<<dim3(5, 8, 16), 256>>>(x);
    stats_fin<<<OTOT, 128>>>(q_g, q_be, k_g, k_be, v_g, v_be);
    qkt_kernel<<<dim3(32, 16), 256>>>();
    v16_kernel<<<dim3(512, 16), 256>>>();

    static int smem_set = 0;
    if (!smem_set) {
        cudaFuncSetAttribute(attn_kernel, cudaFuncAttributeMaxDynamicSharedMemorySize, SMEM_TOTAL);
        smem_set = 1;
    }
    attn_kernel<<<dim3(32, 16), 256, SMEM_TOTAL>>>(x, out);
}

// round 14
// speedup vs baseline: 5.6257x; 1.0577x over previous
#include <cuda_runtime.h>
#include <cuda_fp16.h>
#include <math.h>
#include <stdint.h>

typedef unsigned int u32;
typedef unsigned long long u64;

#define BDIM 16
#define CDIM 256
#define NDIM 2048
#define OTOT 320
#define EPSV 1e-5f

__device__ __align__(16) float g_proj[(size_t)BDIM * OTOT * NDIM];
__device__ __align__(16) u32 g_w16h[OTOT * 128];
__device__ __align__(16) __half g_q16[(size_t)BDIM * NDIM * 32];   // [b][n][32] hi only
__device__ __align__(16) __half g_k16[(size_t)BDIM * NDIM * 32];   // [b][m][32] hi only
__device__ __align__(16) __half g_v16[(size_t)BDIM * CDIM * NDIM]; // [b][c][m]
__device__ float g_ps1[OTOT * 128];
__device__ float g_ps2[OTOT * 128];
__device__ float g_scale[OTOT];
__device__ float g_shift[OTOT];

// ---------------- helpers ----------------
__device__ __forceinline__ u64 dup2(float v) {
    u64 r; asm("mov.b64 %0, {%1, %1};" : "=l"(r) : "f"(v)); return r;
}
__device__ __forceinline__ u64 mul2(u64 a, u64 b) {
    u64 r; asm("mul.rn.f32x2 %0, %1, %2;" : "=l"(r) : "l"(a), "l"(b)); return r;
}
__device__ __forceinline__ u32 smem_u32(const void* p) {
    u32 a; asm("{ .reg .u64 t; cvta.to.shared.u64 t, %1; cvt.u32.u64 %0, t; }" : "=r"(a) : "l"(p));
    return a;
}
__device__ __forceinline__ void mma16(float d[4], const u32 a[4], u32 b0, u32 b1) {
    asm volatile("mma.sync.aligned.m16n8k16.row.col.f32.f16.f16.f32 "
                 "{%0,%1,%2,%3}, {%4,%5,%6,%7}, {%8,%9}, {%0,%1,%2,%3};"
                 : "+f"(d[0]), "+f"(d[1]), "+f"(d[2]), "+f"(d[3])
                 : "r"(a[0]), "r"(a[1]), "r"(a[2]), "r"(a[3]), "r"(b0), "r"(b1));
}
#define CP16(dst, src) asm volatile("cp.async.cg.shared.global [%0], [%1], 16;" :: "r"(dst), "l"(src))
#define CP_COMMIT()    asm volatile("cp.async.commit_group;" ::: "memory")
#define CP_WAIT0()     asm volatile("cp.async.wait_group 0;" ::: "memory")

// ================= Kernel 0: W -> fp16 (hi only) =================
__global__ void __launch_bounds__(128) w16_kernel(
    const float* __restrict__ qw, const float* __restrict__ kw, const float* __restrict__ vw)
{
    const int o = blockIdx.x, t = threadIdx.x;
    const float* row = o < 32 ? qw + (size_t)o * CDIM
                     : o < 64 ? kw + (size_t)(o - 32) * CDIM
                              : vw + (size_t)(o - 64) * CDIM;
    __half2 hh = __floats2half2_rn(row[2 * t], row[2 * t + 1]);
    g_w16h[o * 128 + t] = *(u32*)&hh;
}

// ================= Kernel 1: QKV projection (fp16 mma, 1-pass: Wh*Xh) + fused stats =====
__global__ void __launch_bounds__(256) proj16_kernel(const float* __restrict__ x)
{
    __shared__ u32 xs_h[2][2048];
    __shared__ float2 sm_sp[128];
    const int tid = threadIdx.x, wid = tid >> 5, lane = tid & 31;
    const int tg = lane >> 2, tq = lane & 3;
    const int wo = wid & 3, wn = wid >> 2;
    const int ob = blockIdx.x * 64 + wo * 16;
    const int gn0 = blockIdx.y * 256, b = blockIdx.z;
    const float* xb = x + (size_t)b * CDIM * NDIM + gn0;
    const int pn = tid;

    float acc[16][4];
#pragma unroll
    for (int nf = 0; nf < 16; nf++)
#pragma unroll
        for (int j = 0; j < 4; j++) acc[nf][j] = 0.0f;

    float stg[8][2];
    auto ldg = [&](int t1) {
#pragma unroll
        for (int cp = 0; cp < 8; cp++) {
            int c = t1 * 16 + 2 * cp;
            stg[cp][0] = xb[(size_t)c * NDIM + pn];
            stg[cp][1] = xb[(size_t)(c + 1) * NDIM + pn];
        }
    };
    auto sts = [&](int buf) {
#pragma unroll
        for (int cp = 0; cp < 8; cp++) {
            __half2 hh = __floats2half2_rn(stg[cp][0], stg[cp][1]);
            xs_h[buf][cp * 256 + (pn ^ (cp << 3))] = *(u32*)&hh;
        }
    };

    ldg(0); sts(0);
    __syncthreads();

    for (int t = 0; t < 16; t++) {
        if (t < 15) ldg(t + 1);
        const int buf = t & 1;
        u32 ah[4];
        {
            size_t r = (size_t)(ob + tg) * 128 + 8 * t + tq;
            ah[0] = g_w16h[r];            ah[1] = g_w16h[r + 8 * 128];
            ah[2] = g_w16h[r + 4];        ah[3] = g_w16h[r + 8 * 128 + 4];
        }
#pragma unroll
        for (int nf = 0; nf < 16; nf++) {
            const int nl = wn * 128 + 8 * nf + tg;
            u32 bh0 = xs_h[buf][tq * 256 + (nl ^ (tq << 3))];
            u32 bh1 = xs_h[buf][(tq + 4) * 256 + (nl ^ ((tq + 4) << 3))];
            mma16(acc[nf], ah, bh0, bh1);
        }
        if (t < 15) sts((t + 1) & 1);
        __syncthreads();
    }

    // ---- store proj ----
#pragma unroll
    for (int nf = 0; nf < 16; nf++) {
        const int n = gn0 + wn * 128 + 8 * nf + 2 * tq;
        size_t base = ((size_t)b * OTOT + ob + tg) * NDIM + n;
        *reinterpret_cast<float2*>(&g_proj[base]) = make_float2(acc[nf][0], acc[nf][1]);
        *reinterpret_cast<float2*>(&g_proj[base + (size_t)8 * NDIM]) = make_float2(acc[nf][2], acc[nf][3]);
    }

    // ---- fused per-channel stats partials ----
    float s0 = 0.f, q0 = 0.f, s1 = 0.f, q1 = 0.f;
#pragma unroll
    for (int nf = 0; nf < 16; nf++) {
        s0 += acc[nf][0] + acc[nf][1];
        q0 += acc[nf][0] * acc[nf][0] + acc[nf][1] * acc[nf][1];
        s1 += acc[nf][2] + acc[nf][3];
        q1 += acc[nf][2] * acc[nf][2] + acc[nf][3] * acc[nf][3];
    }
#pragma unroll
    for (int off = 1; off < 4; off <<= 1) {
        s0 += __shfl_xor_sync(0xffffffffu, s0, off);
        q0 += __shfl_xor_sync(0xffffffffu, q0, off);
        s1 += __shfl_xor_sync(0xffffffffu, s1, off);
        q1 += __shfl_xor_sync(0xffffffffu, q1, off);
    }
    if (tq == 0) {
        sm_sp[wid * 16 + tg]     = make_float2(s0, q0);
        sm_sp[wid * 16 + 8 + tg] = make_float2(s1, q1);
    }
    __syncthreads();
    if (tid < 64) {
        int wo2 = tid >> 4, c = tid & 15;
        float2 a = sm_sp[wo2 * 16 + c];
        float2 e = sm_sp[(wo2 + 4) * 16 + c];
        int ch = blockIdx.x * 64 + wo2 * 16 + c;
        g_ps1[ch * 128 + b * 8 + blockIdx.y] = a.x + e.x;
        g_ps2[ch * 128 + b * 8 + blockIdx.y] = a.y + e.y;
    }
}

// ================= Kernel 2: finalize stats -> scale/shift =================
__global__ void __launch_bounds__(128) stats_fin(
    const float* __restrict__ qg, const float* __restrict__ qbe,
    const float* __restrict__ kg, const float* __restrict__ kbe,
    const float* __restrict__ vg, const float* __restrict__ vbe)
{
    const int ch = blockIdx.x, tid = threadIdx.x;
    __shared__ float r1[128], r2[128];
    r1[tid] = g_ps1[ch * 128 + tid];
    r2[tid] = g_ps2[ch * 128 + tid];
    __syncthreads();
    for (int off = 64; off; off >>= 1) {
        if (tid < off) { r1[tid] += r1[tid + off]; r2[tid] += r2[tid + off]; }
        __syncthreads();
    }
    if (tid == 0) {
        const float invM = 1.0f / (float)(BDIM * NDIM);
        float mean = r1[0] * invM;
        float var = r2[0] * invM - mean * mean;
        float gamma, beta;
        if (ch < 32)      { gamma = qg[ch];      beta = qbe[ch]; }
        else if (ch < 64) { gamma = kg[ch - 32]; beta = kbe[ch - 32]; }
        else              { gamma = vg[ch - 64]; beta = vbe[ch - 64]; }
        float sc = gamma * rsqrtf(var + EPSV);
        g_scale[ch] = sc;
        g_shift[ch] = beta - mean * sc;
    }
}

// ================= Kernel 3: Q/K normalize + transpose -> fp16 (hi only) =======
__global__ void __launch_bounds__(256) qkt_kernel()
{
    __shared__ float s[64][65];
    __shared__ float scl[64], shf[64];
    const int tid = threadIdx.x;
    const int n0 = blockIdx.x * 64, b = blockIdx.y;
    if (tid < 64) { scl[tid] = g_scale[tid]; shf[tid] = g_shift[tid]; }
    __syncthreads();
    for (int idx = tid; idx < 4096; idx += 256) {
        int ch = idx >> 6, nn = idx & 63;
        s[ch][nn] = g_proj[((size_t)b * OTOT + ch) * NDIM + n0 + nn] * scl[ch] + shf[ch];
    }
    __syncthreads();
    const int n = tid >> 2, d0 = (tid & 3) * 8;
    const size_t row = ((size_t)b * NDIM + n0 + n) * 32;
#pragma unroll
    for (int qk = 0; qk < 2; qk++) {
        __half* dst = (qk ? g_k16 : g_q16) + row;
        u32 wh[4];
#pragma unroll
        for (int j = 0; j < 4; j++) {
            __half2 hh = __floats2half2_rn(s[qk * 32 + d0 + 2 * j][n],
                                           s[qk * 32 + d0 + 2 * j + 1][n]);
            wh[j] = *(u32*)&hh;
        }
        *reinterpret_cast<uint4*>(dst + d0) = make_uint4(wh[0], wh[1], wh[2], wh[3]);
    }
}

// ================= Kernel 4: V normalize + leaky -> fp16 =================
__global__ void __launch_bounds__(256) v16_kernel()
{
    const int b = blockIdx.y, tid = threadIdx.x;
    const int c = blockIdx.x >> 1;
    const float sc = g_scale[64 + c], sh = g_shift[64 + c];
    const int i4 = blockIdx.x * 256 + tid;
    const int n = (i4 * 4) & 2047;
    float4 v = *reinterpret_cast<const float4*>(&g_proj[((size_t)b * OTOT + 64 + c) * NDIM + n]);
    float a0 = v.x * sc + sh, a1 = v.y * sc + sh, a2 = v.z * sc + sh, a3 = v.w * sc + sh;
    a0 = a0 > 0.f ? a0 : 0.2f * a0; a1 = a1 > 0.f ? a1 : 0.2f * a1;
    a2 = a2 > 0.f ? a2 : 0.2f * a2; a3 = a3 > 0.f ? a3 : 0.2f * a3;
    __half2 p0 = __floats2half2_rn(a0, a1), p1 = __floats2half2_rn(a2, a3);
    uint2 w = make_uint2(*(u32*)&p0, *(u32*)&p1);
    *reinterpret_cast<uint2*>(&g_v16[((size_t)b * CDIM + c) * NDIM + n]) = w;
}

// ================= Kernel 5: fp16 mma flash attention (1-pass S) =====
#define OFF_K0 0
#define OFF_K1 5120
#define OFF_V0 10240
#define OFF_V1 47104
#define OFF_P  83968
#define OFF_M  93184
#define OFF_L  93696
#define OFF_A  93952
#define OFF_RM 94208
#define OFF_PS 94720
#define SMEM_TOTAL 95232

__global__ void __launch_bounds__(256, 2) attn_kernel(
    const float* __restrict__ x, float* __restrict__ out)
{
    extern __shared__ __align__(16) char smc[];
    const u32 sb = smem_u32(smc);
    float* Mbuf = (float*)(smc + OFF_M);
    float* Lbuf = (float*)(smc + OFF_L);
    float* Abuf = (float*)(smc + OFF_A);
    float* Rm   = (float*)(smc + OFF_RM);
    float* Psum = (float*)(smc + OFF_PS);

    const int tid = threadIdx.x, wid = tid >> 5, lane = tid & 31;
    const int wm = wid & 3, wc = wid >> 2;
    const int tg = lane >> 2, tq = lane & 3;
    const int n0 = blockIdx.x * 64, b = blockIdx.y;
    const int r0 = 16 * wm + tg;
    const bool owner = (wc == 0 && tq == 0);

    if (tid < 64) { Mbuf[tid] = -INFINITY; Lbuf[tid] = 0.0f; }

    u32 qh[2][4];
    {
        const __half* Qg = g_q16 + ((size_t)b * NDIM + n0) * 32;
#pragma unroll
        for (int kk = 0; kk < 2; kk++) {
            int d = kk * 16 + 2 * tq;
            qh[kk][0] = *(const u32*)(Qg + (size_t)r0 * 32 + d);
            qh[kk][1] = *(const u32*)(Qg + (size_t)(r0 + 8) * 32 + d);
            qh[kk][2] = *(const u32*)(Qg + (size_t)r0 * 32 + d + 8);
            qh[kk][3] = *(const u32*)(Qg + (size_t)(r0 + 8) * 32 + d + 8);
        }
    }

    float acc[4][4][4];
#pragma unroll
    for (int mj = 0; mj < 4; mj++)
#pragma unroll
        for (int nf = 0; nf < 4; nf++)
#pragma unroll
            for (int j = 0; j < 4; j++) acc[mj][nf][j] = 0.0f;

    auto issue_tile = [&](int m0, int bf) {
        u32 kb = sb + (bf ? OFF_K1 : OFF_K0);
        u32 vb = sb + (bf ? OFF_V1 : OFF_V0);
        const __half* Kg = g_k16 + ((size_t)b * NDIM + m0) * 32;
        const __half* Vg = g_v16 + (size_t)b * CDIM * NDIM + m0;
#pragma unroll
        for (int i = 0; i < 9; i++) {
            int id = tid + i * 256;
            if (id < 256) {
                int m = id >> 2, ch = id & 3;
                CP16(kb + m * 80 + ch * 16, Kg + (size_t)m * 32 + ch * 8);
            } else {
                int j = id - 256, c = j >> 3, ch = j & 7;
                CP16(vb + c * 144 + ch * 16, Vg + (size_t)c * NDIM + ch * 8);
            }
        }
        CP_COMMIT();
    };

    issue_tile(0, 0);

    for (int t = 0; t < 32; t++) {
        const int buf = t & 1, par = t & 1;
        CP_WAIT0();
        __syncthreads();   // bar1
        if (t < 31) issue_tile((t + 1) * 64, buf ^ 1);

        // ---- S = Q K^T, fp16 single pass ----
        const char* K = smc + (buf ? OFF_K1 : OFF_K0);
        float sf[4][4];
#pragma unroll
        for (int nf = 0; nf < 4; nf++) {
#pragma unroll
            for (int j = 0; j < 4; j++) sf[nf][j] = 0.0f;
            const char* krow = K + (32 * wc + 8 * nf + tg) * 80;
#pragma unroll
            for (int kk = 0; kk < 2; kk++) {
                int d = kk * 16 + 2 * tq;
                u32 bh0 = *(const u32*)(krow + d * 2);
                u32 bh1 = *(const u32*)(krow + (d + 8) * 2);
                mma16(sf[nf], qh[kk], bh0, bh1);
            }
        }

        // ---- row max; warp-pair exchange via named barrier ----
        float rm0 = fmaxf(fmaxf(sf[0][0], sf[0][1]), fmaxf(sf[1][0], sf[1][1]));
        rm0 = fmaxf(rm0, fmaxf(fmaxf(sf[2][0], sf[2][1]), fmaxf(sf[3][0], sf[3][1])));
        float rm1 = fmaxf(fmaxf(sf[0][2], sf[0][3]), fmaxf(sf[1][2], sf[1][3]));
        rm1 = fmaxf(rm1, fmaxf(fmaxf(sf[2][2], sf[2][3]), fmaxf(sf[3][2], sf[3][3])));
        rm0 = fmaxf(rm0, __shfl_xor_sync(0xffffffffu, rm0, 1));
        rm0 = fmaxf(rm0, __shfl_xor_sync(0xffffffffu, rm0, 2));
        rm1 = fmaxf(rm1, __shfl_xor_sync(0xffffffffu, rm1, 1));
        rm1 = fmaxf(rm1, __shfl_xor_sync(0xffffffffu, rm1, 2));
        if (tq == 0) { Rm[wc * 64 + r0] = rm0; Rm[wc * 64 + r0 + 8] = rm1; }
        asm volatile("bar.sync %0, 64;" :: "r"(wm + 1) : "memory");

        // ---- softmax ----
        const float mo0 = Mbuf[par * 64 + r0], mo1 = Mbuf[par * 64 + r0 + 8];
        const float nm0 = fmaxf(mo0, fmaxf(Rm[r0], Rm[64 + r0]));
        const float nm1 = fmaxf(mo1, fmaxf(Rm[r0 + 8], Rm[64 + r0 + 8]));
        float lp0 = 0.0f, lp1 = 0.0f;
#pragma unroll
        for (int nf = 0; nf < 4; nf++) {
            __half2 h01 = __floats2half2_rn(__expf(sf[nf][0] - nm0), __expf(sf[nf][1] - nm0));
            __half2 h23 = __floats2half2_rn(__expf(sf[nf][2] - nm1), __expf(sf[nf][3] - nm1));
            float2 f01 = __half22float2(h01), f23 = __half22float2(h23);
            lp0 += f01.x + f01.y; lp1 += f23.x + f23.y;
            const int col = 32 * wc + 8 * nf + 2 * tq;
            *(u32*)(smc + OFF_P + r0 * 144 + col * 2) = *(u32*)&h01;
            *(u32*)(smc + OFF_P + (r0 + 8) * 144 + col * 2) = *(u32*)&h23;
        }
        lp0 += __shfl_xor_sync(0xffffffffu, lp0, 1);
        lp0 += __shfl_xor_sync(0xffffffffu, lp0, 2);
        lp1 += __shfl_xor_sync(0xffffffffu, lp1, 1);
        lp1 += __shfl_xor_sync(0xffffffffu, lp1, 2);
        if (tq == 0) { Psum[wc * 64 + r0] = lp0; Psum[wc * 64 + r0 + 8] = lp1; }
        if (owner) {
            Abuf[r0] = __expf(mo0 - nm0);
            Abuf[r0 + 8] = __expf(mo1 - nm1);
            Mbuf[(par ^ 1) * 64 + r0] = nm0;
            Mbuf[(par ^ 1) * 64 + r0 + 8] = nm1;
        }
        __syncthreads();   // bar3

        if (owner) {
            Lbuf[r0]     = Lbuf[r0]     * Abuf[r0]     + Psum[r0]     + Psum[64 + r0];
            Lbuf[r0 + 8] = Lbuf[r0 + 8] * Abuf[r0 + 8] + Psum[r0 + 8] + Psum[64 + r0 + 8];
        }

        // ---- PV ----
        const char* V = smc + (buf ? OFF_V1 : OFF_V0);
#pragma unroll
        for (int mj = 0; mj < 4; mj++) {
            const float a0 = Abuf[16 * mj + tg], a1 = Abuf[16 * mj + tg + 8];
            if (__all_sync(0xffffffffu, (a0 == 1.0f) && (a1 == 1.0f))) continue;
            const u64 A0 = dup2(a0), A1 = dup2(a1);
#pragma unroll
            for (int nf = 0; nf < 4; nf++) {
                u64* pa = reinterpret_cast<u64*>(acc[mj][nf]);
                pa[0] = mul2(pa[0], A0);
                pa[1] = mul2(pa[1], A1);
            }
        }
#pragma unroll
        for (int kk = 0; kk < 4; kk++) {
            const int m = kk * 16 + 2 * tq;
            u32 af[4][4];
#pragma unroll
            for (int mj = 0; mj < 4; mj++) {
                const int rr = 16 * mj + tg;
                af[mj][0] = *(const u32*)(smc + OFF_P + rr * 144 + m * 2);
                af[mj][1] = *(const u32*)(smc + OFF_P + (rr + 8) * 144 + m * 2);
                af[mj][2] = *(const u32*)(smc + OFF_P + rr * 144 + (m + 8) * 2);
                af[mj][3] = *(const u32*)(smc + OFF_P + (rr + 8) * 144 + (m + 8) * 2);
            }
#pragma unroll
            for (int nf = 0; nf < 4; nf++) {
                const char* vrow = V + (32 * wid + 8 * nf + tg) * 144;
                u32 b0 = *(const u32*)(vrow + m * 2);
                u32 b1 = *(const u32*)(vrow + (m + 8) * 2);
#pragma unroll
                for (int mj = 0; mj < 4; mj++)
                    mma16(acc[mj][nf], af[mj], b0, b1);
            }
        }
        // no end barrier: bar1 of iteration t+1 provides the ordering
    }
    __syncthreads();

    // ---- epilogue: O/L + residual ----
#pragma unroll
    for (int mj = 0; mj < 4; mj++) {
        const int rr = 16 * mj + tg;
        const float il0 = 1.0f / Lbuf[rr];
        const float il1 = 1.0f / Lbuf[rr + 8];
#pragma unroll
        for (int nf = 0; nf < 4; nf++) {
            const int c = 32 * wid + 8 * nf + 2 * tq;
            size_t g00 = ((size_t)b * CDIM + c) * NDIM + n0 + rr;
            size_t g01 = g00 + NDIM;
            size_t g10 = g00 + 8;
            size_t g11 = g01 + 8;
            out[g00] = acc[mj][nf][0] * il0 + x[g00];
            out[g01] = acc[mj][nf][1] * il0 + x[g01];
            out[g10] = acc[mj][nf][2] * il1 + x[g10];
            out[g11] = acc[mj][nf][3] * il1 + x[g11];
        }
    }
}

extern "C" void kernel_launch(void* const* d_in, const int* in_sizes, int n_in,
                              void* d_out, int out_size) {
    const float* x    = (const float*)d_in[0];
    const float* q_w  = (const float*)d_in[1];
    const float* q_g  = (const float*)d_in[3];
    const float* q_be = (const float*)d_in[4];
    const float* k_w  = (const float*)d_in[5];
    const float* k_g  = (const float*)d_in[7];
    const float* k_be = (const float*)d_in[8];
    const float* v_w  = (const float*)d_in[9];
    const float* v_g  = (const float*)d_in[11];
    const float* v_be = (const float*)d_in[12];
    float* out = (float*)d_out;

    w16_kernel<<<OTOT, 128>>>(q_w, k_w, v_w);
    proj16_kernel<<<dim3(5, 8, 16), 256>>>(x);
    stats_fin<<<OTOT, 128>>>(q_g, q_be, k_g, k_be, v_g, v_be);
    qkt_kernel<<<dim3(32, 16), 256>>>();
    v16_kernel<<<dim3(512, 16), 256>>>();

    static int smem_set = 0;
    if (!smem_set) {
        cudaFuncSetAttribute(attn_kernel, cudaFuncAttributeMaxDynamicSharedMemorySize, SMEM_TOTAL);
        smem_set = 1;
    }
    attn_kernel<<<dim3(32, 16), 256, SMEM_TOTAL>>>(x, out);
}

// round 15
// speedup vs baseline: 5.6997x; 1.0131x over previous
#include <cuda_runtime.h>
#include <cuda_fp16.h>
#include <math.h>
#include <stdint.h>

typedef unsigned int u32;
typedef unsigned long long u64;

#define BDIM 16
#define CDIM 256
#define NDIM 2048
#define OTOT 320
#define EPSV 1e-5f
#define LOG2E 1.4426950408889634f

__device__ __align__(16) float g_proj[(size_t)BDIM * 64 * NDIM];   // Q/K channels only
__device__ __align__(16) u32 g_w16h[OTOT * 128];
__device__ __align__(16) __half g_q16[(size_t)BDIM * NDIM * 32];   // [b][n][32] hi only
__device__ __align__(16) __half g_k16[(size_t)BDIM * NDIM * 32];   // [b][m][32] hi only
__device__ __align__(16) __half g_v16[(size_t)BDIM * CDIM * NDIM]; // [b][c][m] raw->normalized
__device__ float g_ps1[OTOT * 128];
__device__ float g_ps2[OTOT * 128];
__device__ float g_scale[OTOT];
__device__ float g_shift[OTOT];

// ---------------- helpers ----------------
__device__ __forceinline__ u64 dup2(float v) {
    u64 r; asm("mov.b64 %0, {%1, %1};" : "=l"(r) : "f"(v)); return r;
}
__device__ __forceinline__ u64 mul2(u64 a, u64 b) {
    u64 r; asm("mul.rn.f32x2 %0, %1, %2;" : "=l"(r) : "l"(a), "l"(b)); return r;
}
__device__ __forceinline__ float ex2(float x) {
    float r; asm("ex2.approx.f32 %0, %1;" : "=f"(r) : "f"(x)); return r;
}
__device__ __forceinline__ u32 smem_u32(const void* p) {
    u32 a; asm("{ .reg .u64 t; cvta.to.shared.u64 t, %1; cvt.u32.u64 %0, t; }" : "=r"(a) : "l"(p));
    return a;
}
__device__ __forceinline__ void mma16(float d[4], const u32 a[4], u32 b0, u32 b1) {
    asm volatile("mma.sync.aligned.m16n8k16.row.col.f32.f16.f16.f32 "
                 "{%0,%1,%2,%3}, {%4,%5,%6,%7}, {%8,%9}, {%0,%1,%2,%3};"
                 : "+f"(d[0]), "+f"(d[1]), "+f"(d[2]), "+f"(d[3])
                 : "r"(a[0]), "r"(a[1]), "r"(a[2]), "r"(a[3]), "r"(b0), "r"(b1));
}
#define CP16(dst, src) asm volatile("cp.async.cg.shared.global [%0], [%1], 16;" :: "r"(dst), "l"(src))
#define CP_COMMIT()    asm volatile("cp.async.commit_group;" ::: "memory")
#define CP_WAIT0()     asm volatile("cp.async.wait_group 0;" ::: "memory")

// ================= Kernel 0: W -> fp16 (hi only) =================
__global__ void __launch_bounds__(128) w16_kernel(
    const float* __restrict__ qw, const float* __restrict__ kw, const float* __restrict__ vw)
{
    const int o = blockIdx.x, t = threadIdx.x;
    const float* row = o < 32 ? qw + (size_t)o * CDIM
                     : o < 64 ? kw + (size_t)(o - 32) * CDIM
                              : vw + (size_t)(o - 64) * CDIM;
    __half2 hh = __floats2half2_rn(row[2 * t], row[2 * t + 1]);
    g_w16h[o * 128 + t] = *(u32*)&hh;
}

// ================= Kernel 1: QKV projection (fp16 mma, 1-pass) + fused stats =====
// blockIdx.x==0: Q/K channels -> fp32 g_proj. blockIdx.x>=1: V -> raw fp16 g_v16.
__global__ void __launch_bounds__(256) proj16_kernel(const float* __restrict__ x)
{
    __shared__ u32 xs_h[2][2048];
    __shared__ float2 sm_sp[128];
    const int tid = threadIdx.x, wid = tid >> 5, lane = tid & 31;
    const int tg = lane >> 2, tq = lane & 3;
    const int wo = wid & 3, wn = wid >> 2;
    const int ob = blockIdx.x * 64 + wo * 16;
    const int gn0 = blockIdx.y * 256, b = blockIdx.z;
    const float* xb = x + (size_t)b * CDIM * NDIM + gn0;
    const int pn = tid;

    float acc[16][4];
#pragma unroll
    for (int nf = 0; nf < 16; nf++)
#pragma unroll
        for (int j = 0; j < 4; j++) acc[nf][j] = 0.0f;

    float stg[8][2];
    auto ldg = [&](int t1) {
#pragma unroll
        for (int cp = 0; cp < 8; cp++) {
            int c = t1 * 16 + 2 * cp;
            stg[cp][0] = xb[(size_t)c * NDIM + pn];
            stg[cp][1] = xb[(size_t)(c + 1) * NDIM + pn];
        }
    };
    auto sts = [&](int buf) {
#pragma unroll
        for (int cp = 0; cp < 8; cp++) {
            __half2 hh = __floats2half2_rn(stg[cp][0], stg[cp][1]);
            xs_h[buf][cp * 256 + (pn ^ (cp << 3))] = *(u32*)&hh;
        }
    };

    ldg(0); sts(0);
    __syncthreads();

    for (int t = 0; t < 16; t++) {
        if (t < 15) ldg(t + 1);
        const int buf = t & 1;
        u32 ah[4];
        {
            size_t r = (size_t)(ob + tg) * 128 + 8 * t + tq;
            ah[0] = g_w16h[r];            ah[1] = g_w16h[r + 8 * 128];
            ah[2] = g_w16h[r + 4];        ah[3] = g_w16h[r + 8 * 128 + 4];
        }
#pragma unroll
        for (int nf = 0; nf < 16; nf++) {
            const int nl = wn * 128 + 8 * nf + tg;
            u32 bh0 = xs_h[buf][tq * 256 + (nl ^ (tq << 3))];
            u32 bh1 = xs_h[buf][(tq + 4) * 256 + (nl ^ ((tq + 4) << 3))];
            mma16(acc[nf], ah, bh0, bh1);
        }
        if (t < 15) sts((t + 1) & 1);
        __syncthreads();
    }

    // ---- store: Q/K (block 0) -> fp32 g_proj; V -> raw fp16 g_v16 ----
    if (blockIdx.x == 0) {
#pragma unroll
        for (int nf = 0; nf < 16; nf++) {
            const int n = gn0 + wn * 128 + 8 * nf + 2 * tq;
            size_t base = ((size_t)b * 64 + ob + tg) * NDIM + n;
            *reinterpret_cast<float2*>(&g_proj[base]) = make_float2(acc[nf][0], acc[nf][1]);
            *reinterpret_cast<float2*>(&g_proj[base + (size_t)8 * NDIM]) = make_float2(acc[nf][2], acc[nf][3]);
        }
    } else {
        const int cb = ob - 64;   // V channel base
#pragma unroll
        for (int nf = 0; nf < 16; nf++) {
            const int n = gn0 + wn * 128 + 8 * nf + 2 * tq;
            size_t base = ((size_t)b * CDIM + cb + tg) * NDIM + n;
            __half2 h0 = __floats2half2_rn(acc[nf][0], acc[nf][1]);
            __half2 h1 = __floats2half2_rn(acc[nf][2], acc[nf][3]);
            *reinterpret_cast<u32*>(&g_v16[base]) = *(u32*)&h0;
            *reinterpret_cast<u32*>(&g_v16[base + (size_t)8 * NDIM]) = *(u32*)&h1;
        }
    }

    // ---- fused per-channel stats partials ----
    float s0 = 0.f, q0 = 0.f, s1 = 0.f, q1 = 0.f;
#pragma unroll
    for (int nf = 0; nf < 16; nf++) {
        s0 += acc[nf][0] + acc[nf][1];
        q0 += acc[nf][0] * acc[nf][0] + acc[nf][1] * acc[nf][1];
        s1 += acc[nf][2] + acc[nf][3];
        q1 += acc[nf][2] * acc[nf][2] + acc[nf][3] * acc[nf][3];
    }
#pragma unroll
    for (int off = 1; off < 4; off <<= 1) {
        s0 += __shfl_xor_sync(0xffffffffu, s0, off);
        q0 += __shfl_xor_sync(0xffffffffu, q0, off);
        s1 += __shfl_xor_sync(0xffffffffu, s1, off);
        q1 += __shfl_xor_sync(0xffffffffu, q1, off);
    }
    if (tq == 0) {
        sm_sp[wid * 16 + tg]     = make_float2(s0, q0);
        sm_sp[wid * 16 + 8 + tg] = make_float2(s1, q1);
    }
    __syncthreads();
    if (tid < 64) {
        int wo2 = tid >> 4, c = tid & 15;
        float2 a = sm_sp[wo2 * 16 + c];
        float2 e = sm_sp[(wo2 + 4) * 16 + c];
        int ch = blockIdx.x * 64 + wo2 * 16 + c;
        g_ps1[ch * 128 + b * 8 + blockIdx.y] = a.x + e.x;
        g_ps2[ch * 128 + b * 8 + blockIdx.y] = a.y + e.y;
    }
}

// ================= Kernel 2: finalize stats -> scale/shift =================
__global__ void __launch_bounds__(128) stats_fin(
    const float* __restrict__ qg, const float* __restrict__ qbe,
    const float* __restrict__ kg, const float* __restrict__ kbe,
    const float* __restrict__ vg, const float* __restrict__ vbe)
{
    const int ch = blockIdx.x, tid = threadIdx.x;
    __shared__ float r1[128], r2[128];
    r1[tid] = g_ps1[ch * 128 + tid];
    r2[tid] = g_ps2[ch * 128 + tid];
    __syncthreads();
    for (int off = 64; off; off >>= 1) {
        if (tid < off) { r1[tid] += r1[tid + off]; r2[tid] += r2[tid + off]; }
        __syncthreads();
    }
    if (tid == 0) {
        const float invM = 1.0f / (float)(BDIM * NDIM);
        float mean = r1[0] * invM;
        float var = r2[0] * invM - mean * mean;
        float gamma, beta;
        if (ch < 32)      { gamma = qg[ch];      beta = qbe[ch]; }
        else if (ch < 64) { gamma = kg[ch - 32]; beta = kbe[ch - 32]; }
        else              { gamma = vg[ch - 64]; beta = vbe[ch - 64]; }
        float sc = gamma * rsqrtf(var + EPSV);
        g_scale[ch] = sc;
        g_shift[ch] = beta - mean * sc;
    }
}

// ================= Kernel 3: Q/K normalize + transpose -> fp16; Q pre-scaled by log2e =======
__global__ void __launch_bounds__(256) qkt_kernel()
{
    __shared__ float s[64][65];
    __shared__ float scl[64], shf[64];
    const int tid = threadIdx.x;
    const int n0 = blockIdx.x * 64, b = blockIdx.y;
    if (tid < 64) {
        float f = (tid < 32) ? LOG2E : 1.0f;   // fold log2e into Q so softmax uses ex2
        scl[tid] = g_scale[tid] * f;
        shf[tid] = g_shift[tid] * f;
    }
    __syncthreads();
    for (int idx = tid; idx < 4096; idx += 256) {
        int ch = idx >> 6, nn = idx & 63;
        s[ch][nn] = g_proj[((size_t)b * 64 + ch) * NDIM + n0 + nn] * scl[ch] + shf[ch];
    }
    __syncthreads();
    const int n = tid >> 2, d0 = (tid & 3) * 8;
    const size_t row = ((size_t)b * NDIM + n0 + n) * 32;
#pragma unroll
    for (int qk = 0; qk < 2; qk++) {
        __half* dst = (qk ? g_k16 : g_q16) + row;
        u32 wh[4];
#pragma unroll
        for (int j = 0; j < 4; j++) {
            __half2 hh = __floats2half2_rn(s[qk * 32 + d0 + 2 * j][n],
                                           s[qk * 32 + d0 + 2 * j + 1][n]);
            wh[j] = *(u32*)&hh;
        }
        *reinterpret_cast<uint4*>(dst + d0) = make_uint4(wh[0], wh[1], wh[2], wh[3]);
    }
}

// ================= Kernel 4: V in-place normalize + leaky (fp16) =================
__global__ void __launch_bounds__(256) v16_kernel()
{
    const int b = blockIdx.y, tid = threadIdx.x;
    const int i4 = blockIdx.x * 256 + tid;
    const int off = i4 * 4;                 // half index within batch V
    const int c = off >> 11, n = off & 2047;
    const float sc = g_scale[64 + c], sh = g_shift[64 + c];
    __half* p = &g_v16[((size_t)b * CDIM + c) * NDIM + n];
    uint2 w = *reinterpret_cast<const uint2*>(p);
    __half2 h0 = *(__half2*)&w.x, h1 = *(__half2*)&w.y;
    float2 f0 = __half22float2(h0), f1 = __half22float2(h1);
    float a0 = f0.x * sc + sh, a1 = f0.y * sc + sh;
    float a2 = f1.x * sc + sh, a3 = f1.y * sc + sh;
    a0 = a0 > 0.f ? a0 : 0.2f * a0; a1 = a1 > 0.f ? a1 : 0.2f * a1;
    a2 = a2 > 0.f ? a2 : 0.2f * a2; a3 = a3 > 0.f ? a3 : 0.2f * a3;
    __half2 p0 = __floats2half2_rn(a0, a1), p1 = __floats2half2_rn(a2, a3);
    *reinterpret_cast<uint2*>(p) = make_uint2(*(u32*)&p0, *(u32*)&p1);
}

// ================= Kernel 5: fp16 mma flash attention (1-pass S, base-2 softmax) =====
#define OFF_K0 0
#define OFF_K1 5120
#define OFF_V0 10240
#define OFF_V1 47104
#define OFF_P  83968
#define OFF_M  93184
#define OFF_L  93696
#define OFF_A  93952
#define OFF_RM 94208
#define OFF_PS 94720
#define SMEM_TOTAL 95232

__global__ void __launch_bounds__(256, 2) attn_kernel(
    const float* __restrict__ x, float* __restrict__ out)
{
    extern __shared__ __align__(16) char smc[];
    const u32 sb = smem_u32(smc);
    float* Mbuf = (float*)(smc + OFF_M);
    float* Lbuf = (float*)(smc + OFF_L);
    float* Abuf = (float*)(smc + OFF_A);
    float* Rm   = (float*)(smc + OFF_RM);
    float* Psum = (float*)(smc + OFF_PS);

    const int tid = threadIdx.x, wid = tid >> 5, lane = tid & 31;
    const int wm = wid & 3, wc = wid >> 2;
    const int tg = lane >> 2, tq = lane & 3;
    const int n0 = blockIdx.x * 64, b = blockIdx.y;
    const int r0 = 16 * wm + tg;
    const bool owner = (wc == 0 && tq == 0);

    if (tid < 64) { Mbuf[tid] = -INFINITY; Lbuf[tid] = 0.0f; }

    u32 qh[2][4];
    {
        const __half* Qg = g_q16 + ((size_t)b * NDIM + n0) * 32;
#pragma unroll
        for (int kk = 0; kk < 2; kk++) {
            int d = kk * 16 + 2 * tq;
            qh[kk][0] = *(const u32*)(Qg + (size_t)r0 * 32 + d);
            qh[kk][1] = *(const u32*)(Qg + (size_t)(r0 + 8) * 32 + d);
            qh[kk][2] = *(const u32*)(Qg + (size_t)r0 * 32 + d + 8);
            qh[kk][3] = *(const u32*)(Qg + (size_t)(r0 + 8) * 32 + d + 8);
        }
    }

    float acc[4][4][4];
#pragma unroll
    for (int mj = 0; mj < 4; mj++)
#pragma unroll
        for (int nf = 0; nf < 4; nf++)
#pragma unroll
            for (int j = 0; j < 4; j++) acc[mj][nf][j] = 0.0f;

    auto issue_tile = [&](int m0, int bf) {
        u32 kb = sb + (bf ? OFF_K1 : OFF_K0);
        u32 vb = sb + (bf ? OFF_V1 : OFF_V0);
        const __half* Kg = g_k16 + ((size_t)b * NDIM + m0) * 32;
        const __half* Vg = g_v16 + (size_t)b * CDIM * NDIM + m0;
#pragma unroll
        for (int i = 0; i < 9; i++) {
            int id = tid + i * 256;
            if (id < 256) {
                int m = id >> 2, ch = id & 3;
                CP16(kb + m * 80 + ch * 16, Kg + (size_t)m * 32 + ch * 8);
            } else {
                int j = id - 256, c = j >> 3, ch = j & 7;
                CP16(vb + c * 144 + ch * 16, Vg + (size_t)c * NDIM + ch * 8);
            }
        }
        CP_COMMIT();
    };

    issue_tile(0, 0);

    for (int t = 0; t < 32; t++) {
        const int buf = t & 1, par = t & 1;
        CP_WAIT0();
        __syncthreads();   // bar1
        if (t < 31) issue_tile((t + 1) * 64, buf ^ 1);

        // ---- S = Q K^T (S already in base-2 units) ----
        const char* K = smc + (buf ? OFF_K1 : OFF_K0);
        float sf[4][4];
#pragma unroll
        for (int nf = 0; nf < 4; nf++) {
#pragma unroll
            for (int j = 0; j < 4; j++) sf[nf][j] = 0.0f;
            const char* krow = K + (32 * wc + 8 * nf + tg) * 80;
#pragma unroll
            for (int kk = 0; kk < 2; kk++) {
                int d = kk * 16 + 2 * tq;
                u32 bh0 = *(const u32*)(krow + d * 2);
                u32 bh1 = *(const u32*)(krow + (d + 8) * 2);
                mma16(sf[nf], qh[kk], bh0, bh1);
            }
        }

        // ---- row max; warp-pair exchange via named barrier ----
        float rm0 = fmaxf(fmaxf(sf[0][0], sf[0][1]), fmaxf(sf[1][0], sf[1][1]));
        rm0 = fmaxf(rm0, fmaxf(fmaxf(sf[2][0], sf[2][1]), fmaxf(sf[3][0], sf[3][1])));
        float rm1 = fmaxf(fmaxf(sf[0][2], sf[0][3]), fmaxf(sf[1][2], sf[1][3]));
        rm1 = fmaxf(rm1, fmaxf(fmaxf(sf[2][2], sf[2][3]), fmaxf(sf[3][2], sf[3][3])));
        rm0 = fmaxf(rm0, __shfl_xor_sync(0xffffffffu, rm0, 1));
        rm0 = fmaxf(rm0, __shfl_xor_sync(0xffffffffu, rm0, 2));
        rm1 = fmaxf(rm1, __shfl_xor_sync(0xffffffffu, rm1, 1));
        rm1 = fmaxf(rm1, __shfl_xor_sync(0xffffffffu, rm1, 2));
        if (tq == 0) { Rm[wc * 64 + r0] = rm0; Rm[wc * 64 + r0 + 8] = rm1; }
        asm volatile("bar.sync %0, 64;" :: "r"(wm + 1) : "memory");

        // ---- softmax: p = 2^(s - m) ----
        const float mo0 = Mbuf[par * 64 + r0], mo1 = Mbuf[par * 64 + r0 + 8];
        const float nm0 = fmaxf(mo0, fmaxf(Rm[r0], Rm[64 + r0]));
        const float nm1 = fmaxf(mo1, fmaxf(Rm[r0 + 8], Rm[64 + r0 + 8]));
        float lp0 = 0.0f, lp1 = 0.0f;
#pragma unroll
        for (int nf = 0; nf < 4; nf++) {
            __half2 h01 = __floats2half2_rn(ex2(sf[nf][0] - nm0), ex2(sf[nf][1] - nm0));
            __half2 h23 = __floats2half2_rn(ex2(sf[nf][2] - nm1), ex2(sf[nf][3] - nm1));
            float2 f01 = __half22float2(h01), f23 = __half22float2(h23);
            lp0 += f01.x + f01.y; lp1 += f23.x + f23.y;
            const int col = 32 * wc + 8 * nf + 2 * tq;
            *(u32*)(smc + OFF_P + r0 * 144 + col * 2) = *(u32*)&h01;
            *(u32*)(smc + OFF_P + (r0 + 8) * 144 + col * 2) = *(u32*)&h23;
        }
        lp0 += __shfl_xor_sync(0xffffffffu, lp0, 1);
        lp0 += __shfl_xor_sync(0xffffffffu, lp0, 2);
        lp1 += __shfl_xor_sync(0xffffffffu, lp1, 1);
        lp1 += __shfl_xor_sync(0xffffffffu, lp1, 2);
        if (tq == 0) { Psum[wc * 64 + r0] = lp0; Psum[wc * 64 + r0 + 8] = lp1; }
        if (owner) {
            Abuf[r0] = ex2(mo0 - nm0);
            Abuf[r0 + 8] = ex2(mo1 - nm1);
            Mbuf[(par ^ 1) * 64 + r0] = nm0;
            Mbuf[(par ^ 1) * 64 + r0 + 8] = nm1;
        }
        __syncthreads();   // bar3

        if (owner) {
            Lbuf[r0]     = Lbuf[r0]     * Abuf[r0]     + Psum[r0]     + Psum[64 + r0];
            Lbuf[r0 + 8] = Lbuf[r0 + 8] * Abuf[r0 + 8] + Psum[r0 + 8] + Psum[64 + r0 + 8];
        }

        // ---- PV ----
        const char* V = smc + (buf ? OFF_V1 : OFF_V0);
#pragma unroll
        for (int mj = 0; mj < 4; mj++) {
            const float a0 = Abuf[16 * mj + tg], a1 = Abuf[16 * mj + tg + 8];
            if (__all_sync(0xffffffffu, (a0 == 1.0f) && (a1 == 1.0f))) continue;
            const u64 A0 = dup2(a0), A1 = dup2(a1);
#pragma unroll
            for (int nf = 0; nf < 4; nf++) {
                u64* pa = reinterpret_cast<u64*>(acc[mj][nf]);
                pa[0] = mul2(pa[0], A0);
                pa[1] = mul2(pa[1], A1);
            }
        }
#pragma unroll
        for (int kk = 0; kk < 4; kk++) {
            const int m = kk * 16 + 2 * tq;
            u32 af[4][4];
#pragma unroll
            for (int mj = 0; mj < 4; mj++) {
                const int rr = 16 * mj + tg;
                af[mj][0] = *(const u32*)(smc + OFF_P + rr * 144 + m * 2);
                af[mj][1] = *(const u32*)(smc + OFF_P + (rr + 8) * 144 + m * 2);
                af[mj][2] = *(const u32*)(smc + OFF_P + rr * 144 + (m + 8) * 2);
                af[mj][3] = *(const u32*)(smc + OFF_P + (rr + 8) * 144 + (m + 8) * 2);
            }
#pragma unroll
            for (int nf = 0; nf < 4; nf++) {
                const char* vrow = V + (32 * wid + 8 * nf + tg) * 144;
                u32 b0 = *(const u32*)(vrow + m * 2);
                u32 b1 = *(const u32*)(vrow + (m + 8) * 2);
#pragma unroll
                for (int mj = 0; mj < 4; mj++)
                    mma16(acc[mj][nf], af[mj], b0, b1);
            }
        }
        // no end barrier: bar1 of iteration t+1 provides the ordering
    }
    __syncthreads();

    // ---- epilogue: O/L + residual ----
#pragma unroll
    for (int mj = 0; mj < 4; mj++) {
        const int rr = 16 * mj + tg;
        const float il0 = 1.0f / Lbuf[rr];
        const float il1 = 1.0f / Lbuf[rr + 8];
#pragma unroll
        for (int nf = 0; nf < 4; nf++) {
            const int c = 32 * wid + 8 * nf + 2 * tq;
            size_t g00 = ((size_t)b * CDIM + c) * NDIM + n0 + rr;
            size_t g01 = g00 + NDIM;
            size_t g10 = g00 + 8;
            size_t g11 = g01 + 8;
            out[g00] = acc[mj][nf][0] * il0 + x[g00];
            out[g01] = acc[mj][nf][1] * il0 + x[g01];
            out[g10] = acc[mj][nf][2] * il1 + x[g10];
            out[g11] = acc[mj][nf][3] * il1 + x[g11];
        }
    }
}

extern "C" void kernel_launch(void* const* d_in, const int* in_sizes, int n_in,
                              void* d_out, int out_size) {
    const float* x    = (const float*)d_in[0];
    const float* q_w  = (const float*)d_in[1];
    const float* q_g  = (const float*)d_in[3];
    const float* q_be = (const float*)d_in[4];
    const float* k_w  = (const float*)d_in[5];
    const float* k_g  = (const float*)d_in[7];
    const float* k_be = (const float*)d_in[8];
    const float* v_w  = (const float*)d_in[9];
    const float* v_g  = (const float*)d_in[11];
    const float* v_be = (const float*)d_in[12];
    float* out = (float*)d_out;

    w16_kernel<<<OTOT, 128>>>(q_w, k_w, v_w);
    proj16_kernel<<<dim3(5, 8, 16), 256>>>(x);
    stats_fin<<<OTOT, 128>>>(q_g, q_be, k_g, k_be, v_g, v_be);
    qkt_kernel<<<dim3(32, 16), 256>>>();
    v16_kernel<<<dim3(512, 16), 256>>>();

    static int smem_set = 0;
    if (!smem_set) {
        cudaFuncSetAttribute(attn_kernel, cudaFuncAttributeMaxDynamicSharedMemorySize, SMEM_TOTAL);
        smem_set = 1;
    }
    attn_kernel<<<dim3(32, 16), 256, SMEM_TOTAL>>>(x, out);
}